// round 2
// baseline (speedup 1.0000x reference)
#include <cuda_runtime.h>
#include <cstdint>
#include <cstddef>

// ---------------------------------------------------------------------------
// Problem constants (B fixed by the benchmark)
// ---------------------------------------------------------------------------
#define NB      98304
#define PERIOD  24
#define BB      (NB / PERIOD)     // 4096
#define HID     144
#define G4      576               // 4*HID

// Edge list of the fixed 12x12 adjacency (row-major nonzero order)
__constant__ int c_EI[44] = {0,0,0,0, 1,1,1, 2,2,2, 3,3, 4,4, 5,5,5, 6,6,6,6,
                             7,7,7, 8,8,8,8, 9,9,9,9, 10,10,10,10,10,10,10,
                             11,11,11,11,11};
__constant__ int c_EJ[44] = {0,5,10,11, 1,7,10, 2,6,11, 3,6, 4,5, 0,4,5,
                             2,3,6,10, 1,7,9, 8,9,10,11, 7,8,9,10,
                             0,1,6,8,9,10,11, 0,2,8,10,11};
__constant__ int c_RS[13] = {0,4,7,10,12,14,17,21,24,28,32,39,44};

// ---------------------------------------------------------------------------
// Scratch (single big __device__ buffer, offsets in floats; all 16B aligned)
// ---------------------------------------------------------------------------
#define SZ_H1    ((size_t)NB * 192)
#define SZ_H2    ((size_t)NB * 144)
#define SZ_XPRE  ((size_t)NB * 576)
#define SZ_Y     ((size_t)NB * 144)
#define SZ_H3    ((size_t)NB * 192)
#define SZ_H4    ((size_t)NB * 288)
#define SZ_XR    ((size_t)NB * 264)
#define SZ_ST    ((size_t)BB * 144)

#define OFF_H1    ((size_t)0)
#define OFF_H2    (OFF_H1 + SZ_H1)
#define OFF_XPRE  (OFF_H2 + SZ_H2)
#define OFF_Y0    (OFF_XPRE + SZ_XPRE)
#define OFF_YD0   (OFF_Y0 + SZ_Y)
#define OFF_YD1   (OFF_YD0 + SZ_Y)
#define OFF_H3    (OFF_YD1 + SZ_Y)
#define OFF_H4    (OFF_H3 + SZ_H3)
#define OFF_XR    (OFF_H4 + SZ_H4)
#define OFF_PROBS (OFF_XR + SZ_XR)              // 4 * 576
#define OFF_STATE (OFF_PROBS + 2304)            // 16 * SZ_ST
#define OFF_ZERO  (OFF_STATE + 16 * SZ_ST)      // SZ_ST
#define OFF_WR    (OFF_ZERO + SZ_ST)            // 7 * 576*144
#define OFF_BR    (OFF_WR + (size_t)7 * 576 * 144)  // 4 * 576
#define OFF_FWT   (OFF_BR + 4 * 576)            // 264*288
#define SCRATCH_TOTAL (OFF_FWT + (size_t)264 * 288)

__device__ __align__(128) float g_scratch[SCRATCH_TOTAL];

// ---------------------------------------------------------------------------
// Small helpers
// ---------------------------------------------------------------------------
__device__ __forceinline__ float sigm(float x) { return 1.f / (1.f + expf(-x)); }

// ---------------------------------------------------------------------------
// Misc prep kernels
// ---------------------------------------------------------------------------
__global__ void zero_kernel(float* p, int n) {
    int i = blockIdx.x * 256 + threadIdx.x;
    if (i < n) p[i] = 0.f;
}

// Reorder LSTM weight [576,144] gate-major rows -> interleaved (n' = j*4+g)
__global__ void reorder_w(const float* __restrict__ in, float* __restrict__ out) {
    int idx = blockIdx.x * 256 + threadIdx.x;
    if (idx >= 576 * 144) return;
    int np = idx / 144, k = idx - np * 144;
    int j = np >> 2, g = np & 3;
    out[idx] = in[(g * 144 + j) * 144 + k];
}

__global__ void reorder_b(const float* __restrict__ bih, const float* __restrict__ bhh,
                          float* __restrict__ out) {
    int np = blockIdx.x * 256 + threadIdx.x;
    if (np >= 576) return;
    int j = np >> 2, g = np & 3;
    out[np] = bih[g * 144 + j] + bhh[g * 144 + j];
}

// fW [288,264] -> fWt [264,288]
__global__ void transpose_fw(const float* __restrict__ fW, float* __restrict__ fWt) {
    int idx = blockIdx.x * 256 + threadIdx.x;
    if (idx >= 264 * 288) return;
    int n = idx / 288, k = idx - n * 288;
    fWt[idx] = fW[k * 264 + n];
}

// ---------------------------------------------------------------------------
// GAT attention probabilities (one tiny block; sample 0 only, per reference)
// ---------------------------------------------------------------------------
__global__ void attn_probs(const float* __restrict__ x0, const float* __restrict__ W,
                           const float* __restrict__ bias, const float* __restrict__ a,
                           float* __restrict__ probs, int CIN, int COUT, int CSZ) {
    __shared__ float feat[12 * 24];
    __shared__ float lg[44 * 4];
    int tid = threadIdx.x;
    for (int idx = tid; idx < 12 * COUT; idx += blockDim.x) {
        int i = idx / COUT, f = idx - i * COUT;
        float acc = bias[f];
        for (int k = 0; k < CIN; k++) acc += x0[i * CIN + k] * W[k * COUT + f];
        feat[idx] = acc;
    }
    __syncthreads();
    for (int idx = tid; idx < 44 * 4; idx += blockDim.x) {
        int e = idx >> 2, h = idx & 3;
        const float* ah = a + h * 2 * CSZ;
        float s = 0.f;
        for (int c = 0; c < CSZ; c++)
            s += ah[c] * feat[c_EI[e] * COUT + h * CSZ + c] +
                 ah[CSZ + c] * feat[c_EJ[e] * COUT + h * CSZ + c];
        lg[idx] = s > 0.f ? s : 0.2f * s;   // leaky_relu(0.2)
    }
    __syncthreads();
    for (int idx = tid; idx < 48; idx += blockDim.x) {
        int i = idx >> 2, h = idx & 3;
        int s0 = c_RS[i], s1 = c_RS[i + 1];
        float m = -3.4e38f;
        for (int e = s0; e < s1; e++) m = fmaxf(m, lg[e * 4 + h]);
        float sum = 0.f;
        for (int e = s0; e < s1; e++) sum += expf(lg[e * 4 + h] - m);
        float* pr = probs + (i * 4 + h) * 12;
        for (int j = 0; j < 12; j++) pr[j] = 0.f;
        for (int e = s0; e < s1; e++) pr[c_EJ[e]] = expf(lg[e * 4 + h] - m) / sum;
    }
}

// ---------------------------------------------------------------------------
// Fused GAT layer: feat = x@W+b ; out = elu(probs-aggregate(feat))
// ---------------------------------------------------------------------------
template <int CIN, int COUT>
__global__ __launch_bounds__(256) void gat_fused(const float* __restrict__ in,
                                                 const float* __restrict__ W,
                                                 const float* __restrict__ bias,
                                                 const float* __restrict__ probs,
                                                 float* __restrict__ out) {
    constexpr int CSZ = COUT / 4;
    __shared__ float feat[8 * 12 * COUT];
    __shared__ float Ws[CIN * COUT];
    __shared__ float bs[COUT];
    __shared__ float ps[576];
    int tid = threadIdx.x;
    for (int i = tid; i < CIN * COUT; i += 256) Ws[i] = W[i];
    for (int i = tid; i < COUT; i += 256) bs[i] = bias[i];
    for (int i = tid; i < 576; i += 256) ps[i] = probs[i];
    __syncthreads();
    size_t b0 = (size_t)blockIdx.x * 8;
    for (int idx = tid; idx < 8 * 12 * COUT; idx += 256) {
        int s = idx / (12 * COUT);
        int rem = idx - s * 12 * COUT;
        int i = rem / COUT, f = rem - i * COUT;
        const float* xr = in + (b0 + s) * (12 * CIN) + i * CIN;
        float acc = bs[f];
#pragma unroll
        for (int k = 0; k < CIN; k++) acc += xr[k] * Ws[k * COUT + f];
        feat[idx] = acc;
    }
    __syncthreads();
    for (int idx = tid; idx < 8 * 12 * COUT; idx += 256) {
        int s = idx / (12 * COUT);
        int rem = idx - s * 12 * COUT;
        int i = rem / COUT, f = rem - i * COUT;
        int h = f / CSZ;
        const float* pr = ps + (i * 4 + h) * 12;
        const float* fb = feat + s * 12 * COUT + f;
        float acc = 0.f;
#pragma unroll
        for (int j = 0; j < 12; j++) acc += pr[j] * fb[j * COUT];
        out[(b0 + s) * (12 * COUT) + rem] = acc > 0.f ? acc : expm1f(acc);
    }
}

// ---------------------------------------------------------------------------
// Tiled GEMM: C[M,N] = A[M,K] @ B[N,K]^T  (B row-major, row = output col)
// FC=true adds bias + leaky_relu(0.01) and guards N.
// ---------------------------------------------------------------------------
template <bool FC>
__global__ __launch_bounds__(256) void gemm_nt(const float* __restrict__ A,
                                               const float* __restrict__ B,
                                               float* __restrict__ C, int M, int N,
                                               int K, const float* __restrict__ bias) {
    __shared__ float As[16][68];
    __shared__ float Bs[16][68];
    int tid = threadIdx.x;
    int tx = tid & 15, ty = tid >> 4;
    int r4 = tid >> 2, kq = (tid & 3) << 2;
    size_t arow = (size_t)blockIdx.y * 64 + r4;
    int brow = blockIdx.x * 64 + r4;
    const float* Ap = A + arow * K + kq;
    const float* Bp = B + (size_t)brow * K + kq;
    bool bok = (!FC) || (brow < N);
    float acc[4][4];
#pragma unroll
    for (int r = 0; r < 4; r++)
#pragma unroll
        for (int c = 0; c < 4; c++) acc[r][c] = 0.f;

    for (int k0 = 0; k0 < K; k0 += 16) {
        float4 av = *(const float4*)(Ap + k0);
        float4 bv = bok ? *(const float4*)(Bp + k0) : make_float4(0.f, 0.f, 0.f, 0.f);
        As[kq + 0][r4] = av.x; As[kq + 1][r4] = av.y;
        As[kq + 2][r4] = av.z; As[kq + 3][r4] = av.w;
        Bs[kq + 0][r4] = bv.x; Bs[kq + 1][r4] = bv.y;
        Bs[kq + 2][r4] = bv.z; Bs[kq + 3][r4] = bv.w;
        __syncthreads();
#pragma unroll
        for (int kk = 0; kk < 16; kk++) {
            float4 a = *(const float4*)&As[kk][ty << 2];
            float4 b = *(const float4*)&Bs[kk][tx << 2];
            acc[0][0] += a.x * b.x; acc[0][1] += a.x * b.y; acc[0][2] += a.x * b.z; acc[0][3] += a.x * b.w;
            acc[1][0] += a.y * b.x; acc[1][1] += a.y * b.y; acc[1][2] += a.y * b.z; acc[1][3] += a.y * b.w;
            acc[2][0] += a.z * b.x; acc[2][1] += a.z * b.y; acc[2][2] += a.z * b.z; acc[2][3] += a.z * b.w;
            acc[3][0] += a.w * b.x; acc[3][1] += a.w * b.y; acc[3][2] += a.w * b.z; acc[3][3] += a.w * b.w;
        }
        __syncthreads();
    }
    int n0 = blockIdx.x * 64 + (tx << 2);
    if (FC && n0 >= N) return;
#pragma unroll
    for (int r = 0; r < 4; r++) {
        size_t m = (size_t)blockIdx.y * 64 + (ty << 2) + r;
        float4 v = make_float4(acc[r][0], acc[r][1], acc[r][2], acc[r][3]);
        if (FC) {
            v.x += bias[n0 + 0]; v.y += bias[n0 + 1];
            v.z += bias[n0 + 2]; v.w += bias[n0 + 3];
            v.x = v.x >= 0.f ? v.x : 0.01f * v.x;
            v.y = v.y >= 0.f ? v.y : 0.01f * v.y;
            v.z = v.z >= 0.f ? v.z : 0.01f * v.z;
            v.w = v.w >= 0.f ? v.w : 0.01f * v.w;
        }
        *(float4*)(C + m * N + n0) = v;
    }
}

// ---------------------------------------------------------------------------
// One LSTM recurrence step: gates = xpre + h@Whh_r^T + bias_r  (gate-interleaved)
// then full cell update in the epilogue. Grid (576/64, BB/64), 256 thr.
// ---------------------------------------------------------------------------
__global__ __launch_bounds__(256) void lstm_step(const float* __restrict__ hprev,
                                                 const float* __restrict__ Whh,
                                                 const float* __restrict__ bias,
                                                 const float* __restrict__ xpre,
                                                 const float* __restrict__ cprev,
                                                 float* __restrict__ hnext,
                                                 float* __restrict__ cnext,
                                                 float* __restrict__ yout, int hasx) {
    __shared__ float As[16][68];
    __shared__ float Bs[16][68];
    int tid = threadIdx.x;
    int tx = tid & 15, ty = tid >> 4;
    int r4 = tid >> 2, kq = (tid & 3) << 2;
    const float* Ap = hprev + ((size_t)blockIdx.y * 64 + r4) * 144 + kq;
    const float* Bp = Whh + ((size_t)blockIdx.x * 64 + r4) * 144 + kq;
    float acc[4][4];
#pragma unroll
    for (int r = 0; r < 4; r++)
#pragma unroll
        for (int c = 0; c < 4; c++) acc[r][c] = 0.f;

#pragma unroll
    for (int k0 = 0; k0 < 144; k0 += 16) {
        float4 av = *(const float4*)(Ap + k0);
        float4 bv = *(const float4*)(Bp + k0);
        As[kq + 0][r4] = av.x; As[kq + 1][r4] = av.y;
        As[kq + 2][r4] = av.z; As[kq + 3][r4] = av.w;
        Bs[kq + 0][r4] = bv.x; Bs[kq + 1][r4] = bv.y;
        Bs[kq + 2][r4] = bv.z; Bs[kq + 3][r4] = bv.w;
        __syncthreads();
#pragma unroll
        for (int kk = 0; kk < 16; kk++) {
            float4 a = *(const float4*)&As[kk][ty << 2];
            float4 b = *(const float4*)&Bs[kk][tx << 2];
            acc[0][0] += a.x * b.x; acc[0][1] += a.x * b.y; acc[0][2] += a.x * b.z; acc[0][3] += a.x * b.w;
            acc[1][0] += a.y * b.x; acc[1][1] += a.y * b.y; acc[1][2] += a.y * b.z; acc[1][3] += a.y * b.w;
            acc[2][0] += a.z * b.x; acc[2][1] += a.z * b.y; acc[2][2] += a.z * b.z; acc[2][3] += a.z * b.w;
            acc[3][0] += a.w * b.x; acc[3][1] += a.w * b.y; acc[3][2] += a.w * b.z; acc[3][3] += a.w * b.w;
        }
        __syncthreads();
    }

    int j = blockIdx.x * 16 + tx;               // hidden unit index
    int n0 = blockIdx.x * 64 + (tx << 2);       // interleaved gate base
    float4 bb = *(const float4*)(bias + n0);
#pragma unroll
    for (int r = 0; r < 4; r++) {
        size_t m = (size_t)blockIdx.y * 64 + (ty << 2) + r;
        float gi = acc[r][0] + bb.x;
        float gf = acc[r][1] + bb.y;
        float gg = acc[r][2] + bb.z;
        float go = acc[r][3] + bb.w;
        if (hasx) {
            float4 xp = *(const float4*)(xpre + m * 576 + n0);
            gi += xp.x; gf += xp.y; gg += xp.z; go += xp.w;
        }
        float c = cprev[m * 144 + j];
        float c2 = sigm(gf) * c + sigm(gi) * tanhf(gg);
        float h2 = sigm(go) * tanhf(c2);
        cnext[m * 144 + j] = c2;
        hnext[m * 144 + j] = h2;
        yout[m * 144 + j] = h2;
    }
}

// ---------------------------------------------------------------------------
// Per-row MSE: out[b] = mean((x[b,:] - xr[b,:])^2) over 264 elems
// ---------------------------------------------------------------------------
__global__ void mse_kernel(const float* __restrict__ x, const float* __restrict__ xr,
                           float* __restrict__ out, int Btot) {
    int warp = (blockIdx.x * blockDim.x + threadIdx.x) >> 5;
    int lane = threadIdx.x & 31;
    if (warp >= Btot) return;
    const float* xa = x + (size_t)warp * 264;
    const float* xb = xr + (size_t)warp * 264;
    float s = 0.f;
    for (int e = lane; e < 264; e += 32) {
        float d = xa[e] - xb[e];
        s += d * d;
    }
#pragma unroll
    for (int o = 16; o; o >>= 1) s += __shfl_xor_sync(0xffffffffu, s, o);
    if (lane == 0) out[warp] = s * (1.f / 264.f);
}

// ---------------------------------------------------------------------------
// Host orchestration
// ---------------------------------------------------------------------------
extern "C" void kernel_launch(void* const* d_in, const int* in_sizes, int n_in,
                              void* d_out, int out_size) {
    const float* x     = (const float*)d_in[0];
    const float* gW0   = (const float*)d_in[1];
    const float* gb0   = (const float*)d_in[2];
    const float* ga0   = (const float*)d_in[3];
    const float* gW1   = (const float*)d_in[4];
    const float* gb1   = (const float*)d_in[5];
    const float* ga1   = (const float*)d_in[6];
    const float* eWih0 = (const float*)d_in[7];
    const float* eWhh0 = (const float*)d_in[8];
    const float* ebih0 = (const float*)d_in[9];
    const float* ebhh0 = (const float*)d_in[10];
    const float* eWih1 = (const float*)d_in[11];
    const float* eWhh1 = (const float*)d_in[12];
    const float* ebih1 = (const float*)d_in[13];
    const float* ebhh1 = (const float*)d_in[14];
    // dWih0 (d_in[15]) unused: decoder layer-0 inputs are zeros
    const float* dWhh0 = (const float*)d_in[16];
    const float* dbih0 = (const float*)d_in[17];
    const float* dbhh0 = (const float*)d_in[18];
    const float* dWih1 = (const float*)d_in[19];
    const float* dWhh1 = (const float*)d_in[20];
    const float* dbih1 = (const float*)d_in[21];
    const float* dbhh1 = (const float*)d_in[22];
    const float* gW3   = (const float*)d_in[23];
    const float* gb3   = (const float*)d_in[24];
    const float* ga3   = (const float*)d_in[25];
    const float* gW4   = (const float*)d_in[26];
    const float* gb4   = (const float*)d_in[27];
    const float* ga4   = (const float*)d_in[28];
    const float* fW    = (const float*)d_in[29];
    const float* fb    = (const float*)d_in[30];

    float* S = nullptr;
    cudaGetSymbolAddress((void**)&S, g_scratch);

    const int B  = in_sizes[0] / 264;   // 98304
    const int Bb = B / PERIOD;          // 4096

    float* h1    = S + OFF_H1;
    float* h2    = S + OFF_H2;
    float* Xpre  = S + OFF_XPRE;
    float* y0    = S + OFF_Y0;
    float* yd0   = S + OFF_YD0;
    float* yd1   = S + OFF_YD1;
    float* h3    = S + OFF_H3;
    float* h4    = S + OFF_H4;
    float* xr    = S + OFF_XR;
    float* probs = S + OFF_PROBS;
    float* st    = S + OFF_STATE;   // 16 state buffers of BB*144
    float* zbuf  = S + OFF_ZERO;
    float* wr    = S + OFF_WR;      // 7 reordered [576,144]
    float* br    = S + OFF_BR;      // 4 reordered biases
    float* fWt   = S + OFF_FWT;

    float* wr_eWih0 = wr + 0 * 576 * 144;
    float* wr_eWhh0 = wr + 1 * 576 * 144;
    float* wr_eWih1 = wr + 2 * 576 * 144;
    float* wr_eWhh1 = wr + 3 * 576 * 144;
    float* wr_dWhh0 = wr + 4 * 576 * 144;
    float* wr_dWih1 = wr + 5 * 576 * 144;
    float* wr_dWhh1 = wr + 6 * 576 * 144;
    float* br_e0 = br + 0 * 576;
    float* br_e1 = br + 1 * 576;
    float* br_d0 = br + 2 * 576;
    float* br_d1 = br + 3 * 576;

    const size_t SST = (size_t)Bb * 144;
    float* bufs[16];
    for (int i = 0; i < 16; i++) bufs[i] = st + (size_t)i * SST;
    // 0/1 eh0 A/B, 2/3 ec0, 4/5 eh1, 6/7 ec1, 8/9 dh0, 10/11 dc0, 12/13 dh1, 14/15 dc1

    // ---- prep ----
    zero_kernel<<<(Bb * 144 + 255) / 256, 256>>>(zbuf, Bb * 144);
    reorder_w<<<(576 * 144 + 255) / 256, 256>>>(eWih0, wr_eWih0);
    reorder_w<<<(576 * 144 + 255) / 256, 256>>>(eWhh0, wr_eWhh0);
    reorder_w<<<(576 * 144 + 255) / 256, 256>>>(eWih1, wr_eWih1);
    reorder_w<<<(576 * 144 + 255) / 256, 256>>>(eWhh1, wr_eWhh1);
    reorder_w<<<(576 * 144 + 255) / 256, 256>>>(dWhh0, wr_dWhh0);
    reorder_w<<<(576 * 144 + 255) / 256, 256>>>(dWih1, wr_dWih1);
    reorder_w<<<(576 * 144 + 255) / 256, 256>>>(dWhh1, wr_dWhh1);
    reorder_b<<<3, 256>>>(ebih0, ebhh0, br_e0);
    reorder_b<<<3, 256>>>(ebih1, ebhh1, br_e1);
    reorder_b<<<3, 256>>>(dbih0, dbhh0, br_d0);
    reorder_b<<<3, 256>>>(dbih1, dbhh1, br_d1);
    transpose_fw<<<(264 * 288 + 255) / 256, 256>>>(fW, fWt);

    // ---- GAT 1+2 ----
    attn_probs<<<1, 128>>>(x, gW0, gb0, ga0, probs + 0, 22, 16, 4);
    gat_fused<22, 16><<<B / 8, 256>>>(x, gW0, gb0, probs + 0, h1);
    attn_probs<<<1, 128>>>(h1, gW1, gb1, ga1, probs + 576, 16, 12, 3);
    gat_fused<16, 12><<<B / 8, 256>>>(h1, gW1, gb1, probs + 576, h2);

    dim3 gBig(9, B / 64), tB(256);
    dim3 gStep(9, Bb / 64);

    // ---- Encoder layer 0 ----
    gemm_nt<false><<<gBig, tB>>>(h2, wr_eWih0, Xpre, B, 576, 144, nullptr);
    const float* hp = zbuf; const float* cp = zbuf;
    for (int t = 0; t < PERIOD; t++) {
        float* hn = (t & 1) ? bufs[0] : bufs[1];
        float* cn = (t & 1) ? bufs[2] : bufs[3];
        lstm_step<<<gStep, tB>>>(hp, wr_eWhh0, br_e0, Xpre + (size_t)t * Bb * 576, cp,
                                 hn, cn, y0 + (size_t)t * Bb * 144, 1);
        hp = hn; cp = cn;
    }
    const float* enc_h0 = hp;

    // ---- Encoder layer 1 (y unused; overwrite y0 after consuming it) ----
    gemm_nt<false><<<gBig, tB>>>(y0, wr_eWih1, Xpre, B, 576, 144, nullptr);
    hp = zbuf; cp = zbuf;
    for (int t = 0; t < PERIOD; t++) {
        float* hn = (t & 1) ? bufs[4] : bufs[5];
        float* cn = (t & 1) ? bufs[6] : bufs[7];
        lstm_step<<<gStep, tB>>>(hp, wr_eWhh1, br_e1, Xpre + (size_t)t * Bb * 576, cp,
                                 hn, cn, y0 + (size_t)t * Bb * 144, 1);
        hp = hn; cp = cn;
    }
    const float* enc_h1 = hp;

    // ---- Decoder layer 0 (zero inputs -> no xpre) ----
    hp = enc_h0; cp = zbuf;
    for (int t = 0; t < PERIOD; t++) {
        float* hn = (t & 1) ? bufs[8] : bufs[9];
        float* cn = (t & 1) ? bufs[10] : bufs[11];
        lstm_step<<<gStep, tB>>>(hp, wr_dWhh0, br_d0, nullptr, cp,
                                 hn, cn, yd0 + (size_t)t * Bb * 144, 0);
        hp = hn; cp = cn;
    }

    // ---- Decoder layer 1 ----
    gemm_nt<false><<<gBig, tB>>>(yd0, wr_dWih1, Xpre, B, 576, 144, nullptr);
    hp = enc_h1; cp = zbuf;
    for (int t = 0; t < PERIOD; t++) {
        float* hn = (t & 1) ? bufs[12] : bufs[13];
        float* cn = (t & 1) ? bufs[14] : bufs[15];
        lstm_step<<<gStep, tB>>>(hp, wr_dWhh1, br_d1, Xpre + (size_t)t * Bb * 576, cp,
                                 hn, cn, yd1 + (size_t)t * Bb * 144, 1);
        hp = hn; cp = cn;
    }

    // ---- GAT 3+4 ----
    attn_probs<<<1, 128>>>(yd1, gW3, gb3, ga3, probs + 1152, 12, 16, 4);
    gat_fused<12, 16><<<B / 8, 256>>>(yd1, gW3, gb3, probs + 1152, h3);
    attn_probs<<<1, 128>>>(h3, gW4, gb4, ga4, probs + 1728, 16, 24, 6);
    gat_fused<16, 24><<<B / 8, 256>>>(h3, gW4, gb4, probs + 1728, h4);

    // ---- FC + leaky + MSE ----
    gemm_nt<true><<<dim3(5, B / 64), tB>>>(h4, fWt, xr, B, 264, 288, fb);
    mse_kernel<<<(B + 7) / 8, 256>>>(x, xr, (float*)d_out, B);
}

// round 3
// speedup vs baseline: 1.5483x; 1.5483x over previous
#include <cuda_runtime.h>
#include <cstdint>
#include <cstddef>

// ---------------------------------------------------------------------------
// Problem constants
// ---------------------------------------------------------------------------
#define NB      98304
#define PERIOD  24
#define BB      (NB / PERIOD)     // 4096
#define HID     144
#define G4      576

__constant__ int c_EI[44] = {0,0,0,0, 1,1,1, 2,2,2, 3,3, 4,4, 5,5,5, 6,6,6,6,
                             7,7,7, 8,8,8,8, 9,9,9,9, 10,10,10,10,10,10,10,
                             11,11,11,11,11};
__constant__ int c_EJ[44] = {0,5,10,11, 1,7,10, 2,6,11, 3,6, 4,5, 0,4,5,
                             2,3,6,10, 1,7,9, 8,9,10,11, 7,8,9,10,
                             0,1,6,8,9,10,11, 0,2,8,10,11};
__constant__ int c_RS[13] = {0,4,7,10,12,14,17,21,24,28,32,39,44};

// ---------------------------------------------------------------------------
// Scratch
// ---------------------------------------------------------------------------
#define SZ_H1    ((size_t)NB * 192)
#define SZ_H2    ((size_t)NB * 144)
#define SZ_XPRE  ((size_t)NB * 576)
#define SZ_Y     ((size_t)NB * 144)
#define SZ_H3    ((size_t)NB * 192)
#define SZ_H4    ((size_t)NB * 288)
#define SZ_XR    ((size_t)NB * 264)
#define SZ_ST    ((size_t)BB * 144)
#define SZ_FWT   ((size_t)320 * 288)

#define OFF_H1    ((size_t)0)
#define OFF_H2    (OFF_H1 + SZ_H1)
#define OFF_XPRE  (OFF_H2 + SZ_H2)
#define OFF_Y0    (OFF_XPRE + SZ_XPRE)
#define OFF_YD0   (OFF_Y0 + SZ_Y)
#define OFF_YD1   (OFF_YD0 + SZ_Y)
#define OFF_H3    (OFF_YD1 + SZ_Y)
#define OFF_H4    (OFF_H3 + SZ_H3)
#define OFF_XR    (OFF_H4 + SZ_H4)
#define OFF_PROBS (OFF_XR + SZ_XR)              // 4 * 576
#define OFF_STATE (OFF_PROBS + 2304)            // 16 * SZ_ST
#define OFF_ZERO  (OFF_STATE + 16 * SZ_ST)
#define OFF_WR    (OFF_ZERO + SZ_ST)            // 7 * 576*144
#define OFF_BR    (OFF_WR + (size_t)7 * 576 * 144)
#define OFF_FWT   (OFF_BR + 4 * 576)
#define SCRATCH_TOTAL (OFF_FWT + SZ_FWT)

__device__ __align__(128) float g_scratch[SCRATCH_TOTAL];

__device__ __forceinline__ float sigm(float x) { return 1.f / (1.f + expf(-x)); }

__device__ __forceinline__ float f2tf(float x) {
    uint32_t r;
    asm("cvt.rna.tf32.f32 %0, %1;" : "=r"(r) : "f"(x));
    return __uint_as_float(r);
}

// ---------------------------------------------------------------------------
// Prep kernels
// ---------------------------------------------------------------------------
__global__ void zero_kernel(float* p, int n) {
    int i = blockIdx.x * 256 + threadIdx.x;
    if (i < n) p[i] = 0.f;
}

__global__ void reorder_w(const float* __restrict__ in, float* __restrict__ out) {
    int idx = blockIdx.x * 256 + threadIdx.x;
    if (idx >= 576 * 144) return;
    int np = idx / 144, k = idx - np * 144;
    int j = np >> 2, g = np & 3;
    out[idx] = in[(g * 144 + j) * 144 + k];
}

__global__ void reorder_b(const float* __restrict__ bih, const float* __restrict__ bhh,
                          float* __restrict__ out) {
    int np = blockIdx.x * 256 + threadIdx.x;
    if (np >= 576) return;
    int j = np >> 2, g = np & 3;
    out[np] = bih[g * 144 + j] + bhh[g * 144 + j];
}

// fW [288,264] -> fWt [320,288], zero-padded rows 264..319
__global__ void transpose_fw(const float* __restrict__ fW, float* __restrict__ fWt) {
    int idx = blockIdx.x * 256 + threadIdx.x;
    if (idx >= 320 * 288) return;
    int n = idx / 288, k = idx - n * 288;
    fWt[idx] = (n < 264) ? fW[k * 264 + n] : 0.f;
}

// ---------------------------------------------------------------------------
// GAT attention probabilities (sample 0 only)
// ---------------------------------------------------------------------------
__global__ void attn_probs(const float* __restrict__ x0, const float* __restrict__ W,
                           const float* __restrict__ bias, const float* __restrict__ a,
                           float* __restrict__ probs, int CIN, int COUT, int CSZ) {
    __shared__ float feat[12 * 24];
    __shared__ float lg[44 * 4];
    int tid = threadIdx.x;
    for (int idx = tid; idx < 12 * COUT; idx += blockDim.x) {
        int i = idx / COUT, f = idx - i * COUT;
        float acc = bias[f];
        for (int k = 0; k < CIN; k++) acc += x0[i * CIN + k] * W[k * COUT + f];
        feat[idx] = acc;
    }
    __syncthreads();
    for (int idx = tid; idx < 44 * 4; idx += blockDim.x) {
        int e = idx >> 2, h = idx & 3;
        const float* ah = a + h * 2 * CSZ;
        float s = 0.f;
        for (int c = 0; c < CSZ; c++)
            s += ah[c] * feat[c_EI[e] * COUT + h * CSZ + c] +
                 ah[CSZ + c] * feat[c_EJ[e] * COUT + h * CSZ + c];
        lg[idx] = s > 0.f ? s : 0.2f * s;
    }
    __syncthreads();
    for (int idx = tid; idx < 48; idx += blockDim.x) {
        int i = idx >> 2, h = idx & 3;
        int s0 = c_RS[i], s1 = c_RS[i + 1];
        float m = -3.4e38f;
        for (int e = s0; e < s1; e++) m = fmaxf(m, lg[e * 4 + h]);
        float sum = 0.f;
        for (int e = s0; e < s1; e++) sum += expf(lg[e * 4 + h] - m);
        float* pr = probs + (i * 4 + h) * 12;
        for (int j = 0; j < 12; j++) pr[j] = 0.f;
        for (int e = s0; e < s1; e++) pr[c_EJ[e]] = expf(lg[e * 4 + h] - m) / sum;
    }
}

// ---------------------------------------------------------------------------
// Fused GAT layer
// ---------------------------------------------------------------------------
template <int CIN, int COUT>
__global__ __launch_bounds__(256) void gat_fused(const float* __restrict__ in,
                                                 const float* __restrict__ W,
                                                 const float* __restrict__ bias,
                                                 const float* __restrict__ probs,
                                                 float* __restrict__ out) {
    constexpr int CSZ = COUT / 4;
    __shared__ float feat[8 * 12 * COUT];
    __shared__ float Ws[CIN * COUT];
    __shared__ float bs[COUT];
    __shared__ float ps[576];
    int tid = threadIdx.x;
    for (int i = tid; i < CIN * COUT; i += 256) Ws[i] = W[i];
    for (int i = tid; i < COUT; i += 256) bs[i] = bias[i];
    for (int i = tid; i < 576; i += 256) ps[i] = probs[i];
    __syncthreads();
    size_t b0 = (size_t)blockIdx.x * 8;
    for (int idx = tid; idx < 8 * 12 * COUT; idx += 256) {
        int s = idx / (12 * COUT);
        int rem = idx - s * 12 * COUT;
        int i = rem / COUT, f = rem - i * COUT;
        const float* xr = in + (b0 + s) * (12 * CIN) + i * CIN;
        float acc = bs[f];
#pragma unroll
        for (int k = 0; k < CIN; k++) acc += xr[k] * Ws[k * COUT + f];
        feat[idx] = acc;
    }
    __syncthreads();
    for (int idx = tid; idx < 8 * 12 * COUT; idx += 256) {
        int s = idx / (12 * COUT);
        int rem = idx - s * 12 * COUT;
        int i = rem / COUT, f = rem - i * COUT;
        int h = f / CSZ;
        const float* pr = ps + (i * 4 + h) * 12;
        const float* fb = feat + s * 12 * COUT + f;
        float acc = 0.f;
#pragma unroll
        for (int j = 0; j < 12; j++) acc += pr[j] * fb[j * COUT];
        out[(b0 + s) * (12 * COUT) + rem] = acc > 0.f ? acc : expm1f(acc);
    }
}

// ---------------------------------------------------------------------------
// tf32 mma GEMM: C[M,N] = A[M,K] @ B[N,K]^T with epilogue
//   EPI 0: plain store (ldn = ldc)
//   EPI 1: LSTM cell update (gate-interleaved, + optional xpre)
//   EPI 2: FC bias + leaky_relu(0.01), N guard 264
// Block: BM x 64 tile, BM*2 threads (8 or 4 warps of 32x32 warp tiles).
// ---------------------------------------------------------------------------
template <int BM, int EPI>
__global__ __launch_bounds__(BM * 2) void gemm_mma(
    const float* __restrict__ A, const float* __restrict__ B, int K, int ldn,
    float* __restrict__ C, const float* __restrict__ bias,
    const float* __restrict__ xpre, const float* __restrict__ cprev,
    float* __restrict__ cnext, float* __restrict__ hnext, float* __restrict__ yout) {
    constexpr int NT = BM * 2;
    __shared__ float As[BM][20];
    __shared__ float Bs[64][20];

    int tid = threadIdx.x;
    int w = tid >> 5, lane = tid & 31;
    int warpM = w >> 1, warpN = w & 1;
    int group = lane >> 2, tig = lane & 3;

    float acc[2][4][4];
#pragma unroll
    for (int mt = 0; mt < 2; mt++)
#pragma unroll
        for (int nt = 0; nt < 4; nt++)
#pragma unroll
            for (int i = 0; i < 4; i++) acc[mt][nt][i] = 0.f;

    const size_t mBase = (size_t)blockIdx.y * BM;
    const int nBase = blockIdx.x * 64;

    for (int k0 = 0; k0 < K; k0 += 16) {
        // fill As: BM*16 floats = BM*4 float4
#pragma unroll
        for (int i = 0; i < BM * 4 / NT; i++) {
            int q = tid + i * NT;
            int row = q >> 2, kq = (q & 3) << 2;
            float4 v = *(const float4*)(A + (mBase + row) * K + k0 + kq);
            As[row][kq + 0] = f2tf(v.x); As[row][kq + 1] = f2tf(v.y);
            As[row][kq + 2] = f2tf(v.z); As[row][kq + 3] = f2tf(v.w);
        }
        // fill Bs: 64*16 floats = 256 float4
#pragma unroll
        for (int i = 0; i < 256 / NT; i++) {
            int q = tid + i * NT;
            int n = q >> 2, kq = (q & 3) << 2;
            float4 v = *(const float4*)(B + (size_t)(nBase + n) * K + k0 + kq);
            Bs[n][kq + 0] = f2tf(v.x); Bs[n][kq + 1] = f2tf(v.y);
            Bs[n][kq + 2] = f2tf(v.z); Bs[n][kq + 3] = f2tf(v.w);
        }
        __syncthreads();
#pragma unroll
        for (int k8 = 0; k8 < 16; k8 += 8) {
            uint32_t a[2][4], b[4][2];
#pragma unroll
            for (int mt = 0; mt < 2; mt++) {
                int r0 = warpM * 32 + mt * 16 + group;
                a[mt][0] = __float_as_uint(As[r0][k8 + tig]);
                a[mt][1] = __float_as_uint(As[r0 + 8][k8 + tig]);
                a[mt][2] = __float_as_uint(As[r0][k8 + tig + 4]);
                a[mt][3] = __float_as_uint(As[r0 + 8][k8 + tig + 4]);
            }
#pragma unroll
            for (int nt = 0; nt < 4; nt++) {
                int n0 = warpN * 32 + nt * 8 + group;
                b[nt][0] = __float_as_uint(Bs[n0][k8 + tig]);
                b[nt][1] = __float_as_uint(Bs[n0][k8 + tig + 4]);
            }
#pragma unroll
            for (int mt = 0; mt < 2; mt++)
#pragma unroll
                for (int nt = 0; nt < 4; nt++) {
                    asm volatile(
                        "mma.sync.aligned.m16n8k8.row.col.f32.tf32.tf32.f32 "
                        "{%0,%1,%2,%3}, {%4,%5,%6,%7}, {%8,%9}, {%0,%1,%2,%3};"
                        : "+f"(acc[mt][nt][0]), "+f"(acc[mt][nt][1]),
                          "+f"(acc[mt][nt][2]), "+f"(acc[mt][nt][3])
                        : "r"(a[mt][0]), "r"(a[mt][1]), "r"(a[mt][2]), "r"(a[mt][3]),
                          "r"(b[nt][0]), "r"(b[nt][1]));
                }
        }
        __syncthreads();
    }

    // ---- epilogue ----
#pragma unroll
    for (int mt = 0; mt < 2; mt++)
#pragma unroll
        for (int nt = 0; nt < 4; nt++) {
            float* a = acc[mt][nt];
            int colg = nBase + warpN * 32 + nt * 8 + 2 * tig;
            size_t row0 = mBase + warpM * 32 + mt * 16 + group;
            if (EPI == 0) {
                *(float2*)(C + row0 * ldn + colg) = make_float2(a[0], a[1]);
                *(float2*)(C + (row0 + 8) * ldn + colg) = make_float2(a[2], a[3]);
            } else if (EPI == 2) {
                if (colg < 264) {
                    float bx = bias[colg], by = bias[colg + 1];
                    float v0 = a[0] + bx, v1 = a[1] + by, v2 = a[2] + bx, v3 = a[3] + by;
                    v0 = v0 >= 0.f ? v0 : 0.01f * v0;
                    v1 = v1 >= 0.f ? v1 : 0.01f * v1;
                    v2 = v2 >= 0.f ? v2 : 0.01f * v2;
                    v3 = v3 >= 0.f ? v3 : 0.01f * v3;
                    *(float2*)(C + row0 * 264 + colg) = make_float2(v0, v1);
                    *(float2*)(C + (row0 + 8) * 264 + colg) = make_float2(v2, v3);
                }
            } else {  // LSTM cell
                float bx = bias[colg], by = bias[colg + 1];
                float v0 = a[0] + bx, v1 = a[1] + by, v2 = a[2] + bx, v3 = a[3] + by;
                if (xpre) {
                    float2 xp0 = *(const float2*)(xpre + row0 * 576 + colg);
                    float2 xp1 = *(const float2*)(xpre + (row0 + 8) * 576 + colg);
                    v0 += xp0.x; v1 += xp0.y; v2 += xp1.x; v3 += xp1.y;
                }
                float o0 = __shfl_xor_sync(0xffffffffu, v0, 1);
                float o1 = __shfl_xor_sync(0xffffffffu, v1, 1);
                float o2 = __shfl_xor_sync(0xffffffffu, v2, 1);
                float o3 = __shfl_xor_sync(0xffffffffu, v3, 1);
                if (!(tig & 1)) {   // even lanes hold (i,f); partner holds (g,o)
                    int j = colg >> 2;
                    {
                        float c = cprev[row0 * 144 + j];
                        float c2 = sigm(v1) * c + sigm(v0) * tanhf(o0);
                        float h2 = sigm(o1) * tanhf(c2);
                        cnext[row0 * 144 + j] = c2;
                        hnext[row0 * 144 + j] = h2;
                        yout[row0 * 144 + j] = h2;
                    }
                    {
                        float c = cprev[(row0 + 8) * 144 + j];
                        float c2 = sigm(v3) * c + sigm(v2) * tanhf(o2);
                        float h2 = sigm(o3) * tanhf(c2);
                        cnext[(row0 + 8) * 144 + j] = c2;
                        hnext[(row0 + 8) * 144 + j] = h2;
                        yout[(row0 + 8) * 144 + j] = h2;
                    }
                }
            }
        }
}

// ---------------------------------------------------------------------------
// Per-row MSE
// ---------------------------------------------------------------------------
__global__ void mse_kernel(const float* __restrict__ x, const float* __restrict__ xr,
                           float* __restrict__ out, int Btot) {
    int warp = (blockIdx.x * blockDim.x + threadIdx.x) >> 5;
    int lane = threadIdx.x & 31;
    if (warp >= Btot) return;
    const float* xa = x + (size_t)warp * 264;
    const float* xb = xr + (size_t)warp * 264;
    float s = 0.f;
    for (int e = lane; e < 264; e += 32) {
        float d = xa[e] - xb[e];
        s += d * d;
    }
#pragma unroll
    for (int o = 16; o; o >>= 1) s += __shfl_xor_sync(0xffffffffu, s, o);
    if (lane == 0) out[warp] = s * (1.f / 264.f);
}

// ---------------------------------------------------------------------------
// Host orchestration
// ---------------------------------------------------------------------------
extern "C" void kernel_launch(void* const* d_in, const int* in_sizes, int n_in,
                              void* d_out, int out_size) {
    const float* x     = (const float*)d_in[0];
    const float* gW0   = (const float*)d_in[1];
    const float* gb0   = (const float*)d_in[2];
    const float* ga0   = (const float*)d_in[3];
    const float* gW1   = (const float*)d_in[4];
    const float* gb1   = (const float*)d_in[5];
    const float* ga1   = (const float*)d_in[6];
    const float* eWih0 = (const float*)d_in[7];
    const float* eWhh0 = (const float*)d_in[8];
    const float* ebih0 = (const float*)d_in[9];
    const float* ebhh0 = (const float*)d_in[10];
    const float* eWih1 = (const float*)d_in[11];
    const float* eWhh1 = (const float*)d_in[12];
    const float* ebih1 = (const float*)d_in[13];
    const float* ebhh1 = (const float*)d_in[14];
    const float* dWhh0 = (const float*)d_in[16];
    const float* dbih0 = (const float*)d_in[17];
    const float* dbhh0 = (const float*)d_in[18];
    const float* dWih1 = (const float*)d_in[19];
    const float* dWhh1 = (const float*)d_in[20];
    const float* dbih1 = (const float*)d_in[21];
    const float* dbhh1 = (const float*)d_in[22];
    const float* gW3   = (const float*)d_in[23];
    const float* gb3   = (const float*)d_in[24];
    const float* ga3   = (const float*)d_in[25];
    const float* gW4   = (const float*)d_in[26];
    const float* gb4   = (const float*)d_in[27];
    const float* ga4   = (const float*)d_in[28];
    const float* fW    = (const float*)d_in[29];
    const float* fb    = (const float*)d_in[30];

    float* S = nullptr;
    cudaGetSymbolAddress((void**)&S, g_scratch);

    const int B  = in_sizes[0] / 264;   // 98304
    const int Bb = B / PERIOD;          // 4096

    float* h1    = S + OFF_H1;
    float* h2    = S + OFF_H2;
    float* Xpre  = S + OFF_XPRE;
    float* y0    = S + OFF_Y0;
    float* yd0   = S + OFF_YD0;
    float* yd1   = S + OFF_YD1;
    float* h3    = S + OFF_H3;
    float* h4    = S + OFF_H4;
    float* xr    = S + OFF_XR;
    float* probs = S + OFF_PROBS;
    float* st    = S + OFF_STATE;
    float* zbuf  = S + OFF_ZERO;
    float* wr    = S + OFF_WR;
    float* br    = S + OFF_BR;
    float* fWt   = S + OFF_FWT;

    float* wr_eWih0 = wr + 0 * 576 * 144;
    float* wr_eWhh0 = wr + 1 * 576 * 144;
    float* wr_eWih1 = wr + 2 * 576 * 144;
    float* wr_eWhh1 = wr + 3 * 576 * 144;
    float* wr_dWhh0 = wr + 4 * 576 * 144;
    float* wr_dWih1 = wr + 5 * 576 * 144;
    float* wr_dWhh1 = wr + 6 * 576 * 144;
    float* br_e0 = br + 0 * 576;
    float* br_e1 = br + 1 * 576;
    float* br_d0 = br + 2 * 576;
    float* br_d1 = br + 3 * 576;

    const size_t SST = (size_t)Bb * 144;
    float* bufs[16];
    for (int i = 0; i < 16; i++) bufs[i] = st + (size_t)i * SST;

    // ---- prep ----
    zero_kernel<<<(Bb * 144 + 255) / 256, 256>>>(zbuf, Bb * 144);
    reorder_w<<<(576 * 144 + 255) / 256, 256>>>(eWih0, wr_eWih0);
    reorder_w<<<(576 * 144 + 255) / 256, 256>>>(eWhh0, wr_eWhh0);
    reorder_w<<<(576 * 144 + 255) / 256, 256>>>(eWih1, wr_eWih1);
    reorder_w<<<(576 * 144 + 255) / 256, 256>>>(eWhh1, wr_eWhh1);
    reorder_w<<<(576 * 144 + 255) / 256, 256>>>(dWhh0, wr_dWhh0);
    reorder_w<<<(576 * 144 + 255) / 256, 256>>>(dWih1, wr_dWih1);
    reorder_w<<<(576 * 144 + 255) / 256, 256>>>(dWhh1, wr_dWhh1);
    reorder_b<<<3, 256>>>(ebih0, ebhh0, br_e0);
    reorder_b<<<3, 256>>>(ebih1, ebhh1, br_e1);
    reorder_b<<<3, 256>>>(dbih0, dbhh0, br_d0);
    reorder_b<<<3, 256>>>(dbih1, dbhh1, br_d1);
    transpose_fw<<<(320 * 288 + 255) / 256, 256>>>(fW, fWt);

    // ---- GAT 1+2 ----
    attn_probs<<<1, 128>>>(x, gW0, gb0, ga0, probs + 0, 22, 16, 4);
    gat_fused<22, 16><<<B / 8, 256>>>(x, gW0, gb0, probs + 0, h1);
    attn_probs<<<1, 128>>>(h1, gW1, gb1, ga1, probs + 576, 16, 12, 3);
    gat_fused<16, 12><<<B / 8, 256>>>(h1, gW1, gb1, probs + 576, h2);

    dim3 gBig(9, B / 128);
    dim3 gStep(9, Bb / 64);

    // ---- Encoder layer 0 ----
    gemm_mma<128, 0><<<gBig, 256>>>(h2, wr_eWih0, 144, 576, Xpre, nullptr,
                                    nullptr, nullptr, nullptr, nullptr, nullptr);
    const float* hp = zbuf; const float* cp = zbuf;
    for (int t = 0; t < PERIOD; t++) {
        float* hn = (t & 1) ? bufs[0] : bufs[1];
        float* cn = (t & 1) ? bufs[2] : bufs[3];
        gemm_mma<64, 1><<<gStep, 128>>>(hp, wr_eWhh0, 144, 0, nullptr, br_e0,
                                        Xpre + (size_t)t * Bb * 576, cp, cn, hn,
                                        y0 + (size_t)t * Bb * 144);
        hp = hn; cp = cn;
    }
    const float* enc_h0 = hp;

    // ---- Encoder layer 1 ----
    gemm_mma<128, 0><<<gBig, 256>>>(y0, wr_eWih1, 144, 576, Xpre, nullptr,
                                    nullptr, nullptr, nullptr, nullptr, nullptr);
    hp = zbuf; cp = zbuf;
    for (int t = 0; t < PERIOD; t++) {
        float* hn = (t & 1) ? bufs[4] : bufs[5];
        float* cn = (t & 1) ? bufs[6] : bufs[7];
        gemm_mma<64, 1><<<gStep, 128>>>(hp, wr_eWhh1, 144, 0, nullptr, br_e1,
                                        Xpre + (size_t)t * Bb * 576, cp, cn, hn,
                                        y0 + (size_t)t * Bb * 144);
        hp = hn; cp = cn;
    }
    const float* enc_h1 = hp;

    // ---- Decoder layer 0 (zero inputs) ----
    hp = enc_h0; cp = zbuf;
    for (int t = 0; t < PERIOD; t++) {
        float* hn = (t & 1) ? bufs[8] : bufs[9];
        float* cn = (t & 1) ? bufs[10] : bufs[11];
        gemm_mma<64, 1><<<gStep, 128>>>(hp, wr_dWhh0, 144, 0, nullptr, br_d0,
                                        nullptr, cp, cn, hn,
                                        yd0 + (size_t)t * Bb * 144);
        hp = hn; cp = cn;
    }

    // ---- Decoder layer 1 ----
    gemm_mma<128, 0><<<gBig, 256>>>(yd0, wr_dWih1, 144, 576, Xpre, nullptr,
                                    nullptr, nullptr, nullptr, nullptr, nullptr);
    hp = enc_h1; cp = zbuf;
    for (int t = 0; t < PERIOD; t++) {
        float* hn = (t & 1) ? bufs[12] : bufs[13];
        float* cn = (t & 1) ? bufs[14] : bufs[15];
        gemm_mma<64, 1><<<gStep, 128>>>(hp, wr_dWhh1, 144, 0, nullptr, br_d1,
                                        Xpre + (size_t)t * Bb * 576, cp, cn, hn,
                                        yd1 + (size_t)t * Bb * 144);
        hp = hn; cp = cn;
    }

    // ---- GAT 3+4 ----
    attn_probs<<<1, 128>>>(yd1, gW3, gb3, ga3, probs + 1152, 12, 16, 4);
    gat_fused<12, 16><<<B / 8, 256>>>(yd1, gW3, gb3, probs + 1152, h3);
    attn_probs<<<1, 128>>>(h3, gW4, gb4, ga4, probs + 1728, 16, 24, 6);
    gat_fused<16, 24><<<B / 8, 256>>>(h3, gW4, gb4, probs + 1728, h4);

    // ---- FC + leaky + MSE ----
    gemm_mma<128, 2><<<dim3(5, B / 128), 256>>>(h4, fWt, 288, 264, xr, fb,
                                                nullptr, nullptr, nullptr, nullptr, nullptr);
    mse_kernel<<<(B + 7) / 8, 256>>>(x, xr, (float*)d_out, B);
}

// round 6
// speedup vs baseline: 1.6661x; 1.0760x over previous
#include <cuda_runtime.h>
#include <cuda_fp16.h>
#include <cstdint>
#include <cstddef>

// ---------------------------------------------------------------------------
// Problem constants
// ---------------------------------------------------------------------------
#define NB      98304
#define PERIOD  24
#define BB      (NB / PERIOD)     // 4096
#define HID     144
#define G4      576
#define WPAD    152               // padded K stride (halves) for bank-conflict-free LDS

__constant__ int c_EI[44] = {0,0,0,0, 1,1,1, 2,2,2, 3,3, 4,4, 5,5,5, 6,6,6,6,
                             7,7,7, 8,8,8,8, 9,9,9,9, 10,10,10,10,10,10,10,
                             11,11,11,11,11};
__constant__ int c_EJ[44] = {0,5,10,11, 1,7,10, 2,6,11, 3,6, 4,5, 0,4,5,
                             2,3,6,10, 1,7,9, 8,9,10,11, 7,8,9,10,
                             0,1,6,8,9,10,11, 0,2,8,10,11};
__constant__ int c_RS[13] = {0,4,7,10,12,14,17,21,24,28,32,39,44};

// ---------------------------------------------------------------------------
// Scratch
// ---------------------------------------------------------------------------
#define SZ_H1    ((size_t)NB * 192)
#define SZ_H2    ((size_t)NB * 144)
#define SZ_XPRE  ((size_t)NB * 576)
#define SZ_Y     ((size_t)NB * 144)
#define SZ_H3    ((size_t)NB * 192)
#define SZ_H4    ((size_t)NB * 288)
#define SZ_XR    ((size_t)NB * 264)
#define SZ_ST    ((size_t)BB * 144)
#define SZ_FWT   ((size_t)320 * 288)
#define SZ_W16   ((size_t)576 * WPAD / 2)   // one fp16 [576][152] matrix, in floats

#define OFF_H1    ((size_t)0)
#define OFF_H2    (OFF_H1 + SZ_H1)
#define OFF_XPRE  (OFF_H2 + SZ_H2)
#define OFF_Y0    (OFF_XPRE + SZ_XPRE)
#define OFF_YD0   (OFF_Y0 + SZ_Y)
#define OFF_YD1   (OFF_YD0 + SZ_Y)
#define OFF_H3    (OFF_YD1 + SZ_Y)
#define OFF_H4    (OFF_H3 + SZ_H3)
#define OFF_XR    (OFF_H4 + SZ_H4)
#define OFF_PROBS (OFF_XR + SZ_XR)              // 4 * 576
#define OFF_STATE (OFF_PROBS + 2304)            // 16 * SZ_ST
#define OFF_WR    (OFF_STATE + 16 * SZ_ST)      // 3 * 576*144 (input-side fp32)
#define OFF_BR    (OFF_WR + (size_t)3 * 576 * 144)
#define OFF_FWT   (OFF_BR + 4 * 576)
#define OFF_W16   (OFF_FWT + SZ_FWT)            // 4 * SZ_W16 (fp16 recurrent weights)
#define SCRATCH_TOTAL (OFF_W16 + 4 * SZ_W16)

__device__ __align__(128) float g_scratch[SCRATCH_TOTAL];

__device__ __forceinline__ float sigm(float x) { return 1.f / (1.f + expf(-x)); }

__device__ __forceinline__ float f2tf(float x) {
    uint32_t r;
    asm("cvt.rna.tf32.f32 %0, %1;" : "=r"(r) : "f"(x));
    return __uint_as_float(r);
}

// ---------------------------------------------------------------------------
// Prep kernels
// ---------------------------------------------------------------------------
__global__ void reorder_w(const float* __restrict__ in, float* __restrict__ out) {
    int idx = blockIdx.x * 256 + threadIdx.x;
    if (idx >= 576 * 144) return;
    int np = idx / 144, k = idx - np * 144;
    int j = np >> 2, g = np & 3;
    out[idx] = in[(g * 144 + j) * 144 + k];
}

// Whh [576,144] gate-major -> fp16 interleaved [576][WPAD]
__global__ void reorder_whh16(const float* __restrict__ in, __half* __restrict__ out) {
    int idx = blockIdx.x * 256 + threadIdx.x;
    if (idx >= 576 * WPAD) return;
    int np = idx / WPAD, k = idx - np * WPAD;
    int j = np >> 2, g = np & 3;
    out[idx] = (k < 144) ? __float2half(in[(g * 144 + j) * 144 + k]) : __half(0.f);
}

__global__ void reorder_b(const float* __restrict__ bih, const float* __restrict__ bhh,
                          float* __restrict__ out) {
    int np = blockIdx.x * 256 + threadIdx.x;
    if (np >= 576) return;
    int j = np >> 2, g = np & 3;
    out[np] = bih[g * 144 + j] + bhh[g * 144 + j];
}

// fW [288,264] -> fWt [320,288], zero-padded rows 264..319
__global__ void transpose_fw(const float* __restrict__ fW, float* __restrict__ fWt) {
    int idx = blockIdx.x * 256 + threadIdx.x;
    if (idx >= 320 * 288) return;
    int n = idx / 288, k = idx - n * 288;
    fWt[idx] = (n < 264) ? fW[k * 264 + n] : 0.f;
}

// ---------------------------------------------------------------------------
// GAT attention probabilities (sample 0 only)
// ---------------------------------------------------------------------------
__global__ void attn_probs(const float* __restrict__ x0, const float* __restrict__ W,
                           const float* __restrict__ bias, const float* __restrict__ a,
                           float* __restrict__ probs, int CIN, int COUT, int CSZ) {
    __shared__ float feat[12 * 24];
    __shared__ float lg[44 * 4];
    int tid = threadIdx.x;
    for (int idx = tid; idx < 12 * COUT; idx += blockDim.x) {
        int i = idx / COUT, f = idx - i * COUT;
        float acc = bias[f];
        for (int k = 0; k < CIN; k++) acc += x0[i * CIN + k] * W[k * COUT + f];
        feat[idx] = acc;
    }
    __syncthreads();
    for (int idx = tid; idx < 44 * 4; idx += blockDim.x) {
        int e = idx >> 2, h = idx & 3;
        const float* ah = a + h * 2 * CSZ;
        float s = 0.f;
        for (int c = 0; c < CSZ; c++)
            s += ah[c] * feat[c_EI[e] * COUT + h * CSZ + c] +
                 ah[CSZ + c] * feat[c_EJ[e] * COUT + h * CSZ + c];
        lg[idx] = s > 0.f ? s : 0.2f * s;
    }
    __syncthreads();
    for (int idx = tid; idx < 48; idx += blockDim.x) {
        int i = idx >> 2, h = idx & 3;
        int s0 = c_RS[i], s1 = c_RS[i + 1];
        float m = -3.4e38f;
        for (int e = s0; e < s1; e++) m = fmaxf(m, lg[e * 4 + h]);
        float sum = 0.f;
        for (int e = s0; e < s1; e++) sum += expf(lg[e * 4 + h] - m);
        float* pr = probs + (i * 4 + h) * 12;
        for (int j = 0; j < 12; j++) pr[j] = 0.f;
        for (int e = s0; e < s1; e++) pr[c_EJ[e]] = expf(lg[e * 4 + h] - m) / sum;
    }
}

// ---------------------------------------------------------------------------
// Fused GAT layer
// ---------------------------------------------------------------------------
template <int CIN, int COUT>
__global__ __launch_bounds__(256) void gat_fused(const float* __restrict__ in,
                                                 const float* __restrict__ W,
                                                 const float* __restrict__ bias,
                                                 const float* __restrict__ probs,
                                                 float* __restrict__ out) {
    constexpr int CSZ = COUT / 4;
    __shared__ float feat[8 * 12 * COUT];
    __shared__ float Ws[CIN * COUT];
    __shared__ float bs[COUT];
    __shared__ float ps[576];
    int tid = threadIdx.x;
    for (int i = tid; i < CIN * COUT; i += 256) Ws[i] = W[i];
    for (int i = tid; i < COUT; i += 256) bs[i] = bias[i];
    for (int i = tid; i < 576; i += 256) ps[i] = probs[i];
    __syncthreads();
    size_t b0 = (size_t)blockIdx.x * 8;
    for (int idx = tid; idx < 8 * 12 * COUT; idx += 256) {
        int s = idx / (12 * COUT);
        int rem = idx - s * 12 * COUT;
        int i = rem / COUT, f = rem - i * COUT;
        const float* xr = in + (b0 + s) * (12 * CIN) + i * CIN;
        float acc = bs[f];
#pragma unroll
        for (int k = 0; k < CIN; k++) acc += xr[k] * Ws[k * COUT + f];
        feat[idx] = acc;
    }
    __syncthreads();
    for (int idx = tid; idx < 8 * 12 * COUT; idx += 256) {
        int s = idx / (12 * COUT);
        int rem = idx - s * 12 * COUT;
        int i = rem / COUT, f = rem - i * COUT;
        int h = f / CSZ;
        const float* pr = ps + (i * 4 + h) * 12;
        const float* fb = feat + s * 12 * COUT + f;
        float acc = 0.f;
#pragma unroll
        for (int j = 0; j < 12; j++) acc += pr[j] * fb[j * COUT];
        out[(b0 + s) * (12 * COUT) + rem] = acc > 0.f ? acc : expm1f(acc);
    }
}

// ---------------------------------------------------------------------------
// tf32 mma GEMM (input-side pre-GEMMs and FC)
//   EPI 0: plain store (ldn = ldc); EPI 2: FC bias + leaky_relu, N guard 264
// ---------------------------------------------------------------------------
template <int BM, int EPI>
__global__ __launch_bounds__(BM * 2) void gemm_mma(
    const float* __restrict__ A, const float* __restrict__ B, int K, int ldn,
    float* __restrict__ C, const float* __restrict__ bias) {
    constexpr int NT = BM * 2;
    __shared__ float As[BM][20];
    __shared__ float Bs[64][20];

    int tid = threadIdx.x;
    int w = tid >> 5, lane = tid & 31;
    int warpM = w >> 1, warpN = w & 1;
    int group = lane >> 2, tig = lane & 3;

    float acc[2][4][4];
#pragma unroll
    for (int mt = 0; mt < 2; mt++)
#pragma unroll
        for (int nt = 0; nt < 4; nt++)
#pragma unroll
            for (int i = 0; i < 4; i++) acc[mt][nt][i] = 0.f;

    const size_t mBase = (size_t)blockIdx.y * BM;
    const int nBase = blockIdx.x * 64;

    for (int k0 = 0; k0 < K; k0 += 16) {
#pragma unroll
        for (int i = 0; i < BM * 4 / NT; i++) {
            int q = tid + i * NT;
            int row = q >> 2, kq = (q & 3) << 2;
            float4 v = *(const float4*)(A + (mBase + row) * K + k0 + kq);
            As[row][kq + 0] = f2tf(v.x); As[row][kq + 1] = f2tf(v.y);
            As[row][kq + 2] = f2tf(v.z); As[row][kq + 3] = f2tf(v.w);
        }
#pragma unroll
        for (int i = 0; i < 256 / NT; i++) {
            int q = tid + i * NT;
            int n = q >> 2, kq = (q & 3) << 2;
            float4 v = *(const float4*)(B + (size_t)(nBase + n) * K + k0 + kq);
            Bs[n][kq + 0] = f2tf(v.x); Bs[n][kq + 1] = f2tf(v.y);
            Bs[n][kq + 2] = f2tf(v.z); Bs[n][kq + 3] = f2tf(v.w);
        }
        __syncthreads();
#pragma unroll
        for (int k8 = 0; k8 < 16; k8 += 8) {
            uint32_t a[2][4], b[4][2];
#pragma unroll
            for (int mt = 0; mt < 2; mt++) {
                int r0 = warpM * 32 + mt * 16 + group;
                a[mt][0] = __float_as_uint(As[r0][k8 + tig]);
                a[mt][1] = __float_as_uint(As[r0 + 8][k8 + tig]);
                a[mt][2] = __float_as_uint(As[r0][k8 + tig + 4]);
                a[mt][3] = __float_as_uint(As[r0 + 8][k8 + tig + 4]);
            }
#pragma unroll
            for (int nt = 0; nt < 4; nt++) {
                int n0 = warpN * 32 + nt * 8 + group;
                b[nt][0] = __float_as_uint(Bs[n0][k8 + tig]);
                b[nt][1] = __float_as_uint(Bs[n0][k8 + tig + 4]);
            }
#pragma unroll
            for (int mt = 0; mt < 2; mt++)
#pragma unroll
                for (int nt = 0; nt < 4; nt++) {
                    asm volatile(
                        "mma.sync.aligned.m16n8k8.row.col.f32.tf32.tf32.f32 "
                        "{%0,%1,%2,%3}, {%4,%5,%6,%7}, {%8,%9}, {%0,%1,%2,%3};"
                        : "+f"(acc[mt][nt][0]), "+f"(acc[mt][nt][1]),
                          "+f"(acc[mt][nt][2]), "+f"(acc[mt][nt][3])
                        : "r"(a[mt][0]), "r"(a[mt][1]), "r"(a[mt][2]), "r"(a[mt][3]),
                          "r"(b[nt][0]), "r"(b[nt][1]));
                }
        }
        __syncthreads();
    }

#pragma unroll
    for (int mt = 0; mt < 2; mt++)
#pragma unroll
        for (int nt = 0; nt < 4; nt++) {
            float* a = acc[mt][nt];
            int colg = nBase + warpN * 32 + nt * 8 + 2 * tig;
            size_t row0 = mBase + warpM * 32 + mt * 16 + group;
            if (EPI == 0) {
                *(float2*)(C + row0 * ldn + colg) = make_float2(a[0], a[1]);
                *(float2*)(C + (row0 + 8) * ldn + colg) = make_float2(a[2], a[3]);
            } else {
                if (colg < 264) {
                    float bx = bias[colg], by = bias[colg + 1];
                    float v0 = a[0] + bx, v1 = a[1] + by, v2 = a[2] + bx, v3 = a[3] + by;
                    v0 = v0 >= 0.f ? v0 : 0.01f * v0;
                    v1 = v1 >= 0.f ? v1 : 0.01f * v1;
                    v2 = v2 >= 0.f ? v2 : 0.01f * v2;
                    v3 = v3 >= 0.f ? v3 : 0.01f * v3;
                    *(float2*)(C + row0 * 264 + colg) = make_float2(v0, v1);
                    *(float2*)(C + (row0 + 8) * 264 + colg) = make_float2(v2, v3);
                }
            }
        }
}

// ---------------------------------------------------------------------------
// Persistent LSTM chain kernel: one launch = 24 steps of one layer.
// Grid 128 blocks x 256 threads; block owns 32 batch rows.
// Whh (fp16, gate-interleaved [576][WPAD]) cached in smem for the whole chain.
// h fp16 ping-pong in smem, c fp32 in smem. gates = h@Whh^T + bias (+ xpre).
// ---------------------------------------------------------------------------
#define CHAIN_SMEM (576 * WPAD * 2 + 2 * 32 * WPAD * 2 + 32 * 144 * 4 + 576 * 4)

__global__ __launch_bounds__(256, 1) void lstm_chain(
    const __half* __restrict__ W16, const float* __restrict__ bias,
    const float* __restrict__ xpre, const float* __restrict__ hInit,
    float* __restrict__ y, size_t yStride) {
    extern __shared__ __align__(16) unsigned char smem_raw[];
    __half* Ws  = (__half*)smem_raw;                   // [576][WPAD]
    __half* h0s = Ws + 576 * WPAD;                     // [32][WPAD]
    __half* h1s = h0s + 32 * WPAD;
    float*  cs  = (float*)(h1s + 32 * WPAD);           // [32][144]
    float*  bs  = cs + 32 * 144;                       // [576]

    const int tid = threadIdx.x;
    const int w = tid >> 5, lane = tid & 31;
    const int warpM = w >> 2, warpN = w & 3;           // 2 x 4 warps
    const int grp = lane >> 2, tig = lane & 3;
    const int blk = blockIdx.x;
    const size_t gRowBase = (size_t)blk * 32;

    // load weights (576*WPAD halves = 10944 uint4)
    {
        const uint4* src = (const uint4*)W16;
        uint4* dst = (uint4*)Ws;
        for (int i = tid; i < 576 * WPAD / 8; i += 256) dst[i] = src[i];
    }
    // init h, c, bias
    for (int i = tid; i < 32 * WPAD; i += 256) { h0s[i] = __half(0.f); h1s[i] = __half(0.f); }
    for (int i = tid; i < 32 * 144; i += 256) cs[i] = 0.f;
    for (int i = tid; i < 576; i += 256) bs[i] = bias[i];
    __syncthreads();
    if (hInit) {
        for (int i = tid; i < 32 * 144; i += 256) {
            int r = i / 144, j = i - r * 144;
            h0s[r * WPAD + j] = __float2half(hInit[(gRowBase + r) * 144 + j]);
        }
        __syncthreads();
    }

    const int row0 = warpM * 16 + grp;                 // block-local row (and +8)

    int p = 0;
    for (int t = 0; t < PERIOD; t++) {
        const __half* hc = p ? h1s : h0s;
        __half* hn = p ? h0s : h1s;
        const float* xslice = xpre ? (xpre + (size_t)t * BB * 576) : nullptr;
        float* yslice = y + (size_t)t * yStride;

        // A fragments for all 9 k-chunks (this warp's 16 rows)
        uint32_t Areg[9][4];
        const __half* hb = hc + row0 * WPAD + 2 * tig;
#pragma unroll
        for (int kc = 0; kc < 9; kc++) {
            const __half* q = hb + kc * 16;
            Areg[kc][0] = *(const uint32_t*)(q);
            Areg[kc][1] = *(const uint32_t*)(q + 8 * WPAD);
            Areg[kc][2] = *(const uint32_t*)(q + 8);
            Areg[kc][3] = *(const uint32_t*)(q + 8 * WPAD + 8);
        }

#pragma unroll
        for (int nt = 0; nt < 18; nt++) {
            float d0 = 0.f, d1 = 0.f, d2 = 0.f, d3 = 0.f;
            const __half* wb = Ws + (warpN * 144 + nt * 8 + grp) * WPAD + 2 * tig;
#pragma unroll
            for (int kc = 0; kc < 9; kc++) {
                uint32_t b0 = *(const uint32_t*)(wb + kc * 16);
                uint32_t b1 = *(const uint32_t*)(wb + kc * 16 + 8);
                asm volatile(
                    "mma.sync.aligned.m16n8k16.row.col.f32.f16.f16.f32 "
                    "{%0,%1,%2,%3}, {%4,%5,%6,%7}, {%8,%9}, {%0,%1,%2,%3};"
                    : "+f"(d0), "+f"(d1), "+f"(d2), "+f"(d3)
                    : "r"(Areg[kc][0]), "r"(Areg[kc][1]), "r"(Areg[kc][2]),
                      "r"(Areg[kc][3]), "r"(b0), "r"(b1));
            }
            // epilogue for this n8 tile
            int colg = warpN * 144 + nt * 8 + 2 * tig;
            float v0 = d0 + bs[colg], v1 = d1 + bs[colg + 1];
            float v2 = d2 + bs[colg], v3 = d3 + bs[colg + 1];
            if (xslice) {
                float2 x0 = *(const float2*)(xslice + (gRowBase + row0) * 576 + colg);
                float2 x1 = *(const float2*)(xslice + (gRowBase + row0 + 8) * 576 + colg);
                v0 += x0.x; v1 += x0.y; v2 += x1.x; v3 += x1.y;
            }
            float o0 = __shfl_xor_sync(0xffffffffu, v0, 1);
            float o1 = __shfl_xor_sync(0xffffffffu, v1, 1);
            float o2 = __shfl_xor_sync(0xffffffffu, v2, 1);
            float o3 = __shfl_xor_sync(0xffffffffu, v3, 1);
            if (!(tig & 1)) {    // even lanes hold (i,f); partner holds (g,o)
                int j = colg >> 2;
                {
                    float c = cs[row0 * 144 + j];
                    float c2 = sigm(v1) * c + sigm(v0) * tanhf(o0);
                    float h2 = sigm(o1) * tanhf(c2);
                    cs[row0 * 144 + j] = c2;
                    hn[row0 * WPAD + j] = __float2half(h2);
                    yslice[(gRowBase + row0) * 144 + j] = h2;
                }
                {
                    float c = cs[(row0 + 8) * 144 + j];
                    float c2 = sigm(v3) * c + sigm(v2) * tanhf(o2);
                    float h2 = sigm(o3) * tanhf(c2);
                    cs[(row0 + 8) * 144 + j] = c2;
                    hn[(row0 + 8) * WPAD + j] = __float2half(h2);
                    yslice[(gRowBase + row0 + 8) * 144 + j] = h2;
                }
            }
        }
        __syncthreads();
        p ^= 1;
    }
}

// ---------------------------------------------------------------------------
// Per-row MSE
// ---------------------------------------------------------------------------
__global__ void mse_kernel(const float* __restrict__ x, const float* __restrict__ xr,
                           float* __restrict__ out, int Btot) {
    int warp = (blockIdx.x * blockDim.x + threadIdx.x) >> 5;
    int lane = threadIdx.x & 31;
    if (warp >= Btot) return;
    const float* xa = x + (size_t)warp * 264;
    const float* xb = xr + (size_t)warp * 264;
    float s = 0.f;
    for (int e = lane; e < 264; e += 32) {
        float d = xa[e] - xb[e];
        s += d * d;
    }
#pragma unroll
    for (int o = 16; o; o >>= 1) s += __shfl_xor_sync(0xffffffffu, s, o);
    if (lane == 0) out[warp] = s * (1.f / 264.f);
}

// ---------------------------------------------------------------------------
// Host orchestration
// ---------------------------------------------------------------------------
extern "C" void kernel_launch(void* const* d_in, const int* in_sizes, int n_in,
                              void* d_out, int out_size) {
    const float* x     = (const float*)d_in[0];
    const float* gW0   = (const float*)d_in[1];
    const float* gb0   = (const float*)d_in[2];
    const float* ga0   = (const float*)d_in[3];
    const float* gW1   = (const float*)d_in[4];
    const float* gb1   = (const float*)d_in[5];
    const float* ga1   = (const float*)d_in[6];
    const float* eWih0 = (const float*)d_in[7];
    const float* eWhh0 = (const float*)d_in[8];
    const float* ebih0 = (const float*)d_in[9];
    const float* ebhh0 = (const float*)d_in[10];
    const float* eWih1 = (const float*)d_in[11];
    const float* eWhh1 = (const float*)d_in[12];
    const float* ebih1 = (const float*)d_in[13];
    const float* ebhh1 = (const float*)d_in[14];
    const float* dWhh0 = (const float*)d_in[16];
    const float* dbih0 = (const float*)d_in[17];
    const float* dbhh0 = (const float*)d_in[18];
    const float* dWih1 = (const float*)d_in[19];
    const float* dWhh1 = (const float*)d_in[20];
    const float* dbih1 = (const float*)d_in[21];
    const float* dbhh1 = (const float*)d_in[22];
    const float* gW3   = (const float*)d_in[23];
    const float* gb3   = (const float*)d_in[24];
    const float* ga3   = (const float*)d_in[25];
    const float* gW4   = (const float*)d_in[26];
    const float* gb4   = (const float*)d_in[27];
    const float* ga4   = (const float*)d_in[28];
    const float* fW    = (const float*)d_in[29];
    const float* fb    = (const float*)d_in[30];

    float* S = nullptr;
    cudaGetSymbolAddress((void**)&S, g_scratch);

    const int B = in_sizes[0] / 264;   // 98304

    float* h1    = S + OFF_H1;
    float* h2    = S + OFF_H2;
    float* Xpre  = S + OFF_XPRE;
    float* y0    = S + OFF_Y0;
    float* yd0   = S + OFF_YD0;
    float* yd1   = S + OFF_YD1;
    float* h3    = S + OFF_H3;
    float* h4    = S + OFF_H4;
    float* xr    = S + OFF_XR;
    float* probs = S + OFF_PROBS;
    float* st    = S + OFF_STATE;
    float* wr    = S + OFF_WR;
    float* br    = S + OFF_BR;
    float* fWt   = S + OFF_FWT;
    __half* w16  = (__half*)(S + OFF_W16);

    float* wr_eWih0 = wr + 0 * 576 * 144;
    float* wr_eWih1 = wr + 1 * 576 * 144;
    float* wr_dWih1 = wr + 2 * 576 * 144;
    __half* w16_e0 = w16 + 0 * 576 * WPAD;
    __half* w16_e1 = w16 + 1 * 576 * WPAD;
    __half* w16_d0 = w16 + 2 * 576 * WPAD;
    __half* w16_d1 = w16 + 3 * 576 * WPAD;
    float* br_e0 = br + 0 * 576;
    float* br_e1 = br + 1 * 576;
    float* br_d0 = br + 2 * 576;
    float* br_d1 = br + 3 * 576;
    float* enc1_y = st;   // Bb*144 slot: enc1 y overwritten each step -> final h

    cudaFuncSetAttribute(lstm_chain, cudaFuncAttributeMaxDynamicSharedMemorySize,
                         CHAIN_SMEM);

    // ---- prep ----
    reorder_w<<<(576 * 144 + 255) / 256, 256>>>(eWih0, wr_eWih0);
    reorder_w<<<(576 * 144 + 255) / 256, 256>>>(eWih1, wr_eWih1);
    reorder_w<<<(576 * 144 + 255) / 256, 256>>>(dWih1, wr_dWih1);
    reorder_whh16<<<(576 * WPAD + 255) / 256, 256>>>(eWhh0, w16_e0);
    reorder_whh16<<<(576 * WPAD + 255) / 256, 256>>>(eWhh1, w16_e1);
    reorder_whh16<<<(576 * WPAD + 255) / 256, 256>>>(dWhh0, w16_d0);
    reorder_whh16<<<(576 * WPAD + 255) / 256, 256>>>(dWhh1, w16_d1);
    reorder_b<<<3, 256>>>(ebih0, ebhh0, br_e0);
    reorder_b<<<3, 256>>>(ebih1, ebhh1, br_e1);
    reorder_b<<<3, 256>>>(dbih0, dbhh0, br_d0);
    reorder_b<<<3, 256>>>(dbih1, dbhh1, br_d1);
    transpose_fw<<<(320 * 288 + 255) / 256, 256>>>(fW, fWt);

    // ---- GAT 1+2 ----
    attn_probs<<<1, 128>>>(x, gW0, gb0, ga0, probs + 0, 22, 16, 4);
    gat_fused<22, 16><<<B / 8, 256>>>(x, gW0, gb0, probs + 0, h1);
    attn_probs<<<1, 128>>>(h1, gW1, gb1, ga1, probs + 576, 16, 12, 3);
    gat_fused<16, 12><<<B / 8, 256>>>(h1, gW1, gb1, probs + 576, h2);

    dim3 gBig(9, B / 128);

    // ---- Encoder layer 0 ----
    gemm_mma<128, 0><<<gBig, 256>>>(h2, wr_eWih0, 144, 576, Xpre, nullptr);
    lstm_chain<<<BB / 32, 256, CHAIN_SMEM>>>(w16_e0, br_e0, Xpre, nullptr,
                                             y0, (size_t)BB * 144);
    // ---- Encoder layer 1 (y discarded; keep only final h in enc1_y) ----
    gemm_mma<128, 0><<<gBig, 256>>>(y0, wr_eWih1, 144, 576, Xpre, nullptr);
    lstm_chain<<<BB / 32, 256, CHAIN_SMEM>>>(w16_e1, br_e1, Xpre, nullptr,
                                             enc1_y, 0);
    // ---- Decoder layer 0 (zero inputs; h0 = enc0 final = y0[t=23]) ----
    lstm_chain<<<BB / 32, 256, CHAIN_SMEM>>>(w16_d0, br_d0, nullptr,
                                             y0 + (size_t)23 * BB * 144,
                                             yd0, (size_t)BB * 144);
    // ---- Decoder layer 1 (h0 = enc1 final) ----
    gemm_mma<128, 0><<<gBig, 256>>>(yd0, wr_dWih1, 144, 576, Xpre, nullptr);
    lstm_chain<<<BB / 32, 256, CHAIN_SMEM>>>(w16_d1, br_d1, Xpre, enc1_y,
                                             yd1, (size_t)BB * 144);

    // ---- GAT 3+4 ----
    attn_probs<<<1, 128>>>(yd1, gW3, gb3, ga3, probs + 1152, 12, 16, 4);
    gat_fused<12, 16><<<B / 8, 256>>>(yd1, gW3, gb3, probs + 1152, h3);
    attn_probs<<<1, 128>>>(h3, gW4, gb4, ga4, probs + 1728, 16, 24, 6);
    gat_fused<16, 24><<<B / 8, 256>>>(h3, gW4, gb4, probs + 1728, h4);

    // ---- FC + leaky + MSE ----
    gemm_mma<128, 2><<<dim3(5, B / 128), 256>>>(h4, fWt, 288, 264, xr, fb);
    mse_kernel<<<(B + 7) / 8, 256>>>(x, xr, (float*)d_out, B);
}

// round 7
// speedup vs baseline: 2.0364x; 1.2223x over previous
#include <cuda_runtime.h>
#include <cuda_fp16.h>
#include <cstdint>
#include <cstddef>

// ---------------------------------------------------------------------------
// Problem constants
// ---------------------------------------------------------------------------
#define NB      98304
#define PERIOD  24
#define BB      (NB / PERIOD)     // 4096
#define WPAD    152               // padded K stride (halves) for weights

__constant__ int c_EI[44] = {0,0,0,0, 1,1,1, 2,2,2, 3,3, 4,4, 5,5,5, 6,6,6,6,
                             7,7,7, 8,8,8,8, 9,9,9,9, 10,10,10,10,10,10,10,
                             11,11,11,11,11};
__constant__ int c_EJ[44] = {0,5,10,11, 1,7,10, 2,6,11, 3,6, 4,5, 0,4,5,
                             2,3,6,10, 1,7,9, 8,9,10,11, 7,8,9,10,
                             0,1,6,8,9,10,11, 0,2,8,10,11};
__constant__ int c_RS[13] = {0,4,7,10,12,14,17,21,24,28,32,39,44};

// ---------------------------------------------------------------------------
// Scratch layout (float units, all offsets multiple of 16 floats)
// ---------------------------------------------------------------------------
#define SZ_H2    ((size_t)NB * 72)      // fp16 [NB][144]
#define SZ_XPRE  ((size_t)NB * 288)     // fp16 [24][BB][576]
#define SZ_Y     ((size_t)NB * 72)      // fp16 [24][BB][144]
#define SZ_H4    ((size_t)NB * 144)     // fp16 [NB][288]
#define SZ_ENC1  ((size_t)BB * 72)      // fp16 [BB][144]
#define SZ_PART  ((size_t)10 * NB)

#define OFF_H2    ((size_t)0)
#define OFF_XPRE  (OFF_H2 + SZ_H2)
#define OFF_Y0    (OFF_XPRE + SZ_XPRE)
#define OFF_YD0   (OFF_Y0 + SZ_Y)
#define OFF_YD1   (OFF_YD0 + SZ_Y)
#define OFF_H4    (OFF_YD1 + SZ_Y)
#define OFF_ENC1  (OFF_H4 + SZ_H4)
#define OFF_PART  (OFF_ENC1 + SZ_ENC1)
#define OFF_PROBS (OFF_PART + SZ_PART)            // 4*576 floats
#define OFF_W16   (OFF_PROBS + 2304)              // 7 * 576*152 halves = 306432 fl
#define OFF_BR    (OFF_W16 + (size_t)7 * 576 * WPAD / 2)
#define OFF_FW16  (OFF_BR + 4 * 576)              // 320*288 halves = 46080 fl
#define SCRATCH_TOTAL (OFF_FW16 + (size_t)320 * 288 / 2)

__device__ __align__(128) float g_scratch[SCRATCH_TOTAL];

__device__ __forceinline__ float sigm(float x) { return 1.f / (1.f + expf(-x)); }

// ---------------------------------------------------------------------------
// One merged prep kernel
// ---------------------------------------------------------------------------
struct PrepArgs {
    const float* wsrc[7];   // gate-major [576][144]
    const float* bih[4];
    const float* bhh[4];
    const float* fW;        // [288][264]
};

#define PREP_W  (7 * 576 * WPAD)
#define PREP_B  (4 * 576)
#define PREP_F  (320 * 288)
#define PREP_TOT (PREP_W + PREP_B + PREP_F)

__global__ void prep_all(PrepArgs args, __half* w16, float* br, __half* fw16) {
    for (size_t idx = blockIdx.x * 256 + threadIdx.x; idx < PREP_TOT;
         idx += (size_t)gridDim.x * 256) {
        if (idx < PREP_W) {
            size_t m = idx / (576 * WPAD);
            int r = (int)(idx - m * (576 * WPAD));
            int np = r / WPAD, k = r - np * WPAD;
            int j = np >> 2, g = np & 3;
            w16[idx] = (k < 144)
                ? __float2half(args.wsrc[m][(g * 144 + j) * 144 + k]) : __half(0.f);
        } else if (idx < PREP_W + PREP_B) {
            int e = (int)(idx - PREP_W);
            int b = e / 576, np = e - b * 576;
            int j = np >> 2, g = np & 3;
            br[e] = args.bih[b][g * 144 + j] + args.bhh[b][g * 144 + j];
        } else {
            int e = (int)(idx - PREP_W - PREP_B);
            int n = e / 288, k = e - n * 288;
            fw16[e] = (n < 264) ? __float2half(args.fW[k * 264 + n]) : __half(0.f);
        }
    }
}

// ---------------------------------------------------------------------------
// Attention probs for a PAIR of GAT layers (sample 0 only); one tiny block.
// ---------------------------------------------------------------------------
template <int CI1, int CO1, int CI2, int CO2, bool HALFIN>
__global__ void attn_pair(const void* xin,
                          const float* W1, const float* b1, const float* a1,
                          const float* W2, const float* b2, const float* a2,
                          float* probs1, float* probs2) {
    constexpr int CS1 = CO1 / 4, CS2 = CO2 / 4;
    __shared__ float x0[12 * CI1];
    __shared__ float feat[12 * CO1];
    __shared__ float lg[44 * 4];
    __shared__ float h1s[12 * CI2];
    __shared__ float feat2[12 * CO2];
    int tid = threadIdx.x;

    for (int i = tid; i < 12 * CI1; i += 128)
        x0[i] = HALFIN ? __half2float(((const __half*)xin)[i]) : ((const float*)xin)[i];
    __syncthreads();
    for (int idx = tid; idx < 12 * CO1; idx += 128) {
        int i = idx / CO1, f = idx - i * CO1;
        float acc = b1[f];
        for (int k = 0; k < CI1; k++) acc += x0[i * CI1 + k] * W1[k * CO1 + f];
        feat[idx] = acc;
    }
    __syncthreads();
    for (int idx = tid; idx < 176; idx += 128) {
        int e = idx >> 2, h = idx & 3;
        const float* ah = a1 + h * 2 * CS1;
        float s = 0.f;
        for (int c = 0; c < CS1; c++)
            s += ah[c] * feat[c_EI[e] * CO1 + h * CS1 + c] +
                 ah[CS1 + c] * feat[c_EJ[e] * CO1 + h * CS1 + c];
        lg[idx] = s > 0.f ? s : 0.2f * s;
    }
    __syncthreads();
    for (int idx = tid; idx < 48; idx += 128) {
        int i = idx >> 2, h = idx & 3;
        int s0 = c_RS[i], s1 = c_RS[i + 1];
        float m = -3.4e38f;
        for (int e = s0; e < s1; e++) m = fmaxf(m, lg[e * 4 + h]);
        float sum = 0.f;
        for (int e = s0; e < s1; e++) sum += expf(lg[e * 4 + h] - m);
        float* pr = probs1 + (i * 4 + h) * 12;
        for (int j = 0; j < 12; j++) pr[j] = 0.f;
        for (int e = s0; e < s1; e++) pr[c_EJ[e]] = expf(lg[e * 4 + h] - m) / sum;
    }
    __syncthreads();
    // h1_0 = elu(probs1-aggregate(feat))
    for (int idx = tid; idx < 12 * CO1; idx += 128) {
        int i = idx / CO1, f = idx - i * CO1;
        int h = f / CS1;
        const float* pr = probs1 + (i * 4 + h) * 12;
        float acc = 0.f;
        for (int j = 0; j < 12; j++) acc += pr[j] * feat[j * CO1 + f];
        h1s[idx] = acc > 0.f ? acc : expm1f(acc);
    }
    __syncthreads();
    for (int idx = tid; idx < 12 * CO2; idx += 128) {
        int i = idx / CO2, f = idx - i * CO2;
        float acc = b2[f];
        for (int k = 0; k < CI2; k++) acc += h1s[i * CI2 + k] * W2[k * CO2 + f];
        feat2[idx] = acc;
    }
    __syncthreads();
    for (int idx = tid; idx < 176; idx += 128) {
        int e = idx >> 2, h = idx & 3;
        const float* ah = a2 + h * 2 * CS2;
        float s = 0.f;
        for (int c = 0; c < CS2; c++)
            s += ah[c] * feat2[c_EI[e] * CO2 + h * CS2 + c] +
                 ah[CS2 + c] * feat2[c_EJ[e] * CO2 + h * CS2 + c];
        lg[idx] = s > 0.f ? s : 0.2f * s;
    }
    __syncthreads();
    for (int idx = tid; idx < 48; idx += 128) {
        int i = idx >> 2, h = idx & 3;
        int s0 = c_RS[i], s1 = c_RS[i + 1];
        float m = -3.4e38f;
        for (int e = s0; e < s1; e++) m = fmaxf(m, lg[e * 4 + h]);
        float sum = 0.f;
        for (int e = s0; e < s1; e++) sum += expf(lg[e * 4 + h] - m);
        float* pr = probs2 + (i * 4 + h) * 12;
        for (int j = 0; j < 12; j++) pr[j] = 0.f;
        for (int e = s0; e < s1; e++) pr[c_EJ[e]] = expf(lg[e * 4 + h] - m) / sum;
    }
}

// ---------------------------------------------------------------------------
// Fused PAIR of GAT layers; 8 samples per block; fp16 output.
// ---------------------------------------------------------------------------
template <int CI1, int CO1, int CO2, bool HALFIN>
__global__ __launch_bounds__(256) void gat_pair(const void* in,
                                                const float* W1f, const float* b1f,
                                                const float* W2f, const float* b2f,
                                                const float* p1g, const float* p2g,
                                                __half* out) {
    constexpr int CS1 = CO1 / 4, CS2 = CO2 / 4;
    __shared__ float W1s[CI1 * CO1];
    __shared__ float W2s[CO1 * CO2];
    __shared__ float b1s[CO1], b2s[CO2];
    __shared__ float p1[576], p2[576];
    __shared__ float fA[8 * 12 * CO1];
    __shared__ float fB[8 * 12 * CO1];
    __shared__ float fC[8 * 12 * CO2];
    int tid = threadIdx.x;
    for (int i = tid; i < CI1 * CO1; i += 256) W1s[i] = W1f[i];
    for (int i = tid; i < CO1 * CO2; i += 256) W2s[i] = W2f[i];
    for (int i = tid; i < CO1; i += 256) b1s[i] = b1f[i];
    for (int i = tid; i < CO2; i += 256) b2s[i] = b2f[i];
    for (int i = tid; i < 576; i += 256) { p1[i] = p1g[i]; p2[i] = p2g[i]; }
    __syncthreads();
    size_t b0 = (size_t)blockIdx.x * 8;
    // feat1 = in @ W1 + b1
    for (int idx = tid; idx < 8 * 12 * CO1; idx += 256) {
        int s = idx / (12 * CO1);
        int rem = idx - s * 12 * CO1;
        int i = rem / CO1, f = rem - i * CO1;
        float acc = b1s[f];
        if (HALFIN) {
            const __half* xr = (const __half*)in + (b0 + s) * (12 * CI1) + i * CI1;
#pragma unroll
            for (int k = 0; k < CI1; k++) acc += __half2float(xr[k]) * W1s[k * CO1 + f];
        } else {
            const float* xr = (const float*)in + (b0 + s) * (12 * CI1) + i * CI1;
#pragma unroll
            for (int k = 0; k < CI1; k++) acc += xr[k] * W1s[k * CO1 + f];
        }
        fA[idx] = acc;
    }
    __syncthreads();
    // agg1 = elu(p1 . feat1)
    for (int idx = tid; idx < 8 * 12 * CO1; idx += 256) {
        int s = idx / (12 * CO1);
        int rem = idx - s * 12 * CO1;
        int i = rem / CO1, f = rem - i * CO1;
        int h = f / CS1;
        const float* pr = p1 + (i * 4 + h) * 12;
        const float* fb = fA + s * 12 * CO1 + f;
        float acc = 0.f;
#pragma unroll
        for (int j = 0; j < 12; j++) acc += pr[j] * fb[j * CO1];
        fB[idx] = acc > 0.f ? acc : expm1f(acc);
    }
    __syncthreads();
    // feat2 = agg1 @ W2 + b2
    for (int idx = tid; idx < 8 * 12 * CO2; idx += 256) {
        int s = idx / (12 * CO2);
        int rem = idx - s * 12 * CO2;
        int i = rem / CO2, f = rem - i * CO2;
        const float* xr = fB + s * 12 * CO1 + i * CO1;
        float acc = b2s[f];
#pragma unroll
        for (int k = 0; k < CO1; k++) acc += xr[k] * W2s[k * CO2 + f];
        fC[idx] = acc;
    }
    __syncthreads();
    // out = elu(p2 . feat2)  (fp16)
    for (int idx = tid; idx < 8 * 12 * CO2; idx += 256) {
        int s = idx / (12 * CO2);
        int rem = idx - s * 12 * CO2;
        int i = rem / CO2, f = rem - i * CO2;
        int h = f / CS2;
        const float* pr = p2 + (i * 4 + h) * 12;
        const float* fb = fC + s * 12 * CO2 + f;
        float acc = 0.f;
#pragma unroll
        for (int j = 0; j < 12; j++) acc += pr[j] * fb[j * CO2];
        out[(b0 + s) * (12 * CO2) + rem] = __float2half(acc > 0.f ? acc : expm1f(acc));
    }
}

// ---------------------------------------------------------------------------
// fp16 MMA GEMM: C[M,64-block] = A[M,K](fp16) @ B[N,K](fp16)^T
//  EPI 0: store fp16 to C with row stride 576 (Xpre)
//  EPI 1: FC: +bias, leaky_relu(0.01), (x - v)^2 partial row sums -> part
// 128x64 tile, 256 threads, 8 warps (4M x 2N), warp tile 32x32.
// ---------------------------------------------------------------------------
template <int K, int EPI>
__global__ __launch_bounds__(256) void gemm_h(
    const __half* __restrict__ A, int lda, const __half* __restrict__ Bw, int ldb,
    __half* __restrict__ C, const float* __restrict__ bias,
    const float* __restrict__ x, float* __restrict__ part) {
    __shared__ __half As[128][56];
    __shared__ __half Bs[64][56];
    int tid = threadIdx.x;
    int w = tid >> 5, lane = tid & 31;
    int warpM = w >> 1, warpN = w & 1;
    int grp = lane >> 2, tig = lane & 3;

    float acc[2][4][4];
#pragma unroll
    for (int mt = 0; mt < 2; mt++)
#pragma unroll
        for (int nt = 0; nt < 4; nt++)
#pragma unroll
            for (int i = 0; i < 4; i++) acc[mt][nt][i] = 0.f;

    const size_t mBase = (size_t)blockIdx.y * 128;
    const int nBase = blockIdx.x * 64;

    for (int k0 = 0; k0 < K; k0 += 48) {
        // A tile: 128 rows x 48 halves = 768 uint4
#pragma unroll
        for (int i = 0; i < 3; i++) {
            int q = tid + i * 256;
            int row = q / 6, off = (q - row * 6) * 8;
            uint4 v = *(const uint4*)(A + (mBase + row) * lda + k0 + off);
            *(uint4*)&As[row][off] = v;
        }
        // B tile: 64 rows x 48 halves = 384 uint4
#pragma unroll
        for (int i = 0; i < 2; i++) {
            int q = tid + i * 256;
            if (q < 384) {
                int n = q / 6, off = (q - n * 6) * 8;
                uint4 v = *(const uint4*)(Bw + (size_t)(nBase + n) * ldb + k0 + off);
                *(uint4*)&Bs[n][off] = v;
            }
        }
        __syncthreads();
#pragma unroll
        for (int kc = 0; kc < 3; kc++) {
            uint32_t a[2][4], b[4][2];
#pragma unroll
            for (int mt = 0; mt < 2; mt++) {
                const __half* ab = &As[warpM * 32 + mt * 16 + grp][kc * 16 + 2 * tig];
                a[mt][0] = *(const uint32_t*)(ab);
                a[mt][1] = *(const uint32_t*)(ab + 8 * 56);
                a[mt][2] = *(const uint32_t*)(ab + 8);
                a[mt][3] = *(const uint32_t*)(ab + 8 * 56 + 8);
            }
#pragma unroll
            for (int nt = 0; nt < 4; nt++) {
                const __half* bb = &Bs[warpN * 32 + nt * 8 + grp][kc * 16 + 2 * tig];
                b[nt][0] = *(const uint32_t*)(bb);
                b[nt][1] = *(const uint32_t*)(bb + 8);
            }
#pragma unroll
            for (int mt = 0; mt < 2; mt++)
#pragma unroll
                for (int nt = 0; nt < 4; nt++) {
                    asm volatile(
                        "mma.sync.aligned.m16n8k16.row.col.f32.f16.f16.f32 "
                        "{%0,%1,%2,%3}, {%4,%5,%6,%7}, {%8,%9}, {%0,%1,%2,%3};"
                        : "+f"(acc[mt][nt][0]), "+f"(acc[mt][nt][1]),
                          "+f"(acc[mt][nt][2]), "+f"(acc[mt][nt][3])
                        : "r"(a[mt][0]), "r"(a[mt][1]), "r"(a[mt][2]), "r"(a[mt][3]),
                          "r"(b[nt][0]), "r"(b[nt][1]));
                }
        }
        __syncthreads();
    }

    if (EPI == 0) {
#pragma unroll
        for (int mt = 0; mt < 2; mt++)
#pragma unroll
            for (int nt = 0; nt < 4; nt++) {
                float* a = acc[mt][nt];
                int colg = nBase + warpN * 32 + nt * 8 + 2 * tig;
                size_t row0 = mBase + warpM * 32 + mt * 16 + grp;
                *(__half2*)(C + row0 * 576 + colg) = __floats2half2_rn(a[0], a[1]);
                *(__half2*)(C + (row0 + 8) * 576 + colg) = __floats2half2_rn(a[2], a[3]);
            }
    } else {
        float s[2][2] = {{0.f, 0.f}, {0.f, 0.f}};
#pragma unroll
        for (int mt = 0; mt < 2; mt++)
#pragma unroll
            for (int nt = 0; nt < 4; nt++) {
                int colg = nBase + warpN * 32 + nt * 8 + 2 * tig;
                if (colg >= 264) continue;
                float* a = acc[mt][nt];
                size_t row0 = mBase + warpM * 32 + mt * 16 + grp;
                float bx = bias[colg], by = bias[colg + 1];
                float v0 = a[0] + bx, v1 = a[1] + by, v2 = a[2] + bx, v3 = a[3] + by;
                v0 = v0 >= 0.f ? v0 : 0.01f * v0;
                v1 = v1 >= 0.f ? v1 : 0.01f * v1;
                v2 = v2 >= 0.f ? v2 : 0.01f * v2;
                v3 = v3 >= 0.f ? v3 : 0.01f * v3;
                float2 xa = *(const float2*)(x + row0 * 264 + colg);
                float2 xb = *(const float2*)(x + (row0 + 8) * 264 + colg);
                float d0 = xa.x - v0, d1 = xa.y - v1, d2 = xb.x - v2, d3 = xb.y - v3;
                s[mt][0] += d0 * d0 + d1 * d1;
                s[mt][1] += d2 * d2 + d3 * d3;
            }
        int slice = blockIdx.x * 2 + warpN;
#pragma unroll
        for (int mt = 0; mt < 2; mt++) {
            size_t row0 = mBase + warpM * 32 + mt * 16 + grp;
            float v0 = s[mt][0], v1 = s[mt][1];
            v0 += __shfl_xor_sync(0xffffffffu, v0, 1);
            v0 += __shfl_xor_sync(0xffffffffu, v0, 2);
            v1 += __shfl_xor_sync(0xffffffffu, v1, 1);
            v1 += __shfl_xor_sync(0xffffffffu, v1, 2);
            if (tig == 0) {
                part[(size_t)slice * NB + row0] = v0;
                part[(size_t)slice * NB + row0 + 8] = v1;
            }
        }
    }
}

__global__ void mse_final(const float* __restrict__ part, float* __restrict__ out) {
    int idx = blockIdx.x * 256 + threadIdx.x;
    if (idx >= NB) return;
    float s = 0.f;
#pragma unroll
    for (int k = 0; k < 10; k++) s += part[(size_t)k * NB + idx];
    out[idx] = s * (1.f / 264.f);
}

// ---------------------------------------------------------------------------
// Persistent LSTM chain: one launch = 24 steps. 128 blocks x 256 threads.
// Whh fp16 in smem; h fp16 ping-pong; c fp32. xpre/y/hInit fp16.
// ---------------------------------------------------------------------------
#define CHAIN_SMEM (576 * WPAD * 2 + 2 * 32 * WPAD * 2 + 32 * 144 * 4 + 576 * 4)

__global__ __launch_bounds__(256, 1) void lstm_chain(
    const __half* __restrict__ W16, const float* __restrict__ bias,
    const __half* __restrict__ xpre, const __half* __restrict__ hInit,
    __half* __restrict__ y, size_t yStride) {
    extern __shared__ __align__(16) unsigned char smem_raw[];
    __half* Ws  = (__half*)smem_raw;                   // [576][WPAD]
    __half* h0s = Ws + 576 * WPAD;                     // [32][WPAD]
    __half* h1s = h0s + 32 * WPAD;
    float*  cs  = (float*)(h1s + 32 * WPAD);           // [32][144]
    float*  bs  = cs + 32 * 144;                       // [576]

    const int tid = threadIdx.x;
    const int w = tid >> 5, lane = tid & 31;
    const int warpM = w >> 2, warpN = w & 3;           // 2 x 4 warps
    const int grp = lane >> 2, tig = lane & 3;
    const size_t gRowBase = (size_t)blockIdx.x * 32;

    {
        const uint4* src = (const uint4*)W16;
        uint4* dst = (uint4*)Ws;
        for (int i = tid; i < 576 * WPAD / 8; i += 256) dst[i] = src[i];
    }
    for (int i = tid; i < 32 * WPAD; i += 256) { h0s[i] = __half(0.f); h1s[i] = __half(0.f); }
    for (int i = tid; i < 32 * 144; i += 256) cs[i] = 0.f;
    for (int i = tid; i < 576; i += 256) bs[i] = bias[i];
    __syncthreads();
    if (hInit) {
        for (int i = tid; i < 32 * 144; i += 256) {
            int r = i / 144, j = i - r * 144;
            h0s[r * WPAD + j] = hInit[(gRowBase + r) * 144 + j];
        }
        __syncthreads();
    }

    const int row0 = warpM * 16 + grp;

    int p = 0;
    for (int t = 0; t < PERIOD; t++) {
        const __half* hc = p ? h1s : h0s;
        __half* hn = p ? h0s : h1s;
        const __half* xslice = xpre ? (xpre + (size_t)t * BB * 576) : nullptr;
        __half* yslice = y + (size_t)t * yStride;

        uint32_t Areg[9][4];
        const __half* hb = hc + row0 * WPAD + 2 * tig;
#pragma unroll
        for (int kc = 0; kc < 9; kc++) {
            const __half* q = hb + kc * 16;
            Areg[kc][0] = *(const uint32_t*)(q);
            Areg[kc][1] = *(const uint32_t*)(q + 8 * WPAD);
            Areg[kc][2] = *(const uint32_t*)(q + 8);
            Areg[kc][3] = *(const uint32_t*)(q + 8 * WPAD + 8);
        }

#pragma unroll
        for (int nt = 0; nt < 18; nt++) {
            float d0 = 0.f, d1 = 0.f, d2 = 0.f, d3 = 0.f;
            const __half* wb = Ws + (warpN * 144 + nt * 8 + grp) * WPAD + 2 * tig;
#pragma unroll
            for (int kc = 0; kc < 9; kc++) {
                uint32_t b0 = *(const uint32_t*)(wb + kc * 16);
                uint32_t b1 = *(const uint32_t*)(wb + kc * 16 + 8);
                asm volatile(
                    "mma.sync.aligned.m16n8k16.row.col.f32.f16.f16.f32 "
                    "{%0,%1,%2,%3}, {%4,%5,%6,%7}, {%8,%9}, {%0,%1,%2,%3};"
                    : "+f"(d0), "+f"(d1), "+f"(d2), "+f"(d3)
                    : "r"(Areg[kc][0]), "r"(Areg[kc][1]), "r"(Areg[kc][2]),
                      "r"(Areg[kc][3]), "r"(b0), "r"(b1));
            }
            int colg = warpN * 144 + nt * 8 + 2 * tig;
            float v0 = d0 + bs[colg], v1 = d1 + bs[colg + 1];
            float v2 = d2 + bs[colg], v3 = d3 + bs[colg + 1];
            if (xslice) {
                __half2 x0 = *(const __half2*)(xslice + (gRowBase + row0) * 576 + colg);
                __half2 x1 = *(const __half2*)(xslice + (gRowBase + row0 + 8) * 576 + colg);
                v0 += __half2float(x0.x); v1 += __half2float(x0.y);
                v2 += __half2float(x1.x); v3 += __half2float(x1.y);
            }
            float o0 = __shfl_xor_sync(0xffffffffu, v0, 1);
            float o1 = __shfl_xor_sync(0xffffffffu, v1, 1);
            float o2 = __shfl_xor_sync(0xffffffffu, v2, 1);
            float o3 = __shfl_xor_sync(0xffffffffu, v3, 1);
            if (!(tig & 1)) {
                int j = colg >> 2;
                {
                    float c = cs[row0 * 144 + j];
                    float c2 = sigm(v1) * c + sigm(v0) * tanhf(o0);
                    float h2 = sigm(o1) * tanhf(c2);
                    cs[row0 * 144 + j] = c2;
                    __half hh = __float2half(h2);
                    hn[row0 * WPAD + j] = hh;
                    yslice[(gRowBase + row0) * 144 + j] = hh;
                }
                {
                    float c = cs[(row0 + 8) * 144 + j];
                    float c2 = sigm(v3) * c + sigm(v2) * tanhf(o2);
                    float h2 = sigm(o3) * tanhf(c2);
                    cs[(row0 + 8) * 144 + j] = c2;
                    __half hh = __float2half(h2);
                    hn[(row0 + 8) * WPAD + j] = hh;
                    yslice[(gRowBase + row0 + 8) * 144 + j] = hh;
                }
            }
        }
        __syncthreads();
        p ^= 1;
    }
}

// ---------------------------------------------------------------------------
// Host orchestration
// ---------------------------------------------------------------------------
extern "C" void kernel_launch(void* const* d_in, const int* in_sizes, int n_in,
                              void* d_out, int out_size) {
    const float* x     = (const float*)d_in[0];
    const float* gW0   = (const float*)d_in[1];
    const float* gb0   = (const float*)d_in[2];
    const float* ga0   = (const float*)d_in[3];
    const float* gW1   = (const float*)d_in[4];
    const float* gb1   = (const float*)d_in[5];
    const float* ga1   = (const float*)d_in[6];
    const float* eWih0 = (const float*)d_in[7];
    const float* eWhh0 = (const float*)d_in[8];
    const float* ebih0 = (const float*)d_in[9];
    const float* ebhh0 = (const float*)d_in[10];
    const float* eWih1 = (const float*)d_in[11];
    const float* eWhh1 = (const float*)d_in[12];
    const float* ebih1 = (const float*)d_in[13];
    const float* ebhh1 = (const float*)d_in[14];
    const float* dWhh0 = (const float*)d_in[16];
    const float* dbih0 = (const float*)d_in[17];
    const float* dbhh0 = (const float*)d_in[18];
    const float* dWih1 = (const float*)d_in[19];
    const float* dWhh1 = (const float*)d_in[20];
    const float* dbih1 = (const float*)d_in[21];
    const float* dbhh1 = (const float*)d_in[22];
    const float* gW3   = (const float*)d_in[23];
    const float* gb3   = (const float*)d_in[24];
    const float* ga3   = (const float*)d_in[25];
    const float* gW4   = (const float*)d_in[26];
    const float* gb4   = (const float*)d_in[27];
    const float* ga4   = (const float*)d_in[28];
    const float* fW    = (const float*)d_in[29];
    const float* fb    = (const float*)d_in[30];

    float* S = nullptr;
    cudaGetSymbolAddress((void**)&S, g_scratch);

    __half* h2_16   = (__half*)(S + OFF_H2);
    __half* Xpre16  = (__half*)(S + OFF_XPRE);
    __half* y0_16   = (__half*)(S + OFF_Y0);
    __half* yd0_16  = (__half*)(S + OFF_YD0);
    __half* yd1_16  = (__half*)(S + OFF_YD1);
    __half* h4_16   = (__half*)(S + OFF_H4);
    __half* enc1_16 = (__half*)(S + OFF_ENC1);
    float*  part    = S + OFF_PART;
    float*  probs   = S + OFF_PROBS;
    __half* w16     = (__half*)(S + OFF_W16);
    float*  br      = S + OFF_BR;
    __half* fw16    = (__half*)(S + OFF_FW16);

    const size_t WSLICE = (size_t)576 * WPAD;
    // w16 slot order: 0 eWih0, 1 eWhh0, 2 eWih1, 3 eWhh1, 4 dWhh0, 5 dWih1, 6 dWhh1
    __half* w_eWih0 = w16 + 0 * WSLICE;
    __half* w_eWhh0 = w16 + 1 * WSLICE;
    __half* w_eWih1 = w16 + 2 * WSLICE;
    __half* w_eWhh1 = w16 + 3 * WSLICE;
    __half* w_dWhh0 = w16 + 4 * WSLICE;
    __half* w_dWih1 = w16 + 5 * WSLICE;
    __half* w_dWhh1 = w16 + 6 * WSLICE;

    cudaFuncSetAttribute(lstm_chain, cudaFuncAttributeMaxDynamicSharedMemorySize,
                         CHAIN_SMEM);

    // ---- prep (single kernel) ----
    PrepArgs pa;
    pa.wsrc[0] = eWih0; pa.wsrc[1] = eWhh0; pa.wsrc[2] = eWih1; pa.wsrc[3] = eWhh1;
    pa.wsrc[4] = dWhh0; pa.wsrc[5] = dWih1; pa.wsrc[6] = dWhh1;
    pa.bih[0] = ebih0; pa.bih[1] = ebih1; pa.bih[2] = dbih0; pa.bih[3] = dbih1;
    pa.bhh[0] = ebhh0; pa.bhh[1] = ebhh1; pa.bhh[2] = dbhh0; pa.bhh[3] = dbhh1;
    pa.fW = fW;
    prep_all<<<(PREP_TOT + 255) / 256, 256>>>(pa, w16, br, fw16);

    // ---- GAT 1+2 ----
    attn_pair<22, 16, 16, 12, false><<<1, 128>>>(x, gW0, gb0, ga0, gW1, gb1, ga1,
                                                 probs, probs + 576);
    gat_pair<22, 16, 12, false><<<NB / 8, 256>>>(x, gW0, gb0, gW1, gb1,
                                                 probs, probs + 576, h2_16);

    dim3 gPre(9, NB / 128);

    // ---- Encoder layer 0 ----
    gemm_h<144, 0><<<gPre, 256>>>(h2_16, 144, w_eWih0, WPAD, Xpre16, nullptr,
                                  nullptr, nullptr);
    lstm_chain<<<BB / 32, 256, CHAIN_SMEM>>>(w_eWhh0, br + 0, Xpre16, nullptr,
                                             y0_16, (size_t)BB * 144);
    // ---- Encoder layer 1 ----
    gemm_h<144, 0><<<gPre, 256>>>(y0_16, 144, w_eWih1, WPAD, Xpre16, nullptr,
                                  nullptr, nullptr);
    lstm_chain<<<BB / 32, 256, CHAIN_SMEM>>>(w_eWhh1, br + 576, Xpre16, nullptr,
                                             enc1_16, 0);
    // ---- Decoder layer 0 (zero inputs; h0 = enc0 final = y0[t=23]) ----
    lstm_chain<<<BB / 32, 256, CHAIN_SMEM>>>(w_dWhh0, br + 1152, nullptr,
                                             y0_16 + (size_t)23 * BB * 144,
                                             yd0_16, (size_t)BB * 144);
    // ---- Decoder layer 1 (h0 = enc1 final) ----
    gemm_h<144, 0><<<gPre, 256>>>(yd0_16, 144, w_dWih1, WPAD, Xpre16, nullptr,
                                  nullptr, nullptr);
    lstm_chain<<<BB / 32, 256, CHAIN_SMEM>>>(w_dWhh1, br + 1728, Xpre16, enc1_16,
                                             yd1_16, (size_t)BB * 144);

    // ---- GAT 3+4 ----
    attn_pair<12, 16, 16, 24, true><<<1, 128>>>(yd1_16, gW3, gb3, ga3, gW4, gb4, ga4,
                                                probs + 1152, probs + 1728);
    gat_pair<12, 16, 24, true><<<NB / 8, 256>>>(yd1_16, gW3, gb3, gW4, gb4,
                                                probs + 1152, probs + 1728, h4_16);

    // ---- FC + leaky + MSE partials + final ----
    gemm_h<288, 1><<<dim3(5, NB / 128), 256>>>(h4_16, 288, fw16, 288, nullptr, fb,
                                               x, part);
    mse_final<<<(NB + 255) / 256, 256>>>(part, (float*)d_out);
}

// round 8
// speedup vs baseline: 2.5422x; 1.2484x over previous
#include <cuda_runtime.h>
#include <cuda_fp16.h>
#include <cstdint>
#include <cstddef>

// ---------------------------------------------------------------------------
// Problem constants
// ---------------------------------------------------------------------------
#define NB      98304
#define PERIOD  24
#define BB      (NB / PERIOD)     // 4096
#define WPAD    152               // padded K stride (halves) for weights

__constant__ int c_EI[44] = {0,0,0,0, 1,1,1, 2,2,2, 3,3, 4,4, 5,5,5, 6,6,6,6,
                             7,7,7, 8,8,8,8, 9,9,9,9, 10,10,10,10,10,10,10,
                             11,11,11,11,11};
__constant__ int c_EJ[44] = {0,5,10,11, 1,7,10, 2,6,11, 3,6, 4,5, 0,4,5,
                             2,3,6,10, 1,7,9, 8,9,10,11, 7,8,9,10,
                             0,1,6,8,9,10,11, 0,2,8,10,11};
__constant__ int c_RS[13] = {0,4,7,10,12,14,17,21,24,28,32,39,44};

// ---------------------------------------------------------------------------
// Scratch layout
// ---------------------------------------------------------------------------
#define SZ_H2    ((size_t)NB * 72)      // fp16 [NB][144]
#define SZ_XPRE  ((size_t)NB * 288)     // fp16 [24][BB][576]
#define SZ_Y     ((size_t)NB * 72)      // fp16 [24][BB][144]
#define SZ_H4    ((size_t)NB * 144)     // fp16 [NB][288]
#define SZ_ENC1  ((size_t)BB * 72)      // fp16 [BB][144]
#define SZ_PART  ((size_t)10 * NB)

#define OFF_H2    ((size_t)0)
#define OFF_XPRE  (OFF_H2 + SZ_H2)
#define OFF_Y0    (OFF_XPRE + SZ_XPRE)
#define OFF_YD0   (OFF_Y0 + SZ_Y)
#define OFF_YD1   (OFF_YD0 + SZ_Y)
#define OFF_H4    (OFF_YD1 + SZ_Y)
#define OFF_ENC1  (OFF_H4 + SZ_H4)
#define OFF_PART  (OFF_ENC1 + SZ_ENC1)
#define OFF_PROBS (OFF_PART + SZ_PART)            // 4*576 floats
#define OFF_W16   (OFF_PROBS + 2304)
#define OFF_BR    (OFF_W16 + (size_t)7 * 576 * WPAD / 2)
#define OFF_FW16  (OFF_BR + 4 * 576)
#define SCRATCH_TOTAL (OFF_FW16 + (size_t)320 * 288 / 2)

__device__ __align__(128) float g_scratch[SCRATCH_TOTAL];

__device__ __forceinline__ float sigm(float x) { return 1.f / (1.f + __expf(-x)); }
__device__ __forceinline__ float ftanh(float x) { return 2.f / (1.f + __expf(-2.f * x)) - 1.f; }
__device__ __forceinline__ float felu(float x) { return x > 0.f ? x : (__expf(x) - 1.f); }

__device__ __forceinline__ uint32_t smem_u32(const void* p) {
    return (uint32_t)__cvta_generic_to_shared(p);
}
__device__ __forceinline__ void ldm_x4(uint32_t& r0, uint32_t& r1, uint32_t& r2,
                                       uint32_t& r3, const void* p) {
    asm volatile("ldmatrix.sync.aligned.m8n8.x4.shared.b16 {%0,%1,%2,%3}, [%4];"
                 : "=r"(r0), "=r"(r1), "=r"(r2), "=r"(r3) : "r"(smem_u32(p)));
}
#define MMA16(d0,d1,d2,d3,a0,a1,a2,a3,b0,b1)                                    \
    asm volatile("mma.sync.aligned.m16n8k16.row.col.f32.f16.f16.f32 "           \
                 "{%0,%1,%2,%3}, {%4,%5,%6,%7}, {%8,%9}, {%0,%1,%2,%3};"        \
                 : "+f"(d0), "+f"(d1), "+f"(d2), "+f"(d3)                       \
                 : "r"(a0), "r"(a1), "r"(a2), "r"(a3), "r"(b0), "r"(b1))

// ---------------------------------------------------------------------------
// Merged prep kernel
// ---------------------------------------------------------------------------
struct PrepArgs {
    const float* wsrc[7];
    const float* bih[4];
    const float* bhh[4];
    const float* fW;
};
#define PREP_W  (7 * 576 * WPAD)
#define PREP_B  (4 * 576)
#define PREP_F  (320 * 288)
#define PREP_TOT (PREP_W + PREP_B + PREP_F)

__global__ void prep_all(PrepArgs args, __half* w16, float* br, __half* fw16) {
    for (size_t idx = blockIdx.x * 256 + threadIdx.x; idx < PREP_TOT;
         idx += (size_t)gridDim.x * 256) {
        if (idx < PREP_W) {
            size_t m = idx / (576 * WPAD);
            int r = (int)(idx - m * (576 * WPAD));
            int np = r / WPAD, k = r - np * WPAD;
            int j = np >> 2, g = np & 3;
            w16[idx] = (k < 144)
                ? __float2half(args.wsrc[m][(g * 144 + j) * 144 + k]) : __half(0.f);
        } else if (idx < PREP_W + PREP_B) {
            int e = (int)(idx - PREP_W);
            int b = e / 576, np = e - b * 576;
            int j = np >> 2, g = np & 3;
            br[e] = args.bih[b][g * 144 + j] + args.bhh[b][g * 144 + j];
        } else {
            int e = (int)(idx - PREP_W - PREP_B);
            int n = e / 288, k = e - n * 288;
            fw16[e] = (n < 264) ? __float2half(args.fW[k * 264 + n]) : __half(0.f);
        }
    }
}

// ---------------------------------------------------------------------------
// Attention probs for a PAIR of GAT layers (sample 0 only)
// ---------------------------------------------------------------------------
template <int CI1, int CO1, int CI2, int CO2, bool HALFIN>
__global__ void attn_pair(const void* xin,
                          const float* W1, const float* b1, const float* a1,
                          const float* W2, const float* b2, const float* a2,
                          float* probs1, float* probs2) {
    constexpr int CS1 = CO1 / 4, CS2 = CO2 / 4;
    __shared__ float x0[12 * CI1];
    __shared__ float feat[12 * CO1];
    __shared__ float lg[44 * 4];
    __shared__ float h1s[12 * CI2];
    __shared__ float feat2[12 * CO2];
    int tid = threadIdx.x;

    for (int i = tid; i < 12 * CI1; i += 128)
        x0[i] = HALFIN ? __half2float(((const __half*)xin)[i]) : ((const float*)xin)[i];
    __syncthreads();
    for (int idx = tid; idx < 12 * CO1; idx += 128) {
        int i = idx / CO1, f = idx - i * CO1;
        float acc = b1[f];
        for (int k = 0; k < CI1; k++) acc += x0[i * CI1 + k] * W1[k * CO1 + f];
        feat[idx] = acc;
    }
    __syncthreads();
    for (int idx = tid; idx < 176; idx += 128) {
        int e = idx >> 2, h = idx & 3;
        const float* ah = a1 + h * 2 * CS1;
        float s = 0.f;
        for (int c = 0; c < CS1; c++)
            s += ah[c] * feat[c_EI[e] * CO1 + h * CS1 + c] +
                 ah[CS1 + c] * feat[c_EJ[e] * CO1 + h * CS1 + c];
        lg[idx] = s > 0.f ? s : 0.2f * s;
    }
    __syncthreads();
    for (int idx = tid; idx < 48; idx += 128) {
        int i = idx >> 2, h = idx & 3;
        int s0 = c_RS[i], s1 = c_RS[i + 1];
        float m = -3.4e38f;
        for (int e = s0; e < s1; e++) m = fmaxf(m, lg[e * 4 + h]);
        float sum = 0.f;
        for (int e = s0; e < s1; e++) sum += expf(lg[e * 4 + h] - m);
        float* pr = probs1 + (i * 4 + h) * 12;
        for (int j = 0; j < 12; j++) pr[j] = 0.f;
        for (int e = s0; e < s1; e++) pr[c_EJ[e]] = expf(lg[e * 4 + h] - m) / sum;
    }
    __syncthreads();
    for (int idx = tid; idx < 12 * CO1; idx += 128) {
        int i = idx / CO1, f = idx - i * CO1;
        int h = f / CS1;
        const float* pr = probs1 + (i * 4 + h) * 12;
        float acc = 0.f;
        for (int j = 0; j < 12; j++) acc += pr[j] * feat[j * CO1 + f];
        h1s[idx] = acc > 0.f ? acc : expm1f(acc);
    }
    __syncthreads();
    for (int idx = tid; idx < 12 * CO2; idx += 128) {
        int i = idx / CO2, f = idx - i * CO2;
        float acc = b2[f];
        for (int k = 0; k < CI2; k++) acc += h1s[i * CI2 + k] * W2[k * CO2 + f];
        feat2[idx] = acc;
    }
    __syncthreads();
    for (int idx = tid; idx < 176; idx += 128) {
        int e = idx >> 2, h = idx & 3;
        const float* ah = a2 + h * 2 * CS2;
        float s = 0.f;
        for (int c = 0; c < CS2; c++)
            s += ah[c] * feat2[c_EI[e] * CO2 + h * CS2 + c] +
                 ah[CS2 + c] * feat2[c_EJ[e] * CO2 + h * CS2 + c];
        lg[idx] = s > 0.f ? s : 0.2f * s;
    }
    __syncthreads();
    for (int idx = tid; idx < 48; idx += 128) {
        int i = idx >> 2, h = idx & 3;
        int s0 = c_RS[i], s1 = c_RS[i + 1];
        float m = -3.4e38f;
        for (int e = s0; e < s1; e++) m = fmaxf(m, lg[e * 4 + h]);
        float sum = 0.f;
        for (int e = s0; e < s1; e++) sum += expf(lg[e * 4 + h] - m);
        float* pr = probs2 + (i * 4 + h) * 12;
        for (int j = 0; j < 12; j++) pr[j] = 0.f;
        for (int e = s0; e < s1; e++) pr[c_EJ[e]] = expf(lg[e * 4 + h] - m) / sum;
    }
}

// ---------------------------------------------------------------------------
// Fused PAIR of GAT layers; 16 samples per block, thread per (sample,node).
// x-row / h1 / accumulators in registers; W smem; probs transposed [i][j][h].
// ---------------------------------------------------------------------------
template <int CI1, int CO1, int CO2, bool HALFIN>
__global__ __launch_bounds__(192) void gat_pair(const void* in,
                                                const float* W1f, const float* b1f,
                                                const float* W2f, const float* b2f,
                                                const float* p1g, const float* p2g,
                                                __half* out) {
    constexpr int CS1 = CO1 / 4, CS2 = CO2 / 4;
    constexpr int CMX = (CO1 > CO2) ? CO1 : CO2;
    __shared__ float W1s[CI1 * CO1];
    __shared__ float W2s[CO1 * CO2];
    __shared__ float b1s[CO1], b2s[CO2];
    __shared__ float pT1[576], pT2[576];     // [i][j][h]
    __shared__ float fS[16 * 12 * CMX];
    int tid = threadIdx.x;
    for (int i = tid; i < CI1 * CO1; i += 192) W1s[i] = W1f[i];
    for (int i = tid; i < CO1 * CO2; i += 192) W2s[i] = W2f[i];
    for (int i = tid; i < CO1; i += 192) b1s[i] = b1f[i];
    for (int i = tid; i < CO2; i += 192) b2s[i] = b2f[i];
    for (int e = tid; e < 576; e += 192) {
        // e = (i*4+h)*12 + j  ->  [(i*12+j)*4 + h]
        int j = e % 12, ih = e / 12;
        int i = ih >> 2, h = ih & 3;
        pT1[(i * 12 + j) * 4 + h] = p1g[e];
        pT2[(i * 12 + j) * 4 + h] = p2g[e];
    }
    __syncthreads();

    const int s = tid / 12, nd = tid - s * 12;
    const size_t samp = (size_t)blockIdx.x * 16 + s;

    // ---- phase 1: feat1 = x @ W1 + b1 ----
    float xr[CI1];
    if (HALFIN) {
        const __half* xp = (const __half*)in + (samp * 12 + nd) * CI1;
#pragma unroll
        for (int k = 0; k < CI1; k++) xr[k] = __half2float(xp[k]);
    } else {
        const float* xp = (const float*)in + (samp * 12 + nd) * CI1;
#pragma unroll
        for (int k = 0; k < CI1; k++) xr[k] = xp[k];
    }
    float acc[CO1];
#pragma unroll
    for (int f = 0; f < CO1; f++) acc[f] = b1s[f];
#pragma unroll
    for (int k = 0; k < CI1; k++) {
        float xk = xr[k];
#pragma unroll
        for (int f = 0; f < CO1; f++) acc[f] += xk * W1s[k * CO1 + f];
    }
    {
        float* dst = &fS[(s * 12 + nd) * CO1];
#pragma unroll
        for (int f = 0; f < CO1; f++) dst[f] = acc[f];
    }
    __syncthreads();

    // ---- agg1 + ELU -> h1 (registers) ----
    float h1[CO1];
#pragma unroll
    for (int f = 0; f < CO1; f++) h1[f] = 0.f;
#pragma unroll
    for (int j = 0; j < 12; j++) {
        float4 pv = *(const float4*)&pT1[(nd * 12 + j) * 4];
        const float* fb = &fS[(s * 12 + j) * CO1];
#pragma unroll
        for (int f = 0; f < CO1; f++) h1[f] += ((&pv.x)[f / CS1]) * fb[f];
    }
#pragma unroll
    for (int f = 0; f < CO1; f++) h1[f] = felu(h1[f]);
    __syncthreads();   // before overwriting fS

    // ---- phase 2: feat2 = h1 @ W2 + b2 ----
    float acc2[CO2];
#pragma unroll
    for (int f = 0; f < CO2; f++) acc2[f] = b2s[f];
#pragma unroll
    for (int k = 0; k < CO1; k++) {
        float hk = h1[k];
#pragma unroll
        for (int f = 0; f < CO2; f++) acc2[f] += hk * W2s[k * CO2 + f];
    }
    {
        float* dst = &fS[(s * 12 + nd) * CO2];
#pragma unroll
        for (int f = 0; f < CO2; f++) dst[f] = acc2[f];
    }
    __syncthreads();

    // ---- agg2 + ELU -> out (fp16) ----
    float o[CO2];
#pragma unroll
    for (int f = 0; f < CO2; f++) o[f] = 0.f;
#pragma unroll
    for (int j = 0; j < 12; j++) {
        float4 pv = *(const float4*)&pT2[(nd * 12 + j) * 4];
        const float* fb = &fS[(s * 12 + j) * CO2];
#pragma unroll
        for (int f = 0; f < CO2; f++) o[f] += ((&pv.x)[f / CS2]) * fb[f];
    }
    __half* op = out + (samp * 12 + nd) * CO2;
#pragma unroll
    for (int f = 0; f < CO2; f++) op[f] = __float2half(felu(o[f]));
}

// ---------------------------------------------------------------------------
// fp16 MMA GEMM with ldmatrix: C[256x64 tile] = A[M,K] @ B[N,K]^T
//  EPI 0: store fp16, row stride 576 (Xpre)
//  EPI 1: FC: +bias, leaky, (x-v)^2 partial sums
// 256 threads = 8 warps (4M x 2N), warp tile 64x32.
// ---------------------------------------------------------------------------
template <int K, int EPI>
__global__ __launch_bounds__(256) void gemm_h(
    const __half* __restrict__ A, int lda, const __half* __restrict__ Bw, int ldb,
    __half* __restrict__ C, const float* __restrict__ bias,
    const float* __restrict__ x, float* __restrict__ part) {
    __shared__ __half As[256][56];
    __shared__ __half Bs[64][56];
    int tid = threadIdx.x;
    int w = tid >> 5, lane = tid & 31;
    int warpM = w >> 1, warpN = w & 1;
    int grp = lane >> 2, tig = lane & 3;

    float acc[4][4][4];
#pragma unroll
    for (int mt = 0; mt < 4; mt++)
#pragma unroll
        for (int nt = 0; nt < 4; nt++)
#pragma unroll
            for (int i = 0; i < 4; i++) acc[mt][nt][i] = 0.f;

    const size_t mBase = (size_t)blockIdx.y * 256;
    const int nBase = blockIdx.x * 64;

    const int aRow = warpM * 64 + (lane & 15);
    const int aCol = (lane >> 4) * 8;
    const int bRow = warpN * 32 + (lane & 7) + ((lane >> 4) & 1) * 8;
    const int bCol = ((lane >> 3) & 1) * 8;

    for (int k0 = 0; k0 < K; k0 += 48) {
#pragma unroll
        for (int i = 0; i < 6; i++) {
            int q = tid + i * 256;
            int row = q / 6, off = (q - row * 6) * 8;
            *(uint4*)&As[row][off] = *(const uint4*)(A + (mBase + row) * lda + k0 + off);
        }
#pragma unroll
        for (int i = 0; i < 2; i++) {
            int q = tid + i * 256;
            if (q < 384) {
                int n = q / 6, off = (q - n * 6) * 8;
                *(uint4*)&Bs[n][off] = *(const uint4*)(Bw + (size_t)(nBase + n) * ldb + k0 + off);
            }
        }
        __syncthreads();
#pragma unroll
        for (int kc = 0; kc < 3; kc++) {
            uint32_t a[4][4], b[2][4];
#pragma unroll
            for (int mt = 0; mt < 4; mt++)
                ldm_x4(a[mt][0], a[mt][1], a[mt][2], a[mt][3],
                       &As[aRow + mt * 16][kc * 16 + aCol]);
#pragma unroll
            for (int np = 0; np < 2; np++)
                ldm_x4(b[np][0], b[np][1], b[np][2], b[np][3],
                       &Bs[bRow + np * 16][kc * 16 + bCol]);
#pragma unroll
            for (int mt = 0; mt < 4; mt++)
#pragma unroll
                for (int np = 0; np < 2; np++) {
                    MMA16(acc[mt][2*np][0], acc[mt][2*np][1], acc[mt][2*np][2], acc[mt][2*np][3],
                          a[mt][0], a[mt][1], a[mt][2], a[mt][3], b[np][0], b[np][1]);
                    MMA16(acc[mt][2*np+1][0], acc[mt][2*np+1][1], acc[mt][2*np+1][2], acc[mt][2*np+1][3],
                          a[mt][0], a[mt][1], a[mt][2], a[mt][3], b[np][2], b[np][3]);
                }
        }
        __syncthreads();
    }

    if (EPI == 0) {
#pragma unroll
        for (int mt = 0; mt < 4; mt++)
#pragma unroll
            for (int nt = 0; nt < 4; nt++) {
                float* a = acc[mt][nt];
                int colg = nBase + warpN * 32 + nt * 8 + 2 * tig;
                size_t row0 = mBase + warpM * 64 + mt * 16 + grp;
                *(__half2*)(C + row0 * 576 + colg) = __floats2half2_rn(a[0], a[1]);
                *(__half2*)(C + (row0 + 8) * 576 + colg) = __floats2half2_rn(a[2], a[3]);
            }
    } else {
        float s[4][2];
#pragma unroll
        for (int mt = 0; mt < 4; mt++) { s[mt][0] = 0.f; s[mt][1] = 0.f; }
#pragma unroll
        for (int mt = 0; mt < 4; mt++)
#pragma unroll
            for (int nt = 0; nt < 4; nt++) {
                int colg = nBase + warpN * 32 + nt * 8 + 2 * tig;
                if (colg >= 264) continue;
                float* a = acc[mt][nt];
                size_t row0 = mBase + warpM * 64 + mt * 16 + grp;
                float bx = bias[colg], by = bias[colg + 1];
                float v0 = a[0] + bx, v1 = a[1] + by, v2 = a[2] + bx, v3 = a[3] + by;
                v0 = v0 >= 0.f ? v0 : 0.01f * v0;
                v1 = v1 >= 0.f ? v1 : 0.01f * v1;
                v2 = v2 >= 0.f ? v2 : 0.01f * v2;
                v3 = v3 >= 0.f ? v3 : 0.01f * v3;
                float2 xa = *(const float2*)(x + row0 * 264 + colg);
                float2 xb = *(const float2*)(x + (row0 + 8) * 264 + colg);
                float d0 = xa.x - v0, d1 = xa.y - v1, d2 = xb.x - v2, d3 = xb.y - v3;
                s[mt][0] += d0 * d0 + d1 * d1;
                s[mt][1] += d2 * d2 + d3 * d3;
            }
        int slice = blockIdx.x * 2 + warpN;
#pragma unroll
        for (int mt = 0; mt < 4; mt++) {
            size_t row0 = mBase + warpM * 64 + mt * 16 + grp;
            float v0 = s[mt][0], v1 = s[mt][1];
            v0 += __shfl_xor_sync(0xffffffffu, v0, 1);
            v0 += __shfl_xor_sync(0xffffffffu, v0, 2);
            v1 += __shfl_xor_sync(0xffffffffu, v1, 1);
            v1 += __shfl_xor_sync(0xffffffffu, v1, 2);
            if (tig == 0) {
                part[(size_t)slice * NB + row0] = v0;
                part[(size_t)slice * NB + row0 + 8] = v1;
            }
        }
    }
}

__global__ void mse_final(const float* __restrict__ part, float* __restrict__ out) {
    int idx = blockIdx.x * 256 + threadIdx.x;
    if (idx >= NB) return;
    float s = 0.f;
#pragma unroll
    for (int k = 0; k < 10; k++) s += part[(size_t)k * NB + idx];
    out[idx] = s * (1.f / 264.f);
}

// ---------------------------------------------------------------------------
// Persistent LSTM chain: 24 steps per launch. 128 blocks x 256 threads.
// ldmatrix fragment loads; balanced epilogue (even lane row0, odd row0+8).
// ---------------------------------------------------------------------------
#define CHAIN_SMEM (576 * WPAD * 2 + 2 * 32 * WPAD * 2 + 32 * 144 * 4 + 576 * 4)

__global__ __launch_bounds__(256, 1) void lstm_chain(
    const __half* __restrict__ W16, const float* __restrict__ bias,
    const __half* __restrict__ xpre, const __half* __restrict__ hInit,
    __half* __restrict__ y, size_t yStride) {
    extern __shared__ __align__(16) unsigned char smem_raw[];
    __half* Ws  = (__half*)smem_raw;                   // [576][WPAD]
    __half* h0s = Ws + 576 * WPAD;                     // [32][WPAD]
    __half* h1s = h0s + 32 * WPAD;
    float*  cs  = (float*)(h1s + 32 * WPAD);           // [32][144]
    float*  bs  = cs + 32 * 144;                       // [576]

    const int tid = threadIdx.x;
    const int w = tid >> 5, lane = tid & 31;
    const int warpM = w >> 2, warpN = w & 3;           // 2 x 4 warps
    const int grp = lane >> 2, tig = lane & 3;
    const size_t gRowBase = (size_t)blockIdx.x * 32;

    {
        const uint4* src = (const uint4*)W16;
        uint4* dst = (uint4*)Ws;
        for (int i = tid; i < 576 * WPAD / 8; i += 256) dst[i] = src[i];
    }
    for (int i = tid; i < 32 * WPAD; i += 256) { h0s[i] = __half(0.f); h1s[i] = __half(0.f); }
    for (int i = tid; i < 32 * 144; i += 256) cs[i] = 0.f;
    for (int i = tid; i < 576; i += 256) bs[i] = bias[i];
    __syncthreads();
    if (hInit) {
        for (int i = tid; i < 32 * 144; i += 256) {
            int r = i / 144, j = i - r * 144;
            h0s[r * WPAD + j] = hInit[(gRowBase + r) * 144 + j];
        }
        __syncthreads();
    }

    const int row0 = warpM * 16 + grp;
    const int aRow = warpM * 16 + (lane & 15);
    const int aCol = (lane >> 4) * 8;
    const int bRowBase = warpN * 144 + (lane & 7) + ((lane >> 4) & 1) * 8;
    const int bCol = ((lane >> 3) & 1) * 8;
    const int myRow = (tig & 1) ? row0 + 8 : row0;     // balanced epilogue row

    int p = 0;
    for (int t = 0; t < PERIOD; t++) {
        const __half* hc = p ? h1s : h0s;
        __half* hn = p ? h0s : h1s;
        const __half* xslice = xpre ? (xpre + (size_t)t * BB * 576) : nullptr;
        __half* yslice = y + (size_t)t * yStride;

        uint32_t Areg[9][4];
#pragma unroll
        for (int kc = 0; kc < 9; kc++)
            ldm_x4(Areg[kc][0], Areg[kc][1], Areg[kc][2], Areg[kc][3],
                   hc + aRow * WPAD + kc * 16 + aCol);

#pragma unroll
        for (int np = 0; np < 9; np++) {
            float d[2][4];
#pragma unroll
            for (int u = 0; u < 2; u++)
#pragma unroll
                for (int i = 0; i < 4; i++) d[u][i] = 0.f;
            const __half* wb = Ws + (bRowBase + np * 16) * WPAD + bCol;
#pragma unroll
            for (int kc = 0; kc < 9; kc++) {
                uint32_t b0, b1, b2, b3;
                ldm_x4(b0, b1, b2, b3, wb + kc * 16);
                MMA16(d[0][0], d[0][1], d[0][2], d[0][3],
                      Areg[kc][0], Areg[kc][1], Areg[kc][2], Areg[kc][3], b0, b1);
                MMA16(d[1][0], d[1][1], d[1][2], d[1][3],
                      Areg[kc][0], Areg[kc][1], Areg[kc][2], Areg[kc][3], b2, b3);
            }
#pragma unroll
            for (int u = 0; u < 2; u++) {
                int colg = warpN * 144 + (2 * np + u) * 8 + 2 * tig;
                float v0 = d[u][0] + bs[colg], v1 = d[u][1] + bs[colg + 1];
                float v2 = d[u][2] + bs[colg], v3 = d[u][3] + bs[colg + 1];
                if (xslice) {
                    __half2 x0 = *(const __half2*)(xslice + (gRowBase + row0) * 576 + colg);
                    __half2 x1 = *(const __half2*)(xslice + (gRowBase + row0 + 8) * 576 + colg);
                    v0 += __half2float(x0.x); v1 += __half2float(x0.y);
                    v2 += __half2float(x1.x); v3 += __half2float(x1.y);
                }
                float t0 = __shfl_xor_sync(0xffffffffu, v0, 1);
                float t1 = __shfl_xor_sync(0xffffffffu, v1, 1);
                float t2 = __shfl_xor_sync(0xffffffffu, v2, 1);
                float t3 = __shfl_xor_sync(0xffffffffu, v3, 1);
                // even lane: (i,f)=(v0,v1), (g,o)=(t0,t1), row = row0
                // odd  lane: (i,f)=(t2,t3), (g,o)=(v2,v3), row = row0+8
                float gi = (tig & 1) ? t2 : v0;
                float gf = (tig & 1) ? t3 : v1;
                float gg = (tig & 1) ? v2 : t0;
                float go = (tig & 1) ? v3 : t1;
                int j = colg >> 2;
                float c = cs[myRow * 144 + j];
                float c2 = sigm(gf) * c + sigm(gi) * ftanh(gg);
                float h2 = sigm(go) * ftanh(c2);
                cs[myRow * 144 + j] = c2;
                __half hh = __float2half(h2);
                hn[myRow * WPAD + j] = hh;
                yslice[(gRowBase + myRow) * 144 + j] = hh;
            }
        }
        __syncthreads();
        p ^= 1;
    }
}

// ---------------------------------------------------------------------------
// Host orchestration
// ---------------------------------------------------------------------------
extern "C" void kernel_launch(void* const* d_in, const int* in_sizes, int n_in,
                              void* d_out, int out_size) {
    const float* x     = (const float*)d_in[0];
    const float* gW0   = (const float*)d_in[1];
    const float* gb0   = (const float*)d_in[2];
    const float* ga0   = (const float*)d_in[3];
    const float* gW1   = (const float*)d_in[4];
    const float* gb1   = (const float*)d_in[5];
    const float* ga1   = (const float*)d_in[6];
    const float* eWih0 = (const float*)d_in[7];
    const float* eWhh0 = (const float*)d_in[8];
    const float* ebih0 = (const float*)d_in[9];
    const float* ebhh0 = (const float*)d_in[10];
    const float* eWih1 = (const float*)d_in[11];
    const float* eWhh1 = (const float*)d_in[12];
    const float* ebih1 = (const float*)d_in[13];
    const float* ebhh1 = (const float*)d_in[14];
    const float* dWhh0 = (const float*)d_in[16];
    const float* dbih0 = (const float*)d_in[17];
    const float* dbhh0 = (const float*)d_in[18];
    const float* dWih1 = (const float*)d_in[19];
    const float* dWhh1 = (const float*)d_in[20];
    const float* dbih1 = (const float*)d_in[21];
    const float* dbhh1 = (const float*)d_in[22];
    const float* gW3   = (const float*)d_in[23];
    const float* gb3   = (const float*)d_in[24];
    const float* ga3   = (const float*)d_in[25];
    const float* gW4   = (const float*)d_in[26];
    const float* gb4   = (const float*)d_in[27];
    const float* ga4   = (const float*)d_in[28];
    const float* fW    = (const float*)d_in[29];
    const float* fb    = (const float*)d_in[30];

    float* S = nullptr;
    cudaGetSymbolAddress((void**)&S, g_scratch);

    __half* h2_16   = (__half*)(S + OFF_H2);
    __half* Xpre16  = (__half*)(S + OFF_XPRE);
    __half* y0_16   = (__half*)(S + OFF_Y0);
    __half* yd0_16  = (__half*)(S + OFF_YD0);
    __half* yd1_16  = (__half*)(S + OFF_YD1);
    __half* h4_16   = (__half*)(S + OFF_H4);
    __half* enc1_16 = (__half*)(S + OFF_ENC1);
    float*  part    = S + OFF_PART;
    float*  probs   = S + OFF_PROBS;
    __half* w16     = (__half*)(S + OFF_W16);
    float*  br      = S + OFF_BR;
    __half* fw16    = (__half*)(S + OFF_FW16);

    const size_t WSLICE = (size_t)576 * WPAD;
    __half* w_eWih0 = w16 + 0 * WSLICE;
    __half* w_eWhh0 = w16 + 1 * WSLICE;
    __half* w_eWih1 = w16 + 2 * WSLICE;
    __half* w_eWhh1 = w16 + 3 * WSLICE;
    __half* w_dWhh0 = w16 + 4 * WSLICE;
    __half* w_dWih1 = w16 + 5 * WSLICE;
    __half* w_dWhh1 = w16 + 6 * WSLICE;

    cudaFuncSetAttribute(lstm_chain, cudaFuncAttributeMaxDynamicSharedMemorySize,
                         CHAIN_SMEM);

    PrepArgs pa;
    pa.wsrc[0] = eWih0; pa.wsrc[1] = eWhh0; pa.wsrc[2] = eWih1; pa.wsrc[3] = eWhh1;
    pa.wsrc[4] = dWhh0; pa.wsrc[5] = dWih1; pa.wsrc[6] = dWhh1;
    pa.bih[0] = ebih0; pa.bih[1] = ebih1; pa.bih[2] = dbih0; pa.bih[3] = dbih1;
    pa.bhh[0] = ebhh0; pa.bhh[1] = ebhh1; pa.bhh[2] = dbhh0; pa.bhh[3] = dbhh1;
    pa.fW = fW;
    prep_all<<<(PREP_TOT + 255) / 256, 256>>>(pa, w16, br, fw16);

    // ---- GAT 1+2 ----
    attn_pair<22, 16, 16, 12, false><<<1, 128>>>(x, gW0, gb0, ga0, gW1, gb1, ga1,
                                                 probs, probs + 576);
    gat_pair<22, 16, 12, false><<<NB / 16, 192>>>(x, gW0, gb0, gW1, gb1,
                                                  probs, probs + 576, h2_16);

    dim3 gPre(9, NB / 256);

    // ---- Encoder layer 0 ----
    gemm_h<144, 0><<<gPre, 256>>>(h2_16, 144, w_eWih0, WPAD, Xpre16, nullptr,
                                  nullptr, nullptr);
    lstm_chain<<<BB / 32, 256, CHAIN_SMEM>>>(w_eWhh0, br + 0, Xpre16, nullptr,
                                             y0_16, (size_t)BB * 144);
    // ---- Encoder layer 1 ----
    gemm_h<144, 0><<<gPre, 256>>>(y0_16, 144, w_eWih1, WPAD, Xpre16, nullptr,
                                  nullptr, nullptr);
    lstm_chain<<<BB / 32, 256, CHAIN_SMEM>>>(w_eWhh1, br + 576, Xpre16, nullptr,
                                             enc1_16, 0);
    // ---- Decoder layer 0 (zero inputs; h0 = enc0 final = y0[t=23]) ----
    lstm_chain<<<BB / 32, 256, CHAIN_SMEM>>>(w_dWhh0, br + 1152, nullptr,
                                             y0_16 + (size_t)23 * BB * 144,
                                             yd0_16, (size_t)BB * 144);
    // ---- Decoder layer 1 (h0 = enc1 final) ----
    gemm_h<144, 0><<<gPre, 256>>>(yd0_16, 144, w_dWih1, WPAD, Xpre16, nullptr,
                                  nullptr, nullptr);
    lstm_chain<<<BB / 32, 256, CHAIN_SMEM>>>(w_dWhh1, br + 1728, Xpre16, enc1_16,
                                             yd1_16, (size_t)BB * 144);

    // ---- GAT 3+4 ----
    attn_pair<12, 16, 16, 24, true><<<1, 128>>>(yd1_16, gW3, gb3, ga3, gW4, gb4, ga4,
                                                probs + 1152, probs + 1728);
    gat_pair<12, 16, 24, true><<<NB / 16, 192>>>(yd1_16, gW3, gb3, gW4, gb4,
                                                 probs + 1152, probs + 1728, h4_16);

    // ---- FC + leaky + MSE ----
    gemm_h<288, 1><<<dim3(5, NB / 256), 256>>>(h4_16, 288, fw16, 288, nullptr, fb,
                                               x, part);
    mse_final<<<(NB + 255) / 256, 256>>>(part, (float*)d_out);
}

// round 10
// speedup vs baseline: 2.6030x; 1.0239x over previous
#include <cuda_runtime.h>
#include <cuda_fp16.h>
#include <cstdint>
#include <cstddef>

// ---------------------------------------------------------------------------
// Problem constants
// ---------------------------------------------------------------------------
#define NB      98304
#define PERIOD  24
#define BB      (NB / PERIOD)     // 4096
#define WPAD    152               // padded K stride (halves) for LSTM weights

__constant__ int c_EI[44] = {0,0,0,0, 1,1,1, 2,2,2, 3,3, 4,4, 5,5,5, 6,6,6,6,
                             7,7,7, 8,8,8,8, 9,9,9,9, 10,10,10,10,10,10,10,
                             11,11,11,11,11};
__constant__ int c_EJ[44] = {0,5,10,11, 1,7,10, 2,6,11, 3,6, 4,5, 0,4,5,
                             2,3,6,10, 1,7,9, 8,9,10,11, 7,8,9,10,
                             0,1,6,8,9,10,11, 0,2,8,10,11};
__constant__ int c_RS[13] = {0,4,7,10,12,14,17,21,24,28,32,39,44};

// ---------------------------------------------------------------------------
// Scratch layout (float units)
// ---------------------------------------------------------------------------
#define OFF_X16   ((size_t)0)                        // fp16 [NB][288]
#define OFF_OUT1  (OFF_X16  + (size_t)NB * 144)      // fp16 [NB][192]
#define OFF_H2    (OFF_OUT1 + (size_t)NB * 96)       // fp16 [NB][144]
#define OFF_XPRE  (OFF_H2   + (size_t)NB * 72)       // fp16 [24][BB][576]
#define OFF_Y0    (OFF_XPRE + (size_t)NB * 288)      // fp16 [24][BB][144]
#define OFF_YD0   (OFF_Y0   + (size_t)NB * 72)
#define OFF_YD1   (OFF_YD0  + (size_t)NB * 72)
#define OFF_O3    (OFF_YD1  + (size_t)NB * 72)       // fp16 [NB][192]
#define OFF_H4    (OFF_O3   + (size_t)NB * 96)       // fp16 [NB][288]
#define OFF_ENC1  (OFF_H4   + (size_t)NB * 144)      // fp16 [BB][144]
#define OFF_PART  (OFF_ENC1 + (size_t)BB * 72)       // fp32 [5][NB]
#define OFF_PROBS (OFF_PART + (size_t)5 * NB)        // fp32 4*576
#define OFF_M     (OFF_PROBS + 2304)                 // fp16 M1..M4
#define SZ_M      ((192*288 + 192*192 + 192*144 + 320*192) / 2)
#define OFF_W16   (OFF_M + SZ_M)
#define OFF_BR    (OFF_W16 + (size_t)7 * 576 * WPAD / 2)
#define OFF_FW16  (OFF_BR + 4 * 576)
#define SCRATCH_TOTAL (OFF_FW16 + (size_t)320 * 288 / 2)

__device__ __align__(128) float g_scratch[SCRATCH_TOTAL];

__device__ __forceinline__ float sigm(float x) { return 1.f / (1.f + __expf(-x)); }
__device__ __forceinline__ float ftanh(float x) { return 2.f / (1.f + __expf(-2.f * x)) - 1.f; }
__device__ __forceinline__ float felu(float x) { return x > 0.f ? x : (__expf(x) - 1.f); }

__device__ __forceinline__ uint32_t smem_u32(const void* p) {
    return (uint32_t)__cvta_generic_to_shared(p);
}
__device__ __forceinline__ void ldm_x4(uint32_t& r0, uint32_t& r1, uint32_t& r2,
                                       uint32_t& r3, const void* p) {
    asm volatile("ldmatrix.sync.aligned.m8n8.x4.shared.b16 {%0,%1,%2,%3}, [%4];"
                 : "=r"(r0), "=r"(r1), "=r"(r2), "=r"(r3) : "r"(smem_u32(p)));
}
__device__ __forceinline__ void cp16(void* dst, const void* src) {
    asm volatile("cp.async.cg.shared.global [%0], [%1], 16;"
                 :: "r"(smem_u32(dst)), "l"(src));
}
__device__ __forceinline__ void cp_commit_wait() {
    asm volatile("cp.async.commit_group;");
    asm volatile("cp.async.wait_group 0;");
}
#define MMA16(d0,d1,d2,d3,a0,a1,a2,a3,b0,b1)                                    \
    asm volatile("mma.sync.aligned.m16n8k16.row.col.f32.f16.f16.f32 "           \
                 "{%0,%1,%2,%3}, {%4,%5,%6,%7}, {%8,%9}, {%0,%1,%2,%3};"        \
                 : "+f"(d0), "+f"(d1), "+f"(d2), "+f"(d3)                       \
                 : "r"(a0), "r"(a1), "r"(a2), "r"(a3), "r"(b0), "r"(b1))

// ---------------------------------------------------------------------------
// Prep kernels
// ---------------------------------------------------------------------------
struct PrepArgs {
    const float* wsrc[7];
    const float* bih[4];
    const float* bhh[4];
    const float* fW;
};
#define PREP_W  (7 * 576 * WPAD)
#define PREP_B  (4 * 576)
#define PREP_F  (320 * 288)
#define PREP_TOT (PREP_W + PREP_B + PREP_F)

__global__ void prep_all(PrepArgs args, __half* w16, float* br, __half* fw16) {
    for (size_t idx = blockIdx.x * 256 + threadIdx.x; idx < PREP_TOT;
         idx += (size_t)gridDim.x * 256) {
        if (idx < PREP_W) {
            size_t m = idx / (576 * WPAD);
            int r = (int)(idx - m * (576 * WPAD));
            int np = r / WPAD, k = r - np * WPAD;
            int j = np >> 2, g = np & 3;
            w16[idx] = (k < 144)
                ? __float2half(args.wsrc[m][(g * 144 + j) * 144 + k]) : __half(0.f);
        } else if (idx < PREP_W + PREP_B) {
            int e = (int)(idx - PREP_W);
            int b = e / 576, np = e - b * 576;
            int j = np >> 2, g = np & 3;
            br[e] = args.bih[b][g * 144 + j] + args.bhh[b][g * 144 + j];
        } else {
            int e = (int)(idx - PREP_W - PREP_B);
            int n = e / 288, k = e - n * 288;
            fw16[e] = (n < 264) ? __float2half(args.fW[k * 264 + n]) : __half(0.f);
        }
    }
}

// x fp32 [NB,12,22] -> x16 fp16 [NB, 12*24] zero-padded
__global__ void convert_x(const float* __restrict__ x, __half* __restrict__ x16) {
    size_t idx = (size_t)blockIdx.x * 256 + threadIdx.x;
    if (idx >= (size_t)NB * 288) return;
    size_t b = idx / 288;
    int r = (int)(idx - b * 288);
    int j = r / 24, k = r - j * 24;
    x16[idx] = (k < 22) ? __float2half(x[b * 264 + j * 22 + k]) : __half(0.f);
}

// Build combined GAT matrix: M^T[n=(i,f)][kk=(j,k)] = P[i,j,h(f)] * W[k,f]
__global__ void build_M(const float* __restrict__ P, const float* __restrict__ W,
                        __half* __restrict__ M, int Nrows, int K,
                        int FPNP, int FV, int KP, int KV) {
    int idx = blockIdx.x * 256 + threadIdx.x;
    if (idx >= Nrows * K) return;
    int n = idx / K, kk = idx - n * K;
    int i = n / FPNP, f = n - i * FPNP;
    int j = kk / KP, k = kk - j * KP;
    float v = 0.f;
    if (f < FV && k < KV && i < 12) {
        int cs = FV >> 2;
        int h = f / cs;
        v = P[(i * 4 + h) * 12 + j] * W[k * FV + f];
    }
    M[idx] = __float2half(v);
}

// ---------------------------------------------------------------------------
// Attention probs for a PAIR of GAT layers (sample 0 only)
// ---------------------------------------------------------------------------
template <int CI1, int CO1, int CI2, int CO2, bool HALFIN>
__global__ void attn_pair(const void* xin,
                          const float* W1, const float* b1, const float* a1,
                          const float* W2, const float* b2, const float* a2,
                          float* probs1, float* probs2) {
    constexpr int CS1 = CO1 / 4, CS2 = CO2 / 4;
    __shared__ float x0[12 * CI1];
    __shared__ float feat[12 * CO1];
    __shared__ float lg[44 * 4];
    __shared__ float h1s[12 * CI2];
    __shared__ float feat2[12 * CO2];
    int tid = threadIdx.x;

    for (int i = tid; i < 12 * CI1; i += 128)
        x0[i] = HALFIN ? __half2float(((const __half*)xin)[i]) : ((const float*)xin)[i];
    __syncthreads();
    for (int idx = tid; idx < 12 * CO1; idx += 128) {
        int i = idx / CO1, f = idx - i * CO1;
        float acc = b1[f];
        for (int k = 0; k < CI1; k++) acc += x0[i * CI1 + k] * W1[k * CO1 + f];
        feat[idx] = acc;
    }
    __syncthreads();
    for (int idx = tid; idx < 176; idx += 128) {
        int e = idx >> 2, h = idx & 3;
        const float* ah = a1 + h * 2 * CS1;
        float s = 0.f;
        for (int c = 0; c < CS1; c++)
            s += ah[c] * feat[c_EI[e] * CO1 + h * CS1 + c] +
                 ah[CS1 + c] * feat[c_EJ[e] * CO1 + h * CS1 + c];
        lg[idx] = s > 0.f ? s : 0.2f * s;
    }
    __syncthreads();
    for (int idx = tid; idx < 48; idx += 128) {
        int i = idx >> 2, h = idx & 3;
        int s0 = c_RS[i], s1 = c_RS[i + 1];
        float m = -3.4e38f;
        for (int e = s0; e < s1; e++) m = fmaxf(m, lg[e * 4 + h]);
        float sum = 0.f;
        for (int e = s0; e < s1; e++) sum += expf(lg[e * 4 + h] - m);
        float* pr = probs1 + (i * 4 + h) * 12;
        for (int j = 0; j < 12; j++) pr[j] = 0.f;
        for (int e = s0; e < s1; e++) pr[c_EJ[e]] = expf(lg[e * 4 + h] - m) / sum;
    }
    __syncthreads();
    for (int idx = tid; idx < 12 * CO1; idx += 128) {
        int i = idx / CO1, f = idx - i * CO1;
        int h = f / CS1;
        const float* pr = probs1 + (i * 4 + h) * 12;
        float acc = 0.f;
        for (int j = 0; j < 12; j++) acc += pr[j] * feat[j * CO1 + f];
        h1s[idx] = acc > 0.f ? acc : expm1f(acc);
    }
    __syncthreads();
    for (int idx = tid; idx < 12 * CO2; idx += 128) {
        int i = idx / CO2, f = idx - i * CO2;
        float acc = b2[f];
        for (int k = 0; k < CI2; k++) acc += h1s[i * CI2 + k] * W2[k * CO2 + f];
        feat2[idx] = acc;
    }
    __syncthreads();
    for (int idx = tid; idx < 176; idx += 128) {
        int e = idx >> 2, h = idx & 3;
        const float* ah = a2 + h * 2 * CS2;
        float s = 0.f;
        for (int c = 0; c < CS2; c++)
            s += ah[c] * feat2[c_EI[e] * CO2 + h * CS2 + c] +
                 ah[CS2 + c] * feat2[c_EJ[e] * CO2 + h * CS2 + c];
        lg[idx] = s > 0.f ? s : 0.2f * s;
    }
    __syncthreads();
    for (int idx = tid; idx < 48; idx += 128) {
        int i = idx >> 2, h = idx & 3;
        int s0 = c_RS[i], s1 = c_RS[i + 1];
        float m = -3.4e38f;
        for (int e = s0; e < s1; e++) m = fmaxf(m, lg[e * 4 + h]);
        float sum = 0.f;
        for (int e = s0; e < s1; e++) sum += expf(lg[e * 4 + h] - m);
        float* pr = probs2 + (i * 4 + h) * 12;
        for (int j = 0; j < 12; j++) pr[j] = 0.f;
        for (int e = s0; e < s1; e++) pr[c_EJ[e]] = expf(lg[e * 4 + h] - m) / sum;
    }
}

// ---------------------------------------------------------------------------
// Unified fp16 GEMM: tile 256x64, 128 threads = 4 warps, warp tile 64x64.
// A [M,K] row-major, B [N,K] row-major (row = output col). cp.async staging.
//  EPI 0: fp16 store, stride ldc (Xpre)
//  EPI 1: FC: +bias, leaky_relu, (x-v)^2 row partials -> part[blockIdx.x][row]
//  EPI 2: ELU + fp16 store stride ldc, col guard nguard, bias idx colg%fpn
//  EPI 3: GAT2 remap: i=colg>>4, f=colg&15 (<12), store col i*12+f, stride 144
// ---------------------------------------------------------------------------
template <int EPI>
__global__ __launch_bounds__(128, 2) void gemm2(
    const __half* __restrict__ A, int K,
    const __half* __restrict__ Bw, int ldb,
    __half* __restrict__ C, int ldc, int nguard, int fpn,
    const float* __restrict__ bias,
    const float* __restrict__ x, float* __restrict__ part) {
    __shared__ __half As[256][56];
    __shared__ __half Bs[64][56];
    const int tid = threadIdx.x;
    const int w = tid >> 5, lane = tid & 31;
    const int grp = lane >> 2, tig = lane & 3;

    float acc[4][8][4];
#pragma unroll
    for (int mt = 0; mt < 4; mt++)
#pragma unroll
        for (int nt = 0; nt < 8; nt++)
#pragma unroll
            for (int i = 0; i < 4; i++) acc[mt][nt][i] = 0.f;

    const size_t mBase = (size_t)blockIdx.y * 256;
    const int nBase = blockIdx.x * 64;

    const int aRow = w * 64 + (lane & 15);
    const int aCol = (lane >> 4) * 8;
    const int bRow = (lane & 7) + ((lane >> 4) & 1) * 8;
    const int bCol = ((lane >> 3) & 1) * 8;

    for (int k0 = 0; k0 < K; k0 += 48) {
#pragma unroll
        for (int i = 0; i < 12; i++) {
            int q = tid + i * 128;
            int row = q / 6, off = (q - row * 6) * 8;
            cp16(&As[row][off], A + (mBase + row) * K + k0 + off);
        }
#pragma unroll
        for (int i = 0; i < 3; i++) {
            int q = tid + i * 128;
            int n = q / 6, off = (q - n * 6) * 8;
            cp16(&Bs[n][off], Bw + (size_t)(nBase + n) * ldb + k0 + off);
        }
        cp_commit_wait();
        __syncthreads();
#pragma unroll
        for (int kc = 0; kc < 3; kc++) {
            uint32_t a[4][4], b[4][4];
#pragma unroll
            for (int mt = 0; mt < 4; mt++)
                ldm_x4(a[mt][0], a[mt][1], a[mt][2], a[mt][3],
                       &As[aRow + mt * 16][kc * 16 + aCol]);
#pragma unroll
            for (int g = 0; g < 4; g++)
                ldm_x4(b[g][0], b[g][1], b[g][2], b[g][3],
                       &Bs[bRow + g * 16][kc * 16 + bCol]);
#pragma unroll
            for (int mt = 0; mt < 4; mt++)
#pragma unroll
                for (int g = 0; g < 4; g++) {
                    MMA16(acc[mt][2*g][0], acc[mt][2*g][1], acc[mt][2*g][2], acc[mt][2*g][3],
                          a[mt][0], a[mt][1], a[mt][2], a[mt][3], b[g][0], b[g][1]);
                    MMA16(acc[mt][2*g+1][0], acc[mt][2*g+1][1], acc[mt][2*g+1][2], acc[mt][2*g+1][3],
                          a[mt][0], a[mt][1], a[mt][2], a[mt][3], b[g][2], b[g][3]);
                }
        }
        __syncthreads();
    }

    if (EPI == 0) {
#pragma unroll
        for (int mt = 0; mt < 4; mt++)
#pragma unroll
            for (int nt = 0; nt < 8; nt++) {
                float* a = acc[mt][nt];
                int colg = nBase + nt * 8 + 2 * tig;
                size_t row0 = mBase + w * 64 + mt * 16 + grp;
                *(__half2*)(C + row0 * ldc + colg) = __floats2half2_rn(a[0], a[1]);
                *(__half2*)(C + (row0 + 8) * ldc + colg) = __floats2half2_rn(a[2], a[3]);
            }
    } else if (EPI == 2) {
#pragma unroll
        for (int mt = 0; mt < 4; mt++)
#pragma unroll
            for (int nt = 0; nt < 8; nt++) {
                int colg = nBase + nt * 8 + 2 * tig;
                if (colg >= nguard) continue;
                float* a = acc[mt][nt];
                size_t row0 = mBase + w * 64 + mt * 16 + grp;
                int f = colg % fpn;
                float bx = bias[f], by = bias[f + 1];
                *(__half2*)(C + row0 * ldc + colg) =
                    __floats2half2_rn(felu(a[0] + bx), felu(a[1] + by));
                *(__half2*)(C + (row0 + 8) * ldc + colg) =
                    __floats2half2_rn(felu(a[2] + bx), felu(a[3] + by));
            }
    } else if (EPI == 3) {
#pragma unroll
        for (int mt = 0; mt < 4; mt++)
#pragma unroll
            for (int nt = 0; nt < 8; nt++) {
                int colg = nBase + nt * 8 + 2 * tig;
                int f = colg & 15;
                if (f >= 12) continue;
                int i = colg >> 4;
                int oc = i * 12 + f;
                float* a = acc[mt][nt];
                size_t row0 = mBase + w * 64 + mt * 16 + grp;
                float bx = bias[f], by = bias[f + 1];
                *(__half2*)(C + row0 * 144 + oc) =
                    __floats2half2_rn(felu(a[0] + bx), felu(a[1] + by));
                *(__half2*)(C + (row0 + 8) * 144 + oc) =
                    __floats2half2_rn(felu(a[2] + bx), felu(a[3] + by));
            }
    } else {  // EPI 1: FC + MSE partials
        float s[4][2];
#pragma unroll
        for (int mt = 0; mt < 4; mt++) { s[mt][0] = 0.f; s[mt][1] = 0.f; }
#pragma unroll
        for (int mt = 0; mt < 4; mt++)
#pragma unroll
            for (int nt = 0; nt < 8; nt++) {
                int colg = nBase + nt * 8 + 2 * tig;
                if (colg >= 264) continue;
                float* a = acc[mt][nt];
                size_t row0 = mBase + w * 64 + mt * 16 + grp;
                float bx = bias[colg], by = bias[colg + 1];
                float v0 = a[0] + bx, v1 = a[1] + by, v2 = a[2] + bx, v3 = a[3] + by;
                v0 = v0 >= 0.f ? v0 : 0.01f * v0;
                v1 = v1 >= 0.f ? v1 : 0.01f * v1;
                v2 = v2 >= 0.f ? v2 : 0.01f * v2;
                v3 = v3 >= 0.f ? v3 : 0.01f * v3;
                float2 xa = *(const float2*)(x + row0 * 264 + colg);
                float2 xb = *(const float2*)(x + (row0 + 8) * 264 + colg);
                float d0 = xa.x - v0, d1 = xa.y - v1, d2 = xb.x - v2, d3 = xb.y - v3;
                s[mt][0] += d0 * d0 + d1 * d1;
                s[mt][1] += d2 * d2 + d3 * d3;
            }
#pragma unroll
        for (int mt = 0; mt < 4; mt++) {
            size_t row0 = mBase + w * 64 + mt * 16 + grp;
            float v0 = s[mt][0], v1 = s[mt][1];
            v0 += __shfl_xor_sync(0xffffffffu, v0, 1);
            v0 += __shfl_xor_sync(0xffffffffu, v0, 2);
            v1 += __shfl_xor_sync(0xffffffffu, v1, 1);
            v1 += __shfl_xor_sync(0xffffffffu, v1, 2);
            if (tig == 0) {
                part[(size_t)blockIdx.x * NB + row0] = v0;
                part[(size_t)blockIdx.x * NB + row0 + 8] = v1;
            }
        }
    }
}

__global__ void mse_final(const float* __restrict__ part, float* __restrict__ out) {
    int idx = blockIdx.x * 256 + threadIdx.x;
    if (idx >= NB) return;
    float s = 0.f;
#pragma unroll
    for (int k = 0; k < 5; k++) s += part[(size_t)k * NB + idx];
    out[idx] = s * (1.f / 264.f);
}

// ---------------------------------------------------------------------------
// Persistent LSTM chain (unchanged from round 8)
// ---------------------------------------------------------------------------
#define CHAIN_SMEM (576 * WPAD * 2 + 2 * 32 * WPAD * 2 + 32 * 144 * 4 + 576 * 4)

__global__ __launch_bounds__(256, 1) void lstm_chain(
    const __half* __restrict__ W16, const float* __restrict__ bias,
    const __half* __restrict__ xpre, const __half* __restrict__ hInit,
    __half* __restrict__ y, size_t yStride) {
    extern __shared__ __align__(16) unsigned char smem_raw[];
    __half* Ws  = (__half*)smem_raw;
    __half* h0s = Ws + 576 * WPAD;
    __half* h1s = h0s + 32 * WPAD;
    float*  cs  = (float*)(h1s + 32 * WPAD);
    float*  bs  = cs + 32 * 144;

    const int tid = threadIdx.x;
    const int w = tid >> 5, lane = tid & 31;
    const int warpM = w >> 2, warpN = w & 3;
    const int grp = lane >> 2, tig = lane & 3;
    const size_t gRowBase = (size_t)blockIdx.x * 32;

    {
        const uint4* src = (const uint4*)W16;
        uint4* dst = (uint4*)Ws;
        for (int i = tid; i < 576 * WPAD / 8; i += 256) dst[i] = src[i];
    }
    for (int i = tid; i < 32 * WPAD; i += 256) { h0s[i] = __half(0.f); h1s[i] = __half(0.f); }
    for (int i = tid; i < 32 * 144; i += 256) cs[i] = 0.f;
    for (int i = tid; i < 576; i += 256) bs[i] = bias[i];
    __syncthreads();
    if (hInit) {
        for (int i = tid; i < 32 * 144; i += 256) {
            int r = i / 144, j = i - r * 144;
            h0s[r * WPAD + j] = hInit[(gRowBase + r) * 144 + j];
        }
        __syncthreads();
    }

    const int row0 = warpM * 16 + grp;
    const int aRow = warpM * 16 + (lane & 15);
    const int aCol = (lane >> 4) * 8;
    const int bRowBase = warpN * 144 + (lane & 7) + ((lane >> 4) & 1) * 8;
    const int bCol = ((lane >> 3) & 1) * 8;
    const int myRow = (tig & 1) ? row0 + 8 : row0;

    int p = 0;
    for (int t = 0; t < PERIOD; t++) {
        const __half* hc = p ? h1s : h0s;
        __half* hn = p ? h0s : h1s;
        const __half* xslice = xpre ? (xpre + (size_t)t * BB * 576) : nullptr;
        __half* yslice = y + (size_t)t * yStride;

        uint32_t Areg[9][4];
#pragma unroll
        for (int kc = 0; kc < 9; kc++)
            ldm_x4(Areg[kc][0], Areg[kc][1], Areg[kc][2], Areg[kc][3],
                   hc + aRow * WPAD + kc * 16 + aCol);

#pragma unroll
        for (int np = 0; np < 9; np++) {
            float d[2][4];
#pragma unroll
            for (int u = 0; u < 2; u++)
#pragma unroll
                for (int i = 0; i < 4; i++) d[u][i] = 0.f;
            const __half* wb = Ws + (bRowBase + np * 16) * WPAD + bCol;
#pragma unroll
            for (int kc = 0; kc < 9; kc++) {
                uint32_t b0, b1, b2, b3;
                ldm_x4(b0, b1, b2, b3, wb + kc * 16);
                MMA16(d[0][0], d[0][1], d[0][2], d[0][3],
                      Areg[kc][0], Areg[kc][1], Areg[kc][2], Areg[kc][3], b0, b1);
                MMA16(d[1][0], d[1][1], d[1][2], d[1][3],
                      Areg[kc][0], Areg[kc][1], Areg[kc][2], Areg[kc][3], b2, b3);
            }
#pragma unroll
            for (int u = 0; u < 2; u++) {
                int colg = warpN * 144 + (2 * np + u) * 8 + 2 * tig;
                float v0 = d[u][0] + bs[colg], v1 = d[u][1] + bs[colg + 1];
                float v2 = d[u][2] + bs[colg], v3 = d[u][3] + bs[colg + 1];
                if (xslice) {
                    __half2 x0 = *(const __half2*)(xslice + (gRowBase + row0) * 576 + colg);
                    __half2 x1 = *(const __half2*)(xslice + (gRowBase + row0 + 8) * 576 + colg);
                    v0 += __half2float(x0.x); v1 += __half2float(x0.y);
                    v2 += __half2float(x1.x); v3 += __half2float(x1.y);
                }
                float t0 = __shfl_xor_sync(0xffffffffu, v0, 1);
                float t1 = __shfl_xor_sync(0xffffffffu, v1, 1);
                float t2 = __shfl_xor_sync(0xffffffffu, v2, 1);
                float t3 = __shfl_xor_sync(0xffffffffu, v3, 1);
                float gi = (tig & 1) ? t2 : v0;
                float gf = (tig & 1) ? t3 : v1;
                float gg = (tig & 1) ? v2 : t0;
                float go = (tig & 1) ? v3 : t1;
                int j = colg >> 2;
                float c = cs[myRow * 144 + j];
                float c2 = sigm(gf) * c + sigm(gi) * ftanh(gg);
                float h2 = sigm(go) * ftanh(c2);
                cs[myRow * 144 + j] = c2;
                __half hh = __float2half(h2);
                hn[myRow * WPAD + j] = hh;
                yslice[(gRowBase + myRow) * 144 + j] = hh;
            }
        }
        __syncthreads();
        p ^= 1;
    }
}

// ---------------------------------------------------------------------------
// Host orchestration
// ---------------------------------------------------------------------------
extern "C" void kernel_launch(void* const* d_in, const int* in_sizes, int n_in,
                              void* d_out, int out_size) {
    const float* x     = (const float*)d_in[0];
    const float* gW0   = (const float*)d_in[1];
    const float* gb0   = (const float*)d_in[2];
    const float* ga0   = (const float*)d_in[3];
    const float* gW1   = (const float*)d_in[4];
    const float* gb1   = (const float*)d_in[5];
    const float* ga1   = (const float*)d_in[6];
    const float* eWih0 = (const float*)d_in[7];
    const float* eWhh0 = (const float*)d_in[8];
    const float* ebih0 = (const float*)d_in[9];
    const float* ebhh0 = (const float*)d_in[10];
    const float* eWih1 = (const float*)d_in[11];
    const float* eWhh1 = (const float*)d_in[12];
    const float* ebih1 = (const float*)d_in[13];
    const float* ebhh1 = (const float*)d_in[14];
    const float* dWhh0 = (const float*)d_in[16];
    const float* dbih0 = (const float*)d_in[17];
    const float* dbhh0 = (const float*)d_in[18];
    const float* dWih1 = (const float*)d_in[19];
    const float* dWhh1 = (const float*)d_in[20];
    const float* dbih1 = (const float*)d_in[21];
    const float* dbhh1 = (const float*)d_in[22];
    const float* gW3   = (const float*)d_in[23];
    const float* gb3   = (const float*)d_in[24];
    const float* ga3   = (const float*)d_in[25];
    const float* gW4   = (const float*)d_in[26];
    const float* gb4   = (const float*)d_in[27];
    const float* ga4   = (const float*)d_in[28];
    const float* fW    = (const float*)d_in[29];
    const float* fb    = (const float*)d_in[30];

    float* S = nullptr;
    cudaGetSymbolAddress((void**)&S, g_scratch);

    __half* x16     = (__half*)(S + OFF_X16);
    __half* out1    = (__half*)(S + OFF_OUT1);
    __half* h2_16   = (__half*)(S + OFF_H2);
    __half* Xpre16  = (__half*)(S + OFF_XPRE);
    __half* y0_16   = (__half*)(S + OFF_Y0);
    __half* yd0_16  = (__half*)(S + OFF_YD0);
    __half* yd1_16  = (__half*)(S + OFF_YD1);
    __half* o3_16   = (__half*)(S + OFF_O3);
    __half* h4_16   = (__half*)(S + OFF_H4);
    __half* enc1_16 = (__half*)(S + OFF_ENC1);
    float*  part    = S + OFF_PART;
    float*  probs   = S + OFF_PROBS;
    __half* Mb      = (__half*)(S + OFF_M);
    __half* w16     = (__half*)(S + OFF_W16);
    float*  br      = S + OFF_BR;
    __half* fw16    = (__half*)(S + OFF_FW16);

    __half* M1 = Mb;
    __half* M2 = M1 + 192 * 288;
    __half* M3 = M2 + 192 * 192;
    __half* M4 = M3 + 192 * 144;

    const size_t WSLICE = (size_t)576 * WPAD;
    __half* w_eWih0 = w16 + 0 * WSLICE;
    __half* w_eWhh0 = w16 + 1 * WSLICE;
    __half* w_eWih1 = w16 + 2 * WSLICE;
    __half* w_eWhh1 = w16 + 3 * WSLICE;
    __half* w_dWhh0 = w16 + 4 * WSLICE;
    __half* w_dWih1 = w16 + 5 * WSLICE;
    __half* w_dWhh1 = w16 + 6 * WSLICE;

    cudaFuncSetAttribute(lstm_chain, cudaFuncAttributeMaxDynamicSharedMemorySize,
                         CHAIN_SMEM);

    PrepArgs pa;
    pa.wsrc[0] = eWih0; pa.wsrc[1] = eWhh0; pa.wsrc[2] = eWih1; pa.wsrc[3] = eWhh1;
    pa.wsrc[4] = dWhh0; pa.wsrc[5] = dWih1; pa.wsrc[6] = dWhh1;
    pa.bih[0] = ebih0; pa.bih[1] = ebih1; pa.bih[2] = dbih0; pa.bih[3] = dbih1;
    pa.bhh[0] = ebhh0; pa.bhh[1] = ebhh1; pa.bhh[2] = dbhh0; pa.bhh[3] = dbhh1;
    pa.fW = fW;
    prep_all<<<(PREP_TOT + 255) / 256, 256>>>(pa, w16, br, fw16);
    convert_x<<<(int)(((size_t)NB * 288 + 255) / 256), 256>>>(x, x16);

    // ---- GAT 1+2 as GEMMs ----
    attn_pair<22, 16, 16, 12, false><<<1, 128>>>(x, gW0, gb0, ga0, gW1, gb1, ga1,
                                                 probs, probs + 576);
    build_M<<<(192 * 288 + 255) / 256, 256>>>(probs, gW0, M1, 192, 288, 16, 16, 24, 22);
    build_M<<<(192 * 192 + 255) / 256, 256>>>(probs + 576, gW1, M2, 192, 192, 16, 12, 16, 16);
    gemm2<2><<<dim3(3, NB / 256), 128>>>(x16, 288, M1, 288, out1, 192, 192, 16,
                                         gb0, nullptr, nullptr);
    gemm2<3><<<dim3(3, NB / 256), 128>>>(out1, 192, M2, 192, h2_16, 144, 192, 16,
                                         gb1, nullptr, nullptr);

    // ---- Encoder layer 0 ----
    gemm2<0><<<dim3(9, NB / 256), 128>>>(h2_16, 144, w_eWih0, WPAD, Xpre16, 576,
                                         0, 0, nullptr, nullptr, nullptr);
    lstm_chain<<<BB / 32, 256, CHAIN_SMEM>>>(w_eWhh0, br + 0, Xpre16, nullptr,
                                             y0_16, (size_t)BB * 144);
    // ---- Encoder layer 1 ----
    gemm2<0><<<dim3(9, NB / 256), 128>>>(y0_16, 144, w_eWih1, WPAD, Xpre16, 576,
                                         0, 0, nullptr, nullptr, nullptr);
    lstm_chain<<<BB / 32, 256, CHAIN_SMEM>>>(w_eWhh1, br + 576, Xpre16, nullptr,
                                             enc1_16, 0);
    // ---- Decoder layer 0 ----
    lstm_chain<<<BB / 32, 256, CHAIN_SMEM>>>(w_dWhh0, br + 1152, nullptr,
                                             y0_16 + (size_t)23 * BB * 144,
                                             yd0_16, (size_t)BB * 144);
    // ---- Decoder layer 1 ----
    gemm2<0><<<dim3(9, NB / 256), 128>>>(yd0_16, 144, w_dWih1, WPAD, Xpre16, 576,
                                         0, 0, nullptr, nullptr, nullptr);
    lstm_chain<<<BB / 32, 256, CHAIN_SMEM>>>(w_dWhh1, br + 1728, Xpre16, enc1_16,
                                             yd1_16, (size_t)BB * 144);

    // ---- GAT 3+4 as GEMMs ----
    attn_pair<12, 16, 16, 24, true><<<1, 128>>>(yd1_16, gW3, gb3, ga3, gW4, gb4, ga4,
                                                probs + 1152, probs + 1728);
    build_M<<<(192 * 144 + 255) / 256, 256>>>(probs + 1152, gW3, M3, 192, 144, 16, 16, 12, 12);
    build_M<<<(320 * 192 + 255) / 256, 256>>>(probs + 1728, gW4, M4, 320, 192, 24, 24, 16, 16);
    gemm2<2><<<dim3(3, NB / 256), 128>>>(yd1_16, 144, M3, 144, o3_16, 192, 192, 16,
                                         gb3, nullptr, nullptr);
    gemm2<2><<<dim3(5, NB / 256), 128>>>(o3_16, 192, M4, 192, h4_16, 288, 288, 24,
                                         gb4, nullptr, nullptr);

    // ---- FC + leaky + MSE ----
    gemm2<1><<<dim3(5, NB / 256), 128>>>(h4_16, 288, fw16, 288, nullptr, 0, 0, 0,
                                         fb, x, part);
    mse_final<<<(NB + 255) / 256, 256>>>(part, (float*)d_out);
}

// round 11
// speedup vs baseline: 3.3952x; 1.3043x over previous
#include <cuda_runtime.h>
#include <cuda_fp16.h>
#include <cstdint>
#include <cstddef>

// ---------------------------------------------------------------------------
// Problem constants
// ---------------------------------------------------------------------------
#define NB      98304
#define PERIOD  24
#define BB      (NB / PERIOD)     // 4096
#define WPAD    152               // padded K stride (halves) for LSTM weights

__constant__ int c_EI[44] = {0,0,0,0, 1,1,1, 2,2,2, 3,3, 4,4, 5,5,5, 6,6,6,6,
                             7,7,7, 8,8,8,8, 9,9,9,9, 10,10,10,10,10,10,10,
                             11,11,11,11,11};
__constant__ int c_EJ[44] = {0,5,10,11, 1,7,10, 2,6,11, 3,6, 4,5, 0,4,5,
                             2,3,6,10, 1,7,9, 8,9,10,11, 7,8,9,10,
                             0,1,6,8,9,10,11, 0,2,8,10,11};
__constant__ int c_RS[13] = {0,4,7,10,12,14,17,21,24,28,32,39,44};

// ---------------------------------------------------------------------------
// Scratch layout (float units)
// ---------------------------------------------------------------------------
#define OFF_X16   ((size_t)0)                        // fp16 [NB][288]
#define OFF_OUT1  (OFF_X16  + (size_t)NB * 144)      // fp16 [NB][192]
#define OFF_H2    (OFF_OUT1 + (size_t)NB * 96)       // fp16 [NB][144]
#define OFF_XPRE  (OFF_H2   + (size_t)NB * 72)       // fp16 [24][BB][576]
#define OFF_Y0    (OFF_XPRE + (size_t)NB * 288)      // fp16 [24][BB][144]
#define OFF_YD0   (OFF_Y0   + (size_t)NB * 72)
#define OFF_YD1   (OFF_YD0  + (size_t)NB * 72)
#define OFF_O3    (OFF_YD1  + (size_t)NB * 72)       // fp16 [NB][192]
#define OFF_H4    (OFF_O3   + (size_t)NB * 96)       // fp16 [NB][288]
#define OFF_ENC1  (OFF_H4   + (size_t)NB * 144)      // fp16 [BB][144]
#define OFF_PART  (OFF_ENC1 + (size_t)BB * 72)       // fp32 [5][NB]
#define OFF_PROBS (OFF_PART + (size_t)5 * NB)        // fp32 4*576
#define OFF_M     (OFF_PROBS + 2304)                 // fp16 M1..M4
#define SZ_M      ((192*288 + 192*192 + 192*144 + 320*192) / 2)
#define OFF_W16   (OFF_M + SZ_M)
#define OFF_BR    (OFF_W16 + (size_t)7 * 576 * WPAD / 2)
#define OFF_FW16  (OFF_BR + 4 * 576)
#define SCRATCH_TOTAL (OFF_FW16 + (size_t)320 * 288 / 2)

__device__ __align__(128) float g_scratch[SCRATCH_TOTAL];

__device__ __forceinline__ float tanha(float x) {
    float y;
    asm("tanh.approx.f32 %0, %1;" : "=f"(y) : "f"(x));
    return y;
}
__device__ __forceinline__ float sigm(float x) { return fmaf(tanha(0.5f * x), 0.5f, 0.5f); }
__device__ __forceinline__ float felu(float x) { return x > 0.f ? x : (__expf(x) - 1.f); }

__device__ __forceinline__ uint32_t smem_u32(const void* p) {
    return (uint32_t)__cvta_generic_to_shared(p);
}
__device__ __forceinline__ void ldm_x4(uint32_t& r0, uint32_t& r1, uint32_t& r2,
                                       uint32_t& r3, const void* p) {
    asm volatile("ldmatrix.sync.aligned.m8n8.x4.shared.b16 {%0,%1,%2,%3}, [%4];"
                 : "=r"(r0), "=r"(r1), "=r"(r2), "=r"(r3) : "r"(smem_u32(p)));
}
__device__ __forceinline__ void cp16(void* dst, const void* src) {
    asm volatile("cp.async.cg.shared.global [%0], [%1], 16;"
                 :: "r"(smem_u32(dst)), "l"(src));
}
__device__ __forceinline__ void cp_commit() {
    asm volatile("cp.async.commit_group;");
}
template <int N>
__device__ __forceinline__ void cp_wait() {
    asm volatile("cp.async.wait_group %0;" :: "n"(N));
}
#define MMA16(d0,d1,d2,d3,a0,a1,a2,a3,b0,b1)                                    \
    asm volatile("mma.sync.aligned.m16n8k16.row.col.f32.f16.f16.f32 "           \
                 "{%0,%1,%2,%3}, {%4,%5,%6,%7}, {%8,%9}, {%0,%1,%2,%3};"        \
                 : "+f"(d0), "+f"(d1), "+f"(d2), "+f"(d3)                       \
                 : "r"(a0), "r"(a1), "r"(a2), "r"(a3), "r"(b0), "r"(b1))

// ---------------------------------------------------------------------------
// Prep kernels
// ---------------------------------------------------------------------------
struct PrepArgs {
    const float* wsrc[7];
    const float* bih[4];
    const float* bhh[4];
    const float* fW;
};
#define PREP_W  (7 * 576 * WPAD)
#define PREP_B  (4 * 576)
#define PREP_F  (320 * 288)
#define PREP_TOT (PREP_W + PREP_B + PREP_F)

__global__ void prep_all(PrepArgs args, __half* w16, float* br, __half* fw16) {
    for (size_t idx = blockIdx.x * 256 + threadIdx.x; idx < PREP_TOT;
         idx += (size_t)gridDim.x * 256) {
        if (idx < PREP_W) {
            size_t m = idx / (576 * WPAD);
            int r = (int)(idx - m * (576 * WPAD));
            int np = r / WPAD, k = r - np * WPAD;
            int j = np >> 2, g = np & 3;
            w16[idx] = (k < 144)
                ? __float2half(args.wsrc[m][(g * 144 + j) * 144 + k]) : __half(0.f);
        } else if (idx < PREP_W + PREP_B) {
            int e = (int)(idx - PREP_W);
            int b = e / 576, np = e - b * 576;
            int j = np >> 2, g = np & 3;
            br[e] = args.bih[b][g * 144 + j] + args.bhh[b][g * 144 + j];
        } else {
            int e = (int)(idx - PREP_W - PREP_B);
            int n = e / 288, k = e - n * 288;
            fw16[e] = (n < 264) ? __float2half(args.fW[k * 264 + n]) : __half(0.f);
        }
    }
}

// x fp32 [NB,12,22] -> x16 fp16 [NB, 12*24] zero-padded
__global__ void convert_x(const float* __restrict__ x, __half* __restrict__ x16) {
    size_t idx = (size_t)blockIdx.x * 256 + threadIdx.x;
    if (idx >= (size_t)NB * 288) return;
    size_t b = idx / 288;
    int r = (int)(idx - b * 288);
    int j = r / 24, k = r - j * 24;
    x16[idx] = (k < 22) ? __float2half(x[b * 264 + j * 22 + k]) : __half(0.f);
}

// Build combined GAT matrix: M^T[n=(i,f)][kk=(j,k)] = P[i,j,h(f)] * W[k,f]
__global__ void build_M(const float* __restrict__ P, const float* __restrict__ W,
                        __half* __restrict__ M, int Nrows, int K,
                        int FPNP, int FV, int KP, int KV) {
    int idx = blockIdx.x * 256 + threadIdx.x;
    if (idx >= Nrows * K) return;
    int n = idx / K, kk = idx - n * K;
    int i = n / FPNP, f = n - i * FPNP;
    int j = kk / KP, k = kk - j * KP;
    float v = 0.f;
    if (f < FV && k < KV && i < 12) {
        int cs = FV >> 2;
        int h = f / cs;
        v = P[(i * 4 + h) * 12 + j] * W[k * FV + f];
    }
    M[idx] = __float2half(v);
}

// ---------------------------------------------------------------------------
// Attention probs for a PAIR of GAT layers (sample 0 only)
// ---------------------------------------------------------------------------
template <int CI1, int CO1, int CI2, int CO2, bool HALFIN>
__global__ void attn_pair(const void* xin,
                          const float* W1, const float* b1, const float* a1,
                          const float* W2, const float* b2, const float* a2,
                          float* probs1, float* probs2) {
    constexpr int CS1 = CO1 / 4, CS2 = CO2 / 4;
    __shared__ float x0[12 * CI1];
    __shared__ float feat[12 * CO1];
    __shared__ float lg[44 * 4];
    __shared__ float h1s[12 * CI2];
    __shared__ float feat2[12 * CO2];
    int tid = threadIdx.x;

    for (int i = tid; i < 12 * CI1; i += 128)
        x0[i] = HALFIN ? __half2float(((const __half*)xin)[i]) : ((const float*)xin)[i];
    __syncthreads();
    for (int idx = tid; idx < 12 * CO1; idx += 128) {
        int i = idx / CO1, f = idx - i * CO1;
        float acc = b1[f];
        for (int k = 0; k < CI1; k++) acc += x0[i * CI1 + k] * W1[k * CO1 + f];
        feat[idx] = acc;
    }
    __syncthreads();
    for (int idx = tid; idx < 176; idx += 128) {
        int e = idx >> 2, h = idx & 3;
        const float* ah = a1 + h * 2 * CS1;
        float s = 0.f;
        for (int c = 0; c < CS1; c++)
            s += ah[c] * feat[c_EI[e] * CO1 + h * CS1 + c] +
                 ah[CS1 + c] * feat[c_EJ[e] * CO1 + h * CS1 + c];
        lg[idx] = s > 0.f ? s : 0.2f * s;
    }
    __syncthreads();
    for (int idx = tid; idx < 48; idx += 128) {
        int i = idx >> 2, h = idx & 3;
        int s0 = c_RS[i], s1 = c_RS[i + 1];
        float m = -3.4e38f;
        for (int e = s0; e < s1; e++) m = fmaxf(m, lg[e * 4 + h]);
        float sum = 0.f;
        for (int e = s0; e < s1; e++) sum += expf(lg[e * 4 + h] - m);
        float* pr = probs1 + (i * 4 + h) * 12;
        for (int j = 0; j < 12; j++) pr[j] = 0.f;
        for (int e = s0; e < s1; e++) pr[c_EJ[e]] = expf(lg[e * 4 + h] - m) / sum;
    }
    __syncthreads();
    for (int idx = tid; idx < 12 * CO1; idx += 128) {
        int i = idx / CO1, f = idx - i * CO1;
        int h = f / CS1;
        const float* pr = probs1 + (i * 4 + h) * 12;
        float acc = 0.f;
        for (int j = 0; j < 12; j++) acc += pr[j] * feat[j * CO1 + f];
        h1s[idx] = acc > 0.f ? acc : expm1f(acc);
    }
    __syncthreads();
    for (int idx = tid; idx < 12 * CO2; idx += 128) {
        int i = idx / CO2, f = idx - i * CO2;
        float acc = b2[f];
        for (int k = 0; k < CI2; k++) acc += h1s[i * CI2 + k] * W2[k * CO2 + f];
        feat2[idx] = acc;
    }
    __syncthreads();
    for (int idx = tid; idx < 176; idx += 128) {
        int e = idx >> 2, h = idx & 3;
        const float* ah = a2 + h * 2 * CS2;
        float s = 0.f;
        for (int c = 0; c < CS2; c++)
            s += ah[c] * feat2[c_EI[e] * CO2 + h * CS2 + c] +
                 ah[CS2 + c] * feat2[c_EJ[e] * CO2 + h * CS2 + c];
        lg[idx] = s > 0.f ? s : 0.2f * s;
    }
    __syncthreads();
    for (int idx = tid; idx < 48; idx += 128) {
        int i = idx >> 2, h = idx & 3;
        int s0 = c_RS[i], s1 = c_RS[i + 1];
        float m = -3.4e38f;
        for (int e = s0; e < s1; e++) m = fmaxf(m, lg[e * 4 + h]);
        float sum = 0.f;
        for (int e = s0; e < s1; e++) sum += expf(lg[e * 4 + h] - m);
        float* pr = probs2 + (i * 4 + h) * 12;
        for (int j = 0; j < 12; j++) pr[j] = 0.f;
        for (int e = s0; e < s1; e++) pr[c_EJ[e]] = expf(lg[e * 4 + h] - m) / sum;
    }
}

// ---------------------------------------------------------------------------
// Unified fp16 GEMM, DOUBLE-BUFFERED cp.async pipeline.
// Tile 256x64, 128 threads = 4 warps, warp tile 64x64. Dynamic smem:
//   buffer = As[256][56] + Bs[64][56]  (17920 halves); two buffers.
//  EPI 0: fp16 store, stride ldc (Xpre)
//  EPI 1: FC: +bias, leaky_relu, (x-v)^2 row partials
//  EPI 2: ELU + fp16 store stride ldc, col guard nguard, bias idx colg%fpn
//  EPI 3: GAT2 remap: i=colg>>4, f=colg&15 (<12), store col i*12+f, stride 144
// ---------------------------------------------------------------------------
#define GBUF (256 * 56 + 64 * 56)          // halves per buffer
#define GSMEM (2 * GBUF * 2)               // bytes

template <int EPI>
__global__ __launch_bounds__(128, 2) void gemm2(
    const __half* __restrict__ A, int K,
    const __half* __restrict__ Bw, int ldb,
    __half* __restrict__ C, int ldc, int nguard, int fpn,
    const float* __restrict__ bias,
    const float* __restrict__ x, float* __restrict__ part) {
    extern __shared__ __align__(16) __half gsm[];
    const int tid = threadIdx.x;
    const int w = tid >> 5, lane = tid & 31;
    const int grp = lane >> 2, tig = lane & 3;

    float acc[4][8][4];
#pragma unroll
    for (int mt = 0; mt < 4; mt++)
#pragma unroll
        for (int nt = 0; nt < 8; nt++)
#pragma unroll
            for (int i = 0; i < 4; i++) acc[mt][nt][i] = 0.f;

    const size_t mBase = (size_t)blockIdx.y * 256;
    const int nBase = blockIdx.x * 64;

    const int aRow = w * 64 + (lane & 15);
    const int aCol = (lane >> 4) * 8;
    const int bRow = (lane & 7) + ((lane >> 4) & 1) * 8;
    const int bCol = ((lane >> 3) & 1) * 8;

    const int KT = K / 48;

    auto issue = [&](int buf, int k0) {
        __half* As = gsm + buf * GBUF;
        __half* Bs = As + 256 * 56;
#pragma unroll
        for (int i = 0; i < 12; i++) {
            int q = tid + i * 128;
            int row = q / 6, off = (q - row * 6) * 8;
            cp16(As + row * 56 + off, A + (mBase + row) * K + k0 + off);
        }
#pragma unroll
        for (int i = 0; i < 3; i++) {
            int q = tid + i * 128;
            int n = q / 6, off = (q - n * 6) * 8;
            cp16(Bs + n * 56 + off, Bw + (size_t)(nBase + n) * ldb + k0 + off);
        }
        cp_commit();
    };

    issue(0, 0);
    for (int kt = 0; kt < KT; kt++) {
        int cur = kt & 1;
        if (kt + 1 < KT) issue(cur ^ 1, (kt + 1) * 48);
        if (kt + 1 < KT) cp_wait<1>(); else cp_wait<0>();
        __syncthreads();
        __half* As = gsm + cur * GBUF;
        __half* Bs = As + 256 * 56;
#pragma unroll
        for (int kc = 0; kc < 3; kc++) {
            uint32_t a[4][4], b[4][4];
#pragma unroll
            for (int mt = 0; mt < 4; mt++)
                ldm_x4(a[mt][0], a[mt][1], a[mt][2], a[mt][3],
                       As + (aRow + mt * 16) * 56 + kc * 16 + aCol);
#pragma unroll
            for (int g = 0; g < 4; g++)
                ldm_x4(b[g][0], b[g][1], b[g][2], b[g][3],
                       Bs + (bRow + g * 16) * 56 + kc * 16 + bCol);
#pragma unroll
            for (int mt = 0; mt < 4; mt++)
#pragma unroll
                for (int g = 0; g < 4; g++) {
                    MMA16(acc[mt][2*g][0], acc[mt][2*g][1], acc[mt][2*g][2], acc[mt][2*g][3],
                          a[mt][0], a[mt][1], a[mt][2], a[mt][3], b[g][0], b[g][1]);
                    MMA16(acc[mt][2*g+1][0], acc[mt][2*g+1][1], acc[mt][2*g+1][2], acc[mt][2*g+1][3],
                          a[mt][0], a[mt][1], a[mt][2], a[mt][3], b[g][2], b[g][3]);
                }
        }
        __syncthreads();
    }

    if (EPI == 0) {
#pragma unroll
        for (int mt = 0; mt < 4; mt++)
#pragma unroll
            for (int nt = 0; nt < 8; nt++) {
                float* a = acc[mt][nt];
                int colg = nBase + nt * 8 + 2 * tig;
                size_t row0 = mBase + w * 64 + mt * 16 + grp;
                *(__half2*)(C + row0 * ldc + colg) = __floats2half2_rn(a[0], a[1]);
                *(__half2*)(C + (row0 + 8) * ldc + colg) = __floats2half2_rn(a[2], a[3]);
            }
    } else if (EPI == 2) {
#pragma unroll
        for (int mt = 0; mt < 4; mt++)
#pragma unroll
            for (int nt = 0; nt < 8; nt++) {
                int colg = nBase + nt * 8 + 2 * tig;
                if (colg >= nguard) continue;
                float* a = acc[mt][nt];
                size_t row0 = mBase + w * 64 + mt * 16 + grp;
                int f = colg % fpn;
                float bx = bias[f], by = bias[f + 1];
                *(__half2*)(C + row0 * ldc + colg) =
                    __floats2half2_rn(felu(a[0] + bx), felu(a[1] + by));
                *(__half2*)(C + (row0 + 8) * ldc + colg) =
                    __floats2half2_rn(felu(a[2] + bx), felu(a[3] + by));
            }
    } else if (EPI == 3) {
#pragma unroll
        for (int mt = 0; mt < 4; mt++)
#pragma unroll
            for (int nt = 0; nt < 8; nt++) {
                int colg = nBase + nt * 8 + 2 * tig;
                int f = colg & 15;
                if (f >= 12) continue;
                int i = colg >> 4;
                int oc = i * 12 + f;
                float* a = acc[mt][nt];
                size_t row0 = mBase + w * 64 + mt * 16 + grp;
                float bx = bias[f], by = bias[f + 1];
                *(__half2*)(C + row0 * 144 + oc) =
                    __floats2half2_rn(felu(a[0] + bx), felu(a[1] + by));
                *(__half2*)(C + (row0 + 8) * 144 + oc) =
                    __floats2half2_rn(felu(a[2] + bx), felu(a[3] + by));
            }
    } else {  // EPI 1: FC + MSE partials
        float s[4][2];
#pragma unroll
        for (int mt = 0; mt < 4; mt++) { s[mt][0] = 0.f; s[mt][1] = 0.f; }
#pragma unroll
        for (int mt = 0; mt < 4; mt++)
#pragma unroll
            for (int nt = 0; nt < 8; nt++) {
                int colg = nBase + nt * 8 + 2 * tig;
                if (colg >= 264) continue;
                float* a = acc[mt][nt];
                size_t row0 = mBase + w * 64 + mt * 16 + grp;
                float bx = bias[colg], by = bias[colg + 1];
                float v0 = a[0] + bx, v1 = a[1] + by, v2 = a[2] + bx, v3 = a[3] + by;
                v0 = v0 >= 0.f ? v0 : 0.01f * v0;
                v1 = v1 >= 0.f ? v1 : 0.01f * v1;
                v2 = v2 >= 0.f ? v2 : 0.01f * v2;
                v3 = v3 >= 0.f ? v3 : 0.01f * v3;
                float2 xa = *(const float2*)(x + row0 * 264 + colg);
                float2 xb = *(const float2*)(x + (row0 + 8) * 264 + colg);
                float d0 = xa.x - v0, d1 = xa.y - v1, d2 = xb.x - v2, d3 = xb.y - v3;
                s[mt][0] += d0 * d0 + d1 * d1;
                s[mt][1] += d2 * d2 + d3 * d3;
            }
#pragma unroll
        for (int mt = 0; mt < 4; mt++) {
            size_t row0 = mBase + w * 64 + mt * 16 + grp;
            float v0 = s[mt][0], v1 = s[mt][1];
            v0 += __shfl_xor_sync(0xffffffffu, v0, 1);
            v0 += __shfl_xor_sync(0xffffffffu, v0, 2);
            v1 += __shfl_xor_sync(0xffffffffu, v1, 1);
            v1 += __shfl_xor_sync(0xffffffffu, v1, 2);
            if (tig == 0) {
                part[(size_t)blockIdx.x * NB + row0] = v0;
                part[(size_t)blockIdx.x * NB + row0 + 8] = v1;
            }
        }
    }
}

__global__ void mse_final(const float* __restrict__ part, float* __restrict__ out) {
    int idx = blockIdx.x * 256 + threadIdx.x;
    if (idx >= NB) return;
    float s = 0.f;
#pragma unroll
    for (int k = 0; k < 5; k++) s += part[(size_t)k * NB + idx];
    out[idx] = s * (1.f / 264.f);
}

// ---------------------------------------------------------------------------
// Persistent LSTM chain (tanh.approx activations)
// ---------------------------------------------------------------------------
#define CHAIN_SMEM (576 * WPAD * 2 + 2 * 32 * WPAD * 2 + 32 * 144 * 4 + 576 * 4)

__global__ __launch_bounds__(256, 1) void lstm_chain(
    const __half* __restrict__ W16, const float* __restrict__ bias,
    const __half* __restrict__ xpre, const __half* __restrict__ hInit,
    __half* __restrict__ y, size_t yStride) {
    extern __shared__ __align__(16) unsigned char smem_raw[];
    __half* Ws  = (__half*)smem_raw;
    __half* h0s = Ws + 576 * WPAD;
    __half* h1s = h0s + 32 * WPAD;
    float*  cs  = (float*)(h1s + 32 * WPAD);
    float*  bs  = cs + 32 * 144;

    const int tid = threadIdx.x;
    const int w = tid >> 5, lane = tid & 31;
    const int warpM = w >> 2, warpN = w & 3;
    const int grp = lane >> 2, tig = lane & 3;
    const size_t gRowBase = (size_t)blockIdx.x * 32;

    {
        const uint4* src = (const uint4*)W16;
        uint4* dst = (uint4*)Ws;
        for (int i = tid; i < 576 * WPAD / 8; i += 256) dst[i] = src[i];
    }
    for (int i = tid; i < 32 * WPAD; i += 256) { h0s[i] = __half(0.f); h1s[i] = __half(0.f); }
    for (int i = tid; i < 32 * 144; i += 256) cs[i] = 0.f;
    for (int i = tid; i < 576; i += 256) bs[i] = bias[i];
    __syncthreads();
    if (hInit) {
        for (int i = tid; i < 32 * 144; i += 256) {
            int r = i / 144, j = i - r * 144;
            h0s[r * WPAD + j] = hInit[(gRowBase + r) * 144 + j];
        }
        __syncthreads();
    }

    const int row0 = warpM * 16 + grp;
    const int aRow = warpM * 16 + (lane & 15);
    const int aCol = (lane >> 4) * 8;
    const int bRowBase = warpN * 144 + (lane & 7) + ((lane >> 4) & 1) * 8;
    const int bCol = ((lane >> 3) & 1) * 8;
    const int myRow = (tig & 1) ? row0 + 8 : row0;

    int p = 0;
    for (int t = 0; t < PERIOD; t++) {
        const __half* hc = p ? h1s : h0s;
        __half* hn = p ? h0s : h1s;
        const __half* xslice = xpre ? (xpre + (size_t)t * BB * 576) : nullptr;
        __half* yslice = y + (size_t)t * yStride;

        uint32_t Areg[9][4];
#pragma unroll
        for (int kc = 0; kc < 9; kc++)
            ldm_x4(Areg[kc][0], Areg[kc][1], Areg[kc][2], Areg[kc][3],
                   hc + aRow * WPAD + kc * 16 + aCol);

#pragma unroll
        for (int np = 0; np < 9; np++) {
            float d[2][4];
#pragma unroll
            for (int u = 0; u < 2; u++)
#pragma unroll
                for (int i = 0; i < 4; i++) d[u][i] = 0.f;
            const __half* wb = Ws + (bRowBase + np * 16) * WPAD + bCol;
#pragma unroll
            for (int kc = 0; kc < 9; kc++) {
                uint32_t b0, b1, b2, b3;
                ldm_x4(b0, b1, b2, b3, wb + kc * 16);
                MMA16(d[0][0], d[0][1], d[0][2], d[0][3],
                      Areg[kc][0], Areg[kc][1], Areg[kc][2], Areg[kc][3], b0, b1);
                MMA16(d[1][0], d[1][1], d[1][2], d[1][3],
                      Areg[kc][0], Areg[kc][1], Areg[kc][2], Areg[kc][3], b2, b3);
            }
#pragma unroll
            for (int u = 0; u < 2; u++) {
                int colg = warpN * 144 + (2 * np + u) * 8 + 2 * tig;
                float v0 = d[u][0] + bs[colg], v1 = d[u][1] + bs[colg + 1];
                float v2 = d[u][2] + bs[colg], v3 = d[u][3] + bs[colg + 1];
                if (xslice) {
                    __half2 x0 = *(const __half2*)(xslice + (gRowBase + row0) * 576 + colg);
                    __half2 x1 = *(const __half2*)(xslice + (gRowBase + row0 + 8) * 576 + colg);
                    v0 += __half2float(x0.x); v1 += __half2float(x0.y);
                    v2 += __half2float(x1.x); v3 += __half2float(x1.y);
                }
                float t0 = __shfl_xor_sync(0xffffffffu, v0, 1);
                float t1 = __shfl_xor_sync(0xffffffffu, v1, 1);
                float t2 = __shfl_xor_sync(0xffffffffu, v2, 1);
                float t3 = __shfl_xor_sync(0xffffffffu, v3, 1);
                float gi = (tig & 1) ? t2 : v0;
                float gf = (tig & 1) ? t3 : v1;
                float gg = (tig & 1) ? v2 : t0;
                float go = (tig & 1) ? v3 : t1;
                int j = colg >> 2;
                float c = cs[myRow * 144 + j];
                float c2 = sigm(gf) * c + sigm(gi) * tanha(gg);
                float h2 = sigm(go) * tanha(c2);
                cs[myRow * 144 + j] = c2;
                __half hh = __float2half(h2);
                hn[myRow * WPAD + j] = hh;
                yslice[(gRowBase + myRow) * 144 + j] = hh;
            }
        }
        __syncthreads();
        p ^= 1;
    }
}

// ---------------------------------------------------------------------------
// Host orchestration
// ---------------------------------------------------------------------------
extern "C" void kernel_launch(void* const* d_in, const int* in_sizes, int n_in,
                              void* d_out, int out_size) {
    const float* x     = (const float*)d_in[0];
    const float* gW0   = (const float*)d_in[1];
    const float* gb0   = (const float*)d_in[2];
    const float* ga0   = (const float*)d_in[3];
    const float* gW1   = (const float*)d_in[4];
    const float* gb1   = (const float*)d_in[5];
    const float* ga1   = (const float*)d_in[6];
    const float* eWih0 = (const float*)d_in[7];
    const float* eWhh0 = (const float*)d_in[8];
    const float* ebih0 = (const float*)d_in[9];
    const float* ebhh0 = (const float*)d_in[10];
    const float* eWih1 = (const float*)d_in[11];
    const float* eWhh1 = (const float*)d_in[12];
    const float* ebih1 = (const float*)d_in[13];
    const float* ebhh1 = (const float*)d_in[14];
    const float* dWhh0 = (const float*)d_in[16];
    const float* dbih0 = (const float*)d_in[17];
    const float* dbhh0 = (const float*)d_in[18];
    const float* dWih1 = (const float*)d_in[19];
    const float* dWhh1 = (const float*)d_in[20];
    const float* dbih1 = (const float*)d_in[21];
    const float* dbhh1 = (const float*)d_in[22];
    const float* gW3   = (const float*)d_in[23];
    const float* gb3   = (const float*)d_in[24];
    const float* ga3   = (const float*)d_in[25];
    const float* gW4   = (const float*)d_in[26];
    const float* gb4   = (const float*)d_in[27];
    const float* ga4   = (const float*)d_in[28];
    const float* fW    = (const float*)d_in[29];
    const float* fb    = (const float*)d_in[30];

    float* S = nullptr;
    cudaGetSymbolAddress((void**)&S, g_scratch);

    __half* x16     = (__half*)(S + OFF_X16);
    __half* out1    = (__half*)(S + OFF_OUT1);
    __half* h2_16   = (__half*)(S + OFF_H2);
    __half* Xpre16  = (__half*)(S + OFF_XPRE);
    __half* y0_16   = (__half*)(S + OFF_Y0);
    __half* yd0_16  = (__half*)(S + OFF_YD0);
    __half* yd1_16  = (__half*)(S + OFF_YD1);
    __half* o3_16   = (__half*)(S + OFF_O3);
    __half* h4_16   = (__half*)(S + OFF_H4);
    __half* enc1_16 = (__half*)(S + OFF_ENC1);
    float*  part    = S + OFF_PART;
    float*  probs   = S + OFF_PROBS;
    __half* Mb      = (__half*)(S + OFF_M);
    __half* w16     = (__half*)(S + OFF_W16);
    float*  br      = S + OFF_BR;
    __half* fw16    = (__half*)(S + OFF_FW16);

    __half* M1 = Mb;
    __half* M2 = M1 + 192 * 288;
    __half* M3 = M2 + 192 * 192;
    __half* M4 = M3 + 192 * 144;

    const size_t WSLICE = (size_t)576 * WPAD;
    __half* w_eWih0 = w16 + 0 * WSLICE;
    __half* w_eWhh0 = w16 + 1 * WSLICE;
    __half* w_eWih1 = w16 + 2 * WSLICE;
    __half* w_eWhh1 = w16 + 3 * WSLICE;
    __half* w_dWhh0 = w16 + 4 * WSLICE;
    __half* w_dWih1 = w16 + 5 * WSLICE;
    __half* w_dWhh1 = w16 + 6 * WSLICE;

    cudaFuncSetAttribute(lstm_chain, cudaFuncAttributeMaxDynamicSharedMemorySize,
                         CHAIN_SMEM);
    cudaFuncSetAttribute(gemm2<0>, cudaFuncAttributeMaxDynamicSharedMemorySize, GSMEM);
    cudaFuncSetAttribute(gemm2<1>, cudaFuncAttributeMaxDynamicSharedMemorySize, GSMEM);
    cudaFuncSetAttribute(gemm2<2>, cudaFuncAttributeMaxDynamicSharedMemorySize, GSMEM);
    cudaFuncSetAttribute(gemm2<3>, cudaFuncAttributeMaxDynamicSharedMemorySize, GSMEM);

    PrepArgs pa;
    pa.wsrc[0] = eWih0; pa.wsrc[1] = eWhh0; pa.wsrc[2] = eWih1; pa.wsrc[3] = eWhh1;
    pa.wsrc[4] = dWhh0; pa.wsrc[5] = dWih1; pa.wsrc[6] = dWhh1;
    pa.bih[0] = ebih0; pa.bih[1] = ebih1; pa.bih[2] = dbih0; pa.bih[3] = dbih1;
    pa.bhh[0] = ebhh0; pa.bhh[1] = ebhh1; pa.bhh[2] = dbhh0; pa.bhh[3] = dbhh1;
    pa.fW = fW;
    prep_all<<<(PREP_TOT + 255) / 256, 256>>>(pa, w16, br, fw16);
    convert_x<<<(int)(((size_t)NB * 288 + 255) / 256), 256>>>(x, x16);

    // ---- GAT 1+2 as GEMMs ----
    attn_pair<22, 16, 16, 12, false><<<1, 128>>>(x, gW0, gb0, ga0, gW1, gb1, ga1,
                                                 probs, probs + 576);
    build_M<<<(192 * 288 + 255) / 256, 256>>>(probs, gW0, M1, 192, 288, 16, 16, 24, 22);
    build_M<<<(192 * 192 + 255) / 256, 256>>>(probs + 576, gW1, M2, 192, 192, 16, 12, 16, 16);
    gemm2<2><<<dim3(3, NB / 256), 128, GSMEM>>>(x16, 288, M1, 288, out1, 192, 192, 16,
                                                gb0, nullptr, nullptr);
    gemm2<3><<<dim3(3, NB / 256), 128, GSMEM>>>(out1, 192, M2, 192, h2_16, 144, 192, 16,
                                                gb1, nullptr, nullptr);

    // ---- Encoder layer 0 ----
    gemm2<0><<<dim3(9, NB / 256), 128, GSMEM>>>(h2_16, 144, w_eWih0, WPAD, Xpre16, 576,
                                                0, 0, nullptr, nullptr, nullptr);
    lstm_chain<<<BB / 32, 256, CHAIN_SMEM>>>(w_eWhh0, br + 0, Xpre16, nullptr,
                                             y0_16, (size_t)BB * 144);
    // ---- Encoder layer 1 ----
    gemm2<0><<<dim3(9, NB / 256), 128, GSMEM>>>(y0_16, 144, w_eWih1, WPAD, Xpre16, 576,
                                                0, 0, nullptr, nullptr, nullptr);
    lstm_chain<<<BB / 32, 256, CHAIN_SMEM>>>(w_eWhh1, br + 576, Xpre16, nullptr,
                                             enc1_16, 0);
    // ---- Decoder layer 0 ----
    lstm_chain<<<BB / 32, 256, CHAIN_SMEM>>>(w_dWhh0, br + 1152, nullptr,
                                             y0_16 + (size_t)23 * BB * 144,
                                             yd0_16, (size_t)BB * 144);
    // ---- Decoder layer 1 ----
    gemm2<0><<<dim3(9, NB / 256), 128, GSMEM>>>(yd0_16, 144, w_dWih1, WPAD, Xpre16, 576,
                                                0, 0, nullptr, nullptr, nullptr);
    lstm_chain<<<BB / 32, 256, CHAIN_SMEM>>>(w_dWhh1, br + 1728, Xpre16, enc1_16,
                                             yd1_16, (size_t)BB * 144);

    // ---- GAT 3+4 as GEMMs ----
    attn_pair<12, 16, 16, 24, true><<<1, 128>>>(yd1_16, gW3, gb3, ga3, gW4, gb4, ga4,
                                                probs + 1152, probs + 1728);
    build_M<<<(192 * 144 + 255) / 256, 256>>>(probs + 1152, gW3, M3, 192, 144, 16, 16, 12, 12);
    build_M<<<(320 * 192 + 255) / 256, 256>>>(probs + 1728, gW4, M4, 320, 192, 24, 24, 16, 16);
    gemm2<2><<<dim3(3, NB / 256), 128, GSMEM>>>(yd1_16, 144, M3, 144, o3_16, 192, 192, 16,
                                                gb3, nullptr, nullptr);
    gemm2<2><<<dim3(5, NB / 256), 128, GSMEM>>>(o3_16, 192, M4, 192, h4_16, 288, 288, 24,
                                                gb4, nullptr, nullptr);

    // ---- FC + leaky + MSE ----
    gemm2<1><<<dim3(5, NB / 256), 128, GSMEM>>>(h4_16, 288, fw16, 288, nullptr, 0, 0, 0,
                                                fb, x, part);
    mse_final<<<(NB + 255) / 256, 256>>>(part, (float*)d_out);
}

// round 12
// speedup vs baseline: 3.5176x; 1.0361x over previous
#include <cuda_runtime.h>
#include <cuda_fp16.h>
#include <cstdint>
#include <cstddef>

// ---------------------------------------------------------------------------
// Problem constants
// ---------------------------------------------------------------------------
#define NB      98304
#define PERIOD  24
#define BB      (NB / PERIOD)     // 4096
#define WPAD    152               // padded K stride (halves) for LSTM weights

__constant__ int c_EI[44] = {0,0,0,0, 1,1,1, 2,2,2, 3,3, 4,4, 5,5,5, 6,6,6,6,
                             7,7,7, 8,8,8,8, 9,9,9,9, 10,10,10,10,10,10,10,
                             11,11,11,11,11};
__constant__ int c_EJ[44] = {0,5,10,11, 1,7,10, 2,6,11, 3,6, 4,5, 0,4,5,
                             2,3,6,10, 1,7,9, 8,9,10,11, 7,8,9,10,
                             0,1,6,8,9,10,11, 0,2,8,10,11};
__constant__ int c_RS[13] = {0,4,7,10,12,14,17,21,24,28,32,39,44};

// ---------------------------------------------------------------------------
// Scratch layout (float units)
// ---------------------------------------------------------------------------
#define OFF_X16   ((size_t)0)                        // fp16 [NB][288]
#define OFF_OUT1  (OFF_X16  + (size_t)NB * 144)      // fp16 [NB][192]
#define OFF_H2    (OFF_OUT1 + (size_t)NB * 96)       // fp16 [NB][144]
#define OFF_XPRE  (OFF_H2   + (size_t)NB * 72)       // fp16 [24][72][256][128] tiles
#define OFF_Y0    (OFF_XPRE + (size_t)NB * 288)      // fp16 [24][BB][144]
#define OFF_YD0   (OFF_Y0   + (size_t)NB * 72)
#define OFF_YD1   (OFF_YD0  + (size_t)NB * 72)
#define OFF_O3    (OFF_YD1  + (size_t)NB * 72)       // fp16 [NB][192]
#define OFF_H4    (OFF_O3   + (size_t)NB * 96)       // fp16 [NB][288]
#define OFF_ENC1  (OFF_H4   + (size_t)NB * 144)      // fp16 [BB][144]
#define OFF_PART  (OFF_ENC1 + (size_t)BB * 72)       // fp32 [5][NB]
#define OFF_PROBS (OFF_PART + (size_t)5 * NB)        // fp32 4*576
#define OFF_M     (OFF_PROBS + 2304)                 // fp16 M1..M4
#define SZ_M      ((192*288 + 192*192 + 192*144 + 320*192) / 2)
#define OFF_W16   (OFF_M + SZ_M)
#define OFF_BR    (OFF_W16 + (size_t)7 * 576 * WPAD / 2)
#define OFF_FW16  (OFF_BR + 4 * 576)
#define SCRATCH_TOTAL (OFF_FW16 + (size_t)320 * 288 / 2)

__device__ __align__(128) float g_scratch[SCRATCH_TOTAL];

__device__ __forceinline__ float tanha(float x) {
    float y;
    asm("tanh.approx.f32 %0, %1;" : "=f"(y) : "f"(x));
    return y;
}
__device__ __forceinline__ float sigm(float x) { return fmaf(tanha(0.5f * x), 0.5f, 0.5f); }
__device__ __forceinline__ float felu(float x) { return x > 0.f ? x : (__expf(x) - 1.f); }

__device__ __forceinline__ uint32_t smem_u32(const void* p) {
    return (uint32_t)__cvta_generic_to_shared(p);
}
__device__ __forceinline__ void ldm_x4(uint32_t& r0, uint32_t& r1, uint32_t& r2,
                                       uint32_t& r3, const void* p) {
    asm volatile("ldmatrix.sync.aligned.m8n8.x4.shared.b16 {%0,%1,%2,%3}, [%4];"
                 : "=r"(r0), "=r"(r1), "=r"(r2), "=r"(r3) : "r"(smem_u32(p)));
}
__device__ __forceinline__ void cp16(void* dst, const void* src) {
    asm volatile("cp.async.cg.shared.global [%0], [%1], 16;"
                 :: "r"(smem_u32(dst)), "l"(src));
}
__device__ __forceinline__ void cp_commit() {
    asm volatile("cp.async.commit_group;");
}
template <int N>
__device__ __forceinline__ void cp_wait() {
    asm volatile("cp.async.wait_group %0;" :: "n"(N));
}
#define MMA16(d0,d1,d2,d3,a0,a1,a2,a3,b0,b1)                                    \
    asm volatile("mma.sync.aligned.m16n8k16.row.col.f32.f16.f16.f32 "           \
                 "{%0,%1,%2,%3}, {%4,%5,%6,%7}, {%8,%9}, {%0,%1,%2,%3};"        \
                 : "+f"(d0), "+f"(d1), "+f"(d2), "+f"(d3)                       \
                 : "r"(a0), "r"(a1), "r"(a2), "r"(a3), "r"(b0), "r"(b1))

// ---------------------------------------------------------------------------
// Prep kernels
// ---------------------------------------------------------------------------
struct PrepArgs {
    const float* wsrc[7];
    const float* bih[4];
    const float* bhh[4];
    const float* fW;
};
#define PREP_W  (7 * 576 * WPAD)
#define PREP_B  (4 * 576)
#define PREP_F  (320 * 288)
#define PREP_TOT (PREP_W + PREP_B + PREP_F)

__global__ void prep_all(PrepArgs args, __half* w16, float* br, __half* fw16) {
    for (size_t idx = blockIdx.x * 256 + threadIdx.x; idx < PREP_TOT;
         idx += (size_t)gridDim.x * 256) {
        if (idx < PREP_W) {
            size_t m = idx / (576 * WPAD);
            int r = (int)(idx - m * (576 * WPAD));
            int np = r / WPAD, k = r - np * WPAD;
            int j = np >> 2, g = np & 3;
            w16[idx] = (k < 144)
                ? __float2half(args.wsrc[m][(g * 144 + j) * 144 + k]) : __half(0.f);
        } else if (idx < PREP_W + PREP_B) {
            int e = (int)(idx - PREP_W);
            int b = e / 576, np = e - b * 576;
            int j = np >> 2, g = np & 3;
            br[e] = args.bih[b][g * 144 + j] + args.bhh[b][g * 144 + j];
        } else {
            int e = (int)(idx - PREP_W - PREP_B);
            int n = e / 288, k = e - n * 288;
            fw16[e] = (n < 264) ? __float2half(args.fW[k * 264 + n]) : __half(0.f);
        }
    }
}

// x fp32 [NB,12,22] -> x16 fp16 [NB, 12*24] zero-padded
__global__ void convert_x(const float* __restrict__ x, __half* __restrict__ x16) {
    size_t idx = (size_t)blockIdx.x * 256 + threadIdx.x;
    if (idx >= (size_t)NB * 288) return;
    size_t b = idx / 288;
    int r = (int)(idx - b * 288);
    int j = r / 24, k = r - j * 24;
    x16[idx] = (k < 22) ? __float2half(x[b * 264 + j * 22 + k]) : __half(0.f);
}

// Build combined GAT matrix: M^T[n=(i,f)][kk=(j,k)] = P[i,j,h(f)] * W[k,f]
__global__ void build_M(const float* __restrict__ P, const float* __restrict__ W,
                        __half* __restrict__ M, int Nrows, int K,
                        int FPNP, int FV, int KP, int KV) {
    int idx = blockIdx.x * 256 + threadIdx.x;
    if (idx >= Nrows * K) return;
    int n = idx / K, kk = idx - n * K;
    int i = n / FPNP, f = n - i * FPNP;
    int j = kk / KP, k = kk - j * KP;
    float v = 0.f;
    if (f < FV && k < KV && i < 12) {
        int cs = FV >> 2;
        int h = f / cs;
        v = P[(i * 4 + h) * 12 + j] * W[k * FV + f];
    }
    M[idx] = __float2half(v);
}

// ---------------------------------------------------------------------------
// Attention probs for a PAIR of GAT layers (sample 0 only)
// ---------------------------------------------------------------------------
template <int CI1, int CO1, int CI2, int CO2, bool HALFIN>
__global__ void attn_pair(const void* xin,
                          const float* W1, const float* b1, const float* a1,
                          const float* W2, const float* b2, const float* a2,
                          float* probs1, float* probs2) {
    constexpr int CS1 = CO1 / 4, CS2 = CO2 / 4;
    __shared__ float x0[12 * CI1];
    __shared__ float feat[12 * CO1];
    __shared__ float lg[44 * 4];
    __shared__ float h1s[12 * CI2];
    __shared__ float feat2[12 * CO2];
    int tid = threadIdx.x;

    for (int i = tid; i < 12 * CI1; i += 128)
        x0[i] = HALFIN ? __half2float(((const __half*)xin)[i]) : ((const float*)xin)[i];
    __syncthreads();
    for (int idx = tid; idx < 12 * CO1; idx += 128) {
        int i = idx / CO1, f = idx - i * CO1;
        float acc = b1[f];
        for (int k = 0; k < CI1; k++) acc += x0[i * CI1 + k] * W1[k * CO1 + f];
        feat[idx] = acc;
    }
    __syncthreads();
    for (int idx = tid; idx < 176; idx += 128) {
        int e = idx >> 2, h = idx & 3;
        const float* ah = a1 + h * 2 * CS1;
        float s = 0.f;
        for (int c = 0; c < CS1; c++)
            s += ah[c] * feat[c_EI[e] * CO1 + h * CS1 + c] +
                 ah[CS1 + c] * feat[c_EJ[e] * CO1 + h * CS1 + c];
        lg[idx] = s > 0.f ? s : 0.2f * s;
    }
    __syncthreads();
    for (int idx = tid; idx < 48; idx += 128) {
        int i = idx >> 2, h = idx & 3;
        int s0 = c_RS[i], s1 = c_RS[i + 1];
        float m = -3.4e38f;
        for (int e = s0; e < s1; e++) m = fmaxf(m, lg[e * 4 + h]);
        float sum = 0.f;
        for (int e = s0; e < s1; e++) sum += expf(lg[e * 4 + h] - m);
        float* pr = probs1 + (i * 4 + h) * 12;
        for (int j = 0; j < 12; j++) pr[j] = 0.f;
        for (int e = s0; e < s1; e++) pr[c_EJ[e]] = expf(lg[e * 4 + h] - m) / sum;
    }
    __syncthreads();
    for (int idx = tid; idx < 12 * CO1; idx += 128) {
        int i = idx / CO1, f = idx - i * CO1;
        int h = f / CS1;
        const float* pr = probs1 + (i * 4 + h) * 12;
        float acc = 0.f;
        for (int j = 0; j < 12; j++) acc += pr[j] * feat[j * CO1 + f];
        h1s[idx] = acc > 0.f ? acc : expm1f(acc);
    }
    __syncthreads();
    for (int idx = tid; idx < 12 * CO2; idx += 128) {
        int i = idx / CO2, f = idx - i * CO2;
        float acc = b2[f];
        for (int k = 0; k < CI2; k++) acc += h1s[i * CI2 + k] * W2[k * CO2 + f];
        feat2[idx] = acc;
    }
    __syncthreads();
    for (int idx = tid; idx < 176; idx += 128) {
        int e = idx >> 2, h = idx & 3;
        const float* ah = a2 + h * 2 * CS2;
        float s = 0.f;
        for (int c = 0; c < CS2; c++)
            s += ah[c] * feat2[c_EI[e] * CO2 + h * CS2 + c] +
                 ah[CS2 + c] * feat2[c_EJ[e] * CO2 + h * CS2 + c];
        lg[idx] = s > 0.f ? s : 0.2f * s;
    }
    __syncthreads();
    for (int idx = tid; idx < 48; idx += 128) {
        int i = idx >> 2, h = idx & 3;
        int s0 = c_RS[i], s1 = c_RS[i + 1];
        float m = -3.4e38f;
        for (int e = s0; e < s1; e++) m = fmaxf(m, lg[e * 4 + h]);
        float sum = 0.f;
        for (int e = s0; e < s1; e++) sum += expf(lg[e * 4 + h] - m);
        float* pr = probs2 + (i * 4 + h) * 12;
        for (int j = 0; j < 12; j++) pr[j] = 0.f;
        for (int e = s0; e < s1; e++) pr[c_EJ[e]] = expf(lg[e * 4 + h] - m) / sum;
    }
}

// ---------------------------------------------------------------------------
// Unified fp16 GEMM, double-buffered cp.async pipeline.
// Tile 256x64, 128 threads = 4 warps, warp tile 64x64.
//  EPI 0: fragment-packed Xpre store: [t][tile_n=72][tile_m=256][128]
//  EPI 1: FC: +bias, leaky_relu, (x-v)^2 row partials
//  EPI 2: ELU + fp16 store stride ldc, col guard nguard, bias idx colg%fpn
//  EPI 3: GAT2 remap: i=colg>>4, f=colg&15 (<12), store col i*12+f, stride 144
// ---------------------------------------------------------------------------
#define GBUF (256 * 56 + 64 * 56)          // halves per buffer
#define GSMEM (2 * GBUF * 2)               // bytes

template <int EPI>
__global__ __launch_bounds__(128, 2) void gemm2(
    const __half* __restrict__ A, int K,
    const __half* __restrict__ Bw, int ldb,
    __half* __restrict__ C, int ldc, int nguard, int fpn,
    const float* __restrict__ bias,
    const float* __restrict__ x, float* __restrict__ part) {
    extern __shared__ __align__(16) __half gsm[];
    const int tid = threadIdx.x;
    const int w = tid >> 5, lane = tid & 31;
    const int grp = lane >> 2, tig = lane & 3;

    float acc[4][8][4];
#pragma unroll
    for (int mt = 0; mt < 4; mt++)
#pragma unroll
        for (int nt = 0; nt < 8; nt++)
#pragma unroll
            for (int i = 0; i < 4; i++) acc[mt][nt][i] = 0.f;

    const size_t mBase = (size_t)blockIdx.y * 256;
    const int nBase = blockIdx.x * 64;

    const int aRow = w * 64 + (lane & 15);
    const int aCol = (lane >> 4) * 8;
    const int bRow = (lane & 7) + ((lane >> 4) & 1) * 8;
    const int bCol = ((lane >> 3) & 1) * 8;

    const int KT = K / 48;

    auto issue = [&](int buf, int k0) {
        __half* As = gsm + buf * GBUF;
        __half* Bs = As + 256 * 56;
#pragma unroll
        for (int i = 0; i < 12; i++) {
            int q = tid + i * 128;
            int row = q / 6, off = (q - row * 6) * 8;
            cp16(As + row * 56 + off, A + (mBase + row) * K + k0 + off);
        }
#pragma unroll
        for (int i = 0; i < 3; i++) {
            int q = tid + i * 128;
            int n = q / 6, off = (q - n * 6) * 8;
            cp16(Bs + n * 56 + off, Bw + (size_t)(nBase + n) * ldb + k0 + off);
        }
        cp_commit();
    };

    issue(0, 0);
    for (int kt = 0; kt < KT; kt++) {
        int cur = kt & 1;
        if (kt + 1 < KT) issue(cur ^ 1, (kt + 1) * 48);
        if (kt + 1 < KT) cp_wait<1>(); else cp_wait<0>();
        __syncthreads();
        __half* As = gsm + cur * GBUF;
        __half* Bs = As + 256 * 56;
#pragma unroll
        for (int kc = 0; kc < 3; kc++) {
            uint32_t a[4][4], b[4][4];
#pragma unroll
            for (int mt = 0; mt < 4; mt++)
                ldm_x4(a[mt][0], a[mt][1], a[mt][2], a[mt][3],
                       As + (aRow + mt * 16) * 56 + kc * 16 + aCol);
#pragma unroll
            for (int g = 0; g < 4; g++)
                ldm_x4(b[g][0], b[g][1], b[g][2], b[g][3],
                       Bs + (bRow + g * 16) * 56 + kc * 16 + bCol);
#pragma unroll
            for (int mt = 0; mt < 4; mt++)
#pragma unroll
                for (int g = 0; g < 4; g++) {
                    MMA16(acc[mt][2*g][0], acc[mt][2*g][1], acc[mt][2*g][2], acc[mt][2*g][3],
                          a[mt][0], a[mt][1], a[mt][2], a[mt][3], b[g][0], b[g][1]);
                    MMA16(acc[mt][2*g+1][0], acc[mt][2*g+1][1], acc[mt][2*g+1][2], acc[mt][2*g+1][3],
                          a[mt][0], a[mt][1], a[mt][2], a[mt][3], b[g][2], b[g][3]);
                }
        }
        __syncthreads();
    }

    if (EPI == 0) {
        // fragment-packed Xpre store: coalesced 128B per half-tile
        const int t = (int)(mBase / BB);
        const size_t rowb = (mBase - (size_t)t * BB) + w * 64;
#pragma unroll
        for (int mt = 0; mt < 4; mt++) {
            const int tile_m = (int)((rowb + mt * 16) >> 4);
#pragma unroll
            for (int nt = 0; nt < 8; nt++) {
                const int tile_n = (nBase + nt * 8) >> 3;
                float* a = acc[mt][nt];
                __half* bp = C + (((size_t)t * 72 + tile_n) * 256 + tile_m) * 128 + 2 * lane;
                *(__half2*)bp = __floats2half2_rn(a[0], a[1]);
                *(__half2*)(bp + 64) = __floats2half2_rn(a[2], a[3]);
            }
        }
    } else if (EPI == 2) {
#pragma unroll
        for (int mt = 0; mt < 4; mt++)
#pragma unroll
            for (int nt = 0; nt < 8; nt++) {
                int colg = nBase + nt * 8 + 2 * tig;
                if (colg >= nguard) continue;
                float* a = acc[mt][nt];
                size_t row0 = mBase + w * 64 + mt * 16 + grp;
                int f = colg % fpn;
                float bx = bias[f], by = bias[f + 1];
                *(__half2*)(C + row0 * ldc + colg) =
                    __floats2half2_rn(felu(a[0] + bx), felu(a[1] + by));
                *(__half2*)(C + (row0 + 8) * ldc + colg) =
                    __floats2half2_rn(felu(a[2] + bx), felu(a[3] + by));
            }
    } else if (EPI == 3) {
#pragma unroll
        for (int mt = 0; mt < 4; mt++)
#pragma unroll
            for (int nt = 0; nt < 8; nt++) {
                int colg = nBase + nt * 8 + 2 * tig;
                int f = colg & 15;
                if (f >= 12) continue;
                int i = colg >> 4;
                int oc = i * 12 + f;
                float* a = acc[mt][nt];
                size_t row0 = mBase + w * 64 + mt * 16 + grp;
                float bx = bias[f], by = bias[f + 1];
                *(__half2*)(C + row0 * 144 + oc) =
                    __floats2half2_rn(felu(a[0] + bx), felu(a[1] + by));
                *(__half2*)(C + (row0 + 8) * 144 + oc) =
                    __floats2half2_rn(felu(a[2] + bx), felu(a[3] + by));
            }
    } else {  // EPI 1: FC + MSE partials
        float s[4][2];
#pragma unroll
        for (int mt = 0; mt < 4; mt++) { s[mt][0] = 0.f; s[mt][1] = 0.f; }
#pragma unroll
        for (int mt = 0; mt < 4; mt++)
#pragma unroll
            for (int nt = 0; nt < 8; nt++) {
                int colg = nBase + nt * 8 + 2 * tig;
                if (colg >= 264) continue;
                float* a = acc[mt][nt];
                size_t row0 = mBase + w * 64 + mt * 16 + grp;
                float bx = bias[colg], by = bias[colg + 1];
                float v0 = a[0] + bx, v1 = a[1] + by, v2 = a[2] + bx, v3 = a[3] + by;
                v0 = v0 >= 0.f ? v0 : 0.01f * v0;
                v1 = v1 >= 0.f ? v1 : 0.01f * v1;
                v2 = v2 >= 0.f ? v2 : 0.01f * v2;
                v3 = v3 >= 0.f ? v3 : 0.01f * v3;
                float2 xa = *(const float2*)(x + row0 * 264 + colg);
                float2 xb = *(const float2*)(x + (row0 + 8) * 264 + colg);
                float d0 = xa.x - v0, d1 = xa.y - v1, d2 = xb.x - v2, d3 = xb.y - v3;
                s[mt][0] += d0 * d0 + d1 * d1;
                s[mt][1] += d2 * d2 + d3 * d3;
            }
#pragma unroll
        for (int mt = 0; mt < 4; mt++) {
            size_t row0 = mBase + w * 64 + mt * 16 + grp;
            float v0 = s[mt][0], v1 = s[mt][1];
            v0 += __shfl_xor_sync(0xffffffffu, v0, 1);
            v0 += __shfl_xor_sync(0xffffffffu, v0, 2);
            v1 += __shfl_xor_sync(0xffffffffu, v1, 1);
            v1 += __shfl_xor_sync(0xffffffffu, v1, 2);
            if (tig == 0) {
                part[(size_t)blockIdx.x * NB + row0] = v0;
                part[(size_t)blockIdx.x * NB + row0 + 8] = v1;
            }
        }
    }
}

__global__ void mse_final(const float* __restrict__ part, float* __restrict__ out) {
    int idx = blockIdx.x * 256 + threadIdx.x;
    if (idx >= NB) return;
    float s = 0.f;
#pragma unroll
    for (int k = 0; k < 5; k++) s += part[(size_t)k * NB + idx];
    out[idx] = s * (1.f / 264.f);
}

// ---------------------------------------------------------------------------
// Persistent LSTM chain. Xpre read in fragment-packed layout (coalesced);
// y written via staged smem copy (coalesced STG.128); enc-final-only mode
// when yStride == 0 (writes only t = 23).
// ---------------------------------------------------------------------------
#define CHAIN_SMEM (576 * WPAD * 2 + 2 * 32 * WPAD * 2 + 32 * 144 * 4 + 576 * 4)

__global__ __launch_bounds__(256, 1) void lstm_chain(
    const __half* __restrict__ W16, const float* __restrict__ bias,
    const __half* __restrict__ xpre, const __half* __restrict__ hInit,
    __half* __restrict__ y, size_t yStride) {
    extern __shared__ __align__(16) unsigned char smem_raw[];
    __half* Ws  = (__half*)smem_raw;
    __half* h0s = Ws + 576 * WPAD;
    __half* h1s = h0s + 32 * WPAD;
    float*  cs  = (float*)(h1s + 32 * WPAD);
    float*  bs  = cs + 32 * 144;

    const int tid = threadIdx.x;
    const int w = tid >> 5, lane = tid & 31;
    const int warpM = w >> 2, warpN = w & 3;
    const int grp = lane >> 2, tig = lane & 3;
    const size_t gRowBase = (size_t)blockIdx.x * 32;

    {
        const uint4* src = (const uint4*)W16;
        uint4* dst = (uint4*)Ws;
        for (int i = tid; i < 576 * WPAD / 8; i += 256) dst[i] = src[i];
    }
    for (int i = tid; i < 32 * WPAD; i += 256) { h0s[i] = __half(0.f); h1s[i] = __half(0.f); }
    for (int i = tid; i < 32 * 144; i += 256) cs[i] = 0.f;
    for (int i = tid; i < 576; i += 256) bs[i] = bias[i];
    __syncthreads();
    if (hInit) {
        for (int i = tid; i < 32 * 144; i += 256) {
            int r = i / 144, j = i - r * 144;
            h0s[r * WPAD + j] = hInit[(gRowBase + r) * 144 + j];
        }
        __syncthreads();
    }

    const int row0 = warpM * 16 + grp;
    const int aRow = warpM * 16 + (lane & 15);
    const int aCol = (lane >> 4) * 8;
    const int bRowBase = warpN * 144 + (lane & 7) + ((lane >> 4) & 1) * 8;
    const int bCol = ((lane >> 3) & 1) * 8;
    const int myRow = (tig & 1) ? row0 + 8 : row0;
    const int tile_m = blockIdx.x * 2 + warpM;

    int p = 0;
    for (int t = 0; t < PERIOD; t++) {
        const __half* hc = p ? h1s : h0s;
        __half* hn = p ? h0s : h1s;
        const __half* xslice = xpre ? (xpre + (size_t)t * BB * 576) : nullptr;

        uint32_t Areg[9][4];
#pragma unroll
        for (int kc = 0; kc < 9; kc++)
            ldm_x4(Areg[kc][0], Areg[kc][1], Areg[kc][2], Areg[kc][3],
                   hc + aRow * WPAD + kc * 16 + aCol);

#pragma unroll
        for (int np = 0; np < 9; np++) {
            float d[2][4];
#pragma unroll
            for (int u = 0; u < 2; u++)
#pragma unroll
                for (int i = 0; i < 4; i++) d[u][i] = 0.f;
            const __half* wb = Ws + (bRowBase + np * 16) * WPAD + bCol;
#pragma unroll
            for (int kc = 0; kc < 9; kc++) {
                uint32_t b0, b1, b2, b3;
                ldm_x4(b0, b1, b2, b3, wb + kc * 16);
                MMA16(d[0][0], d[0][1], d[0][2], d[0][3],
                      Areg[kc][0], Areg[kc][1], Areg[kc][2], Areg[kc][3], b0, b1);
                MMA16(d[1][0], d[1][1], d[1][2], d[1][3],
                      Areg[kc][0], Areg[kc][1], Areg[kc][2], Areg[kc][3], b2, b3);
            }
#pragma unroll
            for (int u = 0; u < 2; u++) {
                int colg = warpN * 144 + (2 * np + u) * 8 + 2 * tig;
                float v0 = d[u][0] + bs[colg], v1 = d[u][1] + bs[colg + 1];
                float v2 = d[u][2] + bs[colg], v3 = d[u][3] + bs[colg + 1];
                if (xslice) {
                    // fragment-packed tile read (coalesced)
                    int tile_n = warpN * 18 + 2 * np + u;
                    const __half* tb = xslice +
                        (((size_t)tile_n) * 256 + tile_m) * 128 + 2 * lane;
                    __half2 x01 = *(const __half2*)tb;
                    __half2 x23 = *(const __half2*)(tb + 64);
                    v0 += __half2float(x01.x); v1 += __half2float(x01.y);
                    v2 += __half2float(x23.x); v3 += __half2float(x23.y);
                }
                float t0 = __shfl_xor_sync(0xffffffffu, v0, 1);
                float t1 = __shfl_xor_sync(0xffffffffu, v1, 1);
                float t2 = __shfl_xor_sync(0xffffffffu, v2, 1);
                float t3 = __shfl_xor_sync(0xffffffffu, v3, 1);
                float gi = (tig & 1) ? t2 : v0;
                float gf = (tig & 1) ? t3 : v1;
                float gg = (tig & 1) ? v2 : t0;
                float go = (tig & 1) ? v3 : t1;
                int j = colg >> 2;
                float c = cs[myRow * 144 + j];
                float c2 = sigm(gf) * c + sigm(gi) * tanha(gg);
                float h2 = sigm(go) * tanha(c2);
                cs[myRow * 144 + j] = c2;
                hn[myRow * WPAD + j] = __float2half(h2);
            }
        }
        __syncthreads();
        // staged coalesced y write (STG.128); enc-final mode writes only t=23
        if (yStride != 0 || t == PERIOD - 1) {
            __half* yslice = y + (size_t)t * yStride;
            for (int i = tid; i < 32 * 18; i += 256) {
                int r = i / 18, q = i - r * 18;
                *(uint4*)(yslice + (gRowBase + r) * 144 + q * 8) =
                    *(const uint4*)(hn + r * WPAD + q * 8);
            }
        }
        p ^= 1;
    }
}

// ---------------------------------------------------------------------------
// Host orchestration
// ---------------------------------------------------------------------------
extern "C" void kernel_launch(void* const* d_in, const int* in_sizes, int n_in,
                              void* d_out, int out_size) {
    const float* x     = (const float*)d_in[0];
    const float* gW0   = (const float*)d_in[1];
    const float* gb0   = (const float*)d_in[2];
    const float* ga0   = (const float*)d_in[3];
    const float* gW1   = (const float*)d_in[4];
    const float* gb1   = (const float*)d_in[5];
    const float* ga1   = (const float*)d_in[6];
    const float* eWih0 = (const float*)d_in[7];
    const float* eWhh0 = (const float*)d_in[8];
    const float* ebih0 = (const float*)d_in[9];
    const float* ebhh0 = (const float*)d_in[10];
    const float* eWih1 = (const float*)d_in[11];
    const float* eWhh1 = (const float*)d_in[12];
    const float* ebih1 = (const float*)d_in[13];
    const float* ebhh1 = (const float*)d_in[14];
    const float* dWhh0 = (const float*)d_in[16];
    const float* dbih0 = (const float*)d_in[17];
    const float* dbhh0 = (const float*)d_in[18];
    const float* dWih1 = (const float*)d_in[19];
    const float* dWhh1 = (const float*)d_in[20];
    const float* dbih1 = (const float*)d_in[21];
    const float* dbhh1 = (const float*)d_in[22];
    const float* gW3   = (const float*)d_in[23];
    const float* gb3   = (const float*)d_in[24];
    const float* ga3   = (const float*)d_in[25];
    const float* gW4   = (const float*)d_in[26];
    const float* gb4   = (const float*)d_in[27];
    const float* ga4   = (const float*)d_in[28];
    const float* fW    = (const float*)d_in[29];
    const float* fb    = (const float*)d_in[30];

    float* S = nullptr;
    cudaGetSymbolAddress((void**)&S, g_scratch);

    __half* x16     = (__half*)(S + OFF_X16);
    __half* out1    = (__half*)(S + OFF_OUT1);
    __half* h2_16   = (__half*)(S + OFF_H2);
    __half* Xpre16  = (__half*)(S + OFF_XPRE);
    __half* y0_16   = (__half*)(S + OFF_Y0);
    __half* yd0_16  = (__half*)(S + OFF_YD0);
    __half* yd1_16  = (__half*)(S + OFF_YD1);
    __half* o3_16   = (__half*)(S + OFF_O3);
    __half* h4_16   = (__half*)(S + OFF_H4);
    __half* enc1_16 = (__half*)(S + OFF_ENC1);
    float*  part    = S + OFF_PART;
    float*  probs   = S + OFF_PROBS;
    __half* Mb      = (__half*)(S + OFF_M);
    __half* w16     = (__half*)(S + OFF_W16);
    float*  br      = S + OFF_BR;
    __half* fw16    = (__half*)(S + OFF_FW16);

    __half* M1 = Mb;
    __half* M2 = M1 + 192 * 288;
    __half* M3 = M2 + 192 * 192;
    __half* M4 = M3 + 192 * 144;

    const size_t WSLICE = (size_t)576 * WPAD;
    __half* w_eWih0 = w16 + 0 * WSLICE;
    __half* w_eWhh0 = w16 + 1 * WSLICE;
    __half* w_eWih1 = w16 + 2 * WSLICE;
    __half* w_eWhh1 = w16 + 3 * WSLICE;
    __half* w_dWhh0 = w16 + 4 * WSLICE;
    __half* w_dWih1 = w16 + 5 * WSLICE;
    __half* w_dWhh1 = w16 + 6 * WSLICE;

    cudaFuncSetAttribute(lstm_chain, cudaFuncAttributeMaxDynamicSharedMemorySize,
                         CHAIN_SMEM);
    cudaFuncSetAttribute(gemm2<0>, cudaFuncAttributeMaxDynamicSharedMemorySize, GSMEM);
    cudaFuncSetAttribute(gemm2<1>, cudaFuncAttributeMaxDynamicSharedMemorySize, GSMEM);
    cudaFuncSetAttribute(gemm2<2>, cudaFuncAttributeMaxDynamicSharedMemorySize, GSMEM);
    cudaFuncSetAttribute(gemm2<3>, cudaFuncAttributeMaxDynamicSharedMemorySize, GSMEM);

    PrepArgs pa;
    pa.wsrc[0] = eWih0; pa.wsrc[1] = eWhh0; pa.wsrc[2] = eWih1; pa.wsrc[3] = eWhh1;
    pa.wsrc[4] = dWhh0; pa.wsrc[5] = dWih1; pa.wsrc[6] = dWhh1;
    pa.bih[0] = ebih0; pa.bih[1] = ebih1; pa.bih[2] = dbih0; pa.bih[3] = dbih1;
    pa.bhh[0] = ebhh0; pa.bhh[1] = ebhh1; pa.bhh[2] = dbhh0; pa.bhh[3] = dbhh1;
    pa.fW = fW;
    prep_all<<<(PREP_TOT + 255) / 256, 256>>>(pa, w16, br, fw16);
    convert_x<<<(int)(((size_t)NB * 288 + 255) / 256), 256>>>(x, x16);

    // ---- GAT 1+2 as GEMMs ----
    attn_pair<22, 16, 16, 12, false><<<1, 128>>>(x, gW0, gb0, ga0, gW1, gb1, ga1,
                                                 probs, probs + 576);
    build_M<<<(192 * 288 + 255) / 256, 256>>>(probs, gW0, M1, 192, 288, 16, 16, 24, 22);
    build_M<<<(192 * 192 + 255) / 256, 256>>>(probs + 576, gW1, M2, 192, 192, 16, 12, 16, 16);
    gemm2<2><<<dim3(3, NB / 256), 128, GSMEM>>>(x16, 288, M1, 288, out1, 192, 192, 16,
                                                gb0, nullptr, nullptr);
    gemm2<3><<<dim3(3, NB / 256), 128, GSMEM>>>(out1, 192, M2, 192, h2_16, 144, 192, 16,
                                                gb1, nullptr, nullptr);

    // ---- Encoder layer 0 ----
    gemm2<0><<<dim3(9, NB / 256), 128, GSMEM>>>(h2_16, 144, w_eWih0, WPAD, Xpre16, 0,
                                                0, 0, nullptr, nullptr, nullptr);
    lstm_chain<<<BB / 32, 256, CHAIN_SMEM>>>(w_eWhh0, br + 0, Xpre16, nullptr,
                                             y0_16, (size_t)BB * 144);
    // ---- Encoder layer 1 (final h only) ----
    gemm2<0><<<dim3(9, NB / 256), 128, GSMEM>>>(y0_16, 144, w_eWih1, WPAD, Xpre16, 0,
                                                0, 0, nullptr, nullptr, nullptr);
    lstm_chain<<<BB / 32, 256, CHAIN_SMEM>>>(w_eWhh1, br + 576, Xpre16, nullptr,
                                             enc1_16, 0);
    // ---- Decoder layer 0 (zero inputs; h0 = enc0 final = y0[t=23]) ----
    lstm_chain<<<BB / 32, 256, CHAIN_SMEM>>>(w_dWhh0, br + 1152, nullptr,
                                             y0_16 + (size_t)23 * BB * 144,
                                             yd0_16, (size_t)BB * 144);
    // ---- Decoder layer 1 (h0 = enc1 final) ----
    gemm2<0><<<dim3(9, NB / 256), 128, GSMEM>>>(yd0_16, 144, w_dWih1, WPAD, Xpre16, 0,
                                                0, 0, nullptr, nullptr, nullptr);
    lstm_chain<<<BB / 32, 256, CHAIN_SMEM>>>(w_dWhh1, br + 1728, Xpre16, enc1_16,
                                             yd1_16, (size_t)BB * 144);

    // ---- GAT 3+4 as GEMMs ----
    attn_pair<12, 16, 16, 24, true><<<1, 128>>>(yd1_16, gW3, gb3, ga3, gW4, gb4, ga4,
                                                probs + 1152, probs + 1728);
    build_M<<<(192 * 144 + 255) / 256, 256>>>(probs + 1152, gW3, M3, 192, 144, 16, 16, 12, 12);
    build_M<<<(320 * 192 + 255) / 256, 256>>>(probs + 1728, gW4, M4, 320, 192, 24, 24, 16, 16);
    gemm2<2><<<dim3(3, NB / 256), 128, GSMEM>>>(yd1_16, 144, M3, 144, o3_16, 192, 192, 16,
                                                gb3, nullptr, nullptr);
    gemm2<2><<<dim3(5, NB / 256), 128, GSMEM>>>(o3_16, 192, M4, 192, h4_16, 288, 288, 24,
                                                gb4, nullptr, nullptr);

    // ---- FC + leaky + MSE ----
    gemm2<1><<<dim3(5, NB / 256), 128, GSMEM>>>(h4_16, 288, fw16, 288, nullptr, 0, 0, 0,
                                                fb, x, part);
    mse_final<<<(NB + 255) / 256, 256>>>(part, (float*)d_out);
}

// round 14
// speedup vs baseline: 4.4149x; 1.2551x over previous
#include <cuda_runtime.h>
#include <cuda_fp16.h>
#include <cstdint>
#include <cstddef>

// ---------------------------------------------------------------------------
// Problem constants
// ---------------------------------------------------------------------------
#define NB      98304
#define PERIOD  24
#define BB      (NB / PERIOD)     // 4096
#define WPAD    152               // padded K stride (halves) for LSTM weights

__constant__ int c_EI[44] = {0,0,0,0, 1,1,1, 2,2,2, 3,3, 4,4, 5,5,5, 6,6,6,6,
                             7,7,7, 8,8,8,8, 9,9,9,9, 10,10,10,10,10,10,10,
                             11,11,11,11,11};
__constant__ int c_EJ[44] = {0,5,10,11, 1,7,10, 2,6,11, 3,6, 4,5, 0,4,5,
                             2,3,6,10, 1,7,9, 8,9,10,11, 7,8,9,10,
                             0,1,6,8,9,10,11, 0,2,8,10,11};
__constant__ int c_RS[13] = {0,4,7,10,12,14,17,21,24,28,32,39,44};

// ---------------------------------------------------------------------------
// Scratch layout (float units)
// ---------------------------------------------------------------------------
#define OFF_X16   ((size_t)0)                        // fp16 [NB][288]
#define OFF_OUT1  (OFF_X16  + (size_t)NB * 144)      // fp16 [NB][192]
#define OFF_H2    (OFF_OUT1 + (size_t)NB * 96)       // fp16 [NB][144]
#define OFF_XPRE  (OFF_H2   + (size_t)NB * 72)       // fp16 [24][72][256][128] tiles
#define OFF_Y0    (OFF_XPRE + (size_t)NB * 288)      // fp16 [24][BB][144]
#define OFF_YD0   (OFF_Y0   + (size_t)NB * 72)
#define OFF_YD1   (OFF_YD0  + (size_t)NB * 72)
#define OFF_O3    (OFF_YD1  + (size_t)NB * 72)       // fp16 [NB][192]
#define OFF_H4    (OFF_O3   + (size_t)NB * 96)       // fp16 [NB][288]
#define OFF_ENC1  (OFF_H4   + (size_t)NB * 144)      // fp16 [BB][144]
#define OFF_PART  (OFF_ENC1 + (size_t)BB * 72)       // fp32 [5][NB]
#define OFF_PROBS (OFF_PART + (size_t)5 * NB)        // fp32 4*576
#define OFF_M     (OFF_PROBS + 2304)                 // fp16 M1..M4
#define SZ_M      ((192*288 + 192*192 + 192*144 + 320*192) / 2)
#define OFF_W16   (OFF_M + SZ_M)
#define OFF_BR    (OFF_W16 + (size_t)7 * 576 * WPAD / 2)
#define OFF_FW16  (OFF_BR + 4 * 576)
#define SCRATCH_TOTAL (OFF_FW16 + (size_t)320 * 288 / 2)

__device__ __align__(128) float g_scratch[SCRATCH_TOTAL];

__device__ __forceinline__ float tanha(float x) {
    float y;
    asm("tanh.approx.f32 %0, %1;" : "=f"(y) : "f"(x));
    return y;
}
__device__ __forceinline__ float sigm(float x) { return fmaf(tanha(0.5f * x), 0.5f, 0.5f); }
__device__ __forceinline__ float felu(float x) { return x > 0.f ? x : (__expf(x) - 1.f); }

__device__ __forceinline__ uint32_t smem_u32(const void* p) {
    return (uint32_t)__cvta_generic_to_shared(p);
}
__device__ __forceinline__ void ldm_x4(uint32_t& r0, uint32_t& r1, uint32_t& r2,
                                       uint32_t& r3, const void* p) {
    asm volatile("ldmatrix.sync.aligned.m8n8.x4.shared.b16 {%0,%1,%2,%3}, [%4];"
                 : "=r"(r0), "=r"(r1), "=r"(r2), "=r"(r3) : "r"(smem_u32(p)));
}
__device__ __forceinline__ void cp16(void* dst, const void* src) {
    asm volatile("cp.async.cg.shared.global [%0], [%1], 16;"
                 :: "r"(smem_u32(dst)), "l"(src));
}
__device__ __forceinline__ void cp_commit() {
    asm volatile("cp.async.commit_group;");
}
template <int N>
__device__ __forceinline__ void cp_wait() {
    asm volatile("cp.async.wait_group %0;" :: "n"(N));
}
#define MMA16(d0,d1,d2,d3,a0,a1,a2,a3,b0,b1)                                    \
    asm volatile("mma.sync.aligned.m16n8k16.row.col.f32.f16.f16.f32 "           \
                 "{%0,%1,%2,%3}, {%4,%5,%6,%7}, {%8,%9}, {%0,%1,%2,%3};"        \
                 : "+f"(d0), "+f"(d1), "+f"(d2), "+f"(d3)                       \
                 : "r"(a0), "r"(a1), "r"(a2), "r"(a3), "r"(b0), "r"(b1))

// ---------------------------------------------------------------------------
// Gate-pair column mapping: global col n in [0,576) -> (unit j, gate g).
// Per 144-col warp span: first 72 cols = (i,f) pairs of units u=0..35,
// next 72 cols = (g,o) pairs of the same units. j = warp*36 + u.
// ---------------------------------------------------------------------------
__device__ __forceinline__ void col_to_jg(int n, int& j, int& g) {
    int warp = n / 144, r = n - warp * 144;
    int half = r / 72, rr = r - half * 72;
    int u = rr >> 1, b = rr & 1;
    g = half * 2 + b;
    j = warp * 36 + u;
}

// ---------------------------------------------------------------------------
// Prep kernels
// ---------------------------------------------------------------------------
struct PrepArgs {
    const float* wsrc[7];
    const float* bih[4];
    const float* bhh[4];
    const float* fW;
};
#define PREP_W  (7 * 576 * WPAD)
#define PREP_B  (4 * 576)
#define PREP_F  (320 * 288)
#define PREP_TOT (PREP_W + PREP_B + PREP_F)

__global__ void prep_all(PrepArgs args, __half* w16, float* br, __half* fw16) {
    for (size_t idx = blockIdx.x * 256 + threadIdx.x; idx < PREP_TOT;
         idx += (size_t)gridDim.x * 256) {
        if (idx < PREP_W) {
            size_t m = idx / (576 * WPAD);
            int r = (int)(idx - m * (576 * WPAD));
            int np = r / WPAD, k = r - np * WPAD;
            int j, g;
            col_to_jg(np, j, g);
            w16[idx] = (k < 144)
                ? __float2half(args.wsrc[m][(g * 144 + j) * 144 + k]) : __half(0.f);
        } else if (idx < PREP_W + PREP_B) {
            int e = (int)(idx - PREP_W);
            int b = e / 576, np = e - b * 576;
            int j, g;
            col_to_jg(np, j, g);
            br[e] = args.bih[b][g * 144 + j] + args.bhh[b][g * 144 + j];
        } else {
            int e = (int)(idx - PREP_W - PREP_B);
            int n = e / 288, k = e - n * 288;
            fw16[e] = (n < 264) ? __float2half(args.fW[k * 264 + n]) : __half(0.f);
        }
    }
}

// x fp32 [NB,12,22] -> x16 fp16 [NB, 12*24] zero-padded
__global__ void convert_x(const float* __restrict__ x, __half* __restrict__ x16) {
    size_t idx = (size_t)blockIdx.x * 256 + threadIdx.x;
    if (idx >= (size_t)NB * 288) return;
    size_t b = idx / 288;
    int r = (int)(idx - b * 288);
    int j = r / 24, k = r - j * 24;
    x16[idx] = (k < 22) ? __float2half(x[b * 264 + j * 22 + k]) : __half(0.f);
}

// Build combined GAT matrix: M^T[n=(i,f)][kk=(j,k)] = P[i,j,h(f)] * W[k,f]
__global__ void build_M(const float* __restrict__ P, const float* __restrict__ W,
                        __half* __restrict__ M, int Nrows, int K,
                        int FPNP, int FV, int KP, int KV) {
    int idx = blockIdx.x * 256 + threadIdx.x;
    if (idx >= Nrows * K) return;
    int n = idx / K, kk = idx - n * K;
    int i = n / FPNP, f = n - i * FPNP;
    int j = kk / KP, k = kk - j * KP;
    float v = 0.f;
    if (f < FV && k < KV && i < 12) {
        int cs = FV >> 2;
        int h = f / cs;
        v = P[(i * 4 + h) * 12 + j] * W[k * FV + f];
    }
    M[idx] = __float2half(v);
}

// ---------------------------------------------------------------------------
// Attention probs for a PAIR of GAT layers (sample 0 only)
// ---------------------------------------------------------------------------
template <int CI1, int CO1, int CI2, int CO2, bool HALFIN>
__global__ void attn_pair(const void* xin,
                          const float* W1, const float* b1, const float* a1,
                          const float* W2, const float* b2, const float* a2,
                          float* probs1, float* probs2) {
    constexpr int CS1 = CO1 / 4, CS2 = CO2 / 4;
    __shared__ float x0[12 * CI1];
    __shared__ float feat[12 * CO1];
    __shared__ float lg[44 * 4];
    __shared__ float h1s[12 * CI2];
    __shared__ float feat2[12 * CO2];
    int tid = threadIdx.x;

    for (int i = tid; i < 12 * CI1; i += 128)
        x0[i] = HALFIN ? __half2float(((const __half*)xin)[i]) : ((const float*)xin)[i];
    __syncthreads();
    for (int idx = tid; idx < 12 * CO1; idx += 128) {
        int i = idx / CO1, f = idx - i * CO1;
        float acc = b1[f];
        for (int k = 0; k < CI1; k++) acc += x0[i * CI1 + k] * W1[k * CO1 + f];
        feat[idx] = acc;
    }
    __syncthreads();
    for (int idx = tid; idx < 176; idx += 128) {
        int e = idx >> 2, h = idx & 3;
        const float* ah = a1 + h * 2 * CS1;
        float s = 0.f;
        for (int c = 0; c < CS1; c++)
            s += ah[c] * feat[c_EI[e] * CO1 + h * CS1 + c] +
                 ah[CS1 + c] * feat[c_EJ[e] * CO1 + h * CS1 + c];
        lg[idx] = s > 0.f ? s : 0.2f * s;
    }
    __syncthreads();
    for (int idx = tid; idx < 48; idx += 128) {
        int i = idx >> 2, h = idx & 3;
        int s0 = c_RS[i], s1 = c_RS[i + 1];
        float m = -3.4e38f;
        for (int e = s0; e < s1; e++) m = fmaxf(m, lg[e * 4 + h]);
        float sum = 0.f;
        for (int e = s0; e < s1; e++) sum += expf(lg[e * 4 + h] - m);
        float* pr = probs1 + (i * 4 + h) * 12;
        for (int j = 0; j < 12; j++) pr[j] = 0.f;
        for (int e = s0; e < s1; e++) pr[c_EJ[e]] = expf(lg[e * 4 + h] - m) / sum;
    }
    __syncthreads();
    for (int idx = tid; idx < 12 * CO1; idx += 128) {
        int i = idx / CO1, f = idx - i * CO1;
        int h = f / CS1;
        const float* pr = probs1 + (i * 4 + h) * 12;
        float acc = 0.f;
        for (int j = 0; j < 12; j++) acc += pr[j] * feat[j * CO1 + f];
        h1s[idx] = acc > 0.f ? acc : expm1f(acc);
    }
    __syncthreads();
    for (int idx = tid; idx < 12 * CO2; idx += 128) {
        int i = idx / CO2, f = idx - i * CO2;
        float acc = b2[f];
        for (int k = 0; k < CI2; k++) acc += h1s[i * CI2 + k] * W2[k * CO2 + f];
        feat2[idx] = acc;
    }
    __syncthreads();
    for (int idx = tid; idx < 176; idx += 128) {
        int e = idx >> 2, h = idx & 3;
        const float* ah = a2 + h * 2 * CS2;
        float s = 0.f;
        for (int c = 0; c < CS2; c++)
            s += ah[c] * feat2[c_EI[e] * CO2 + h * CS2 + c] +
                 ah[CS2 + c] * feat2[c_EJ[e] * CO2 + h * CS2 + c];
        lg[idx] = s > 0.f ? s : 0.2f * s;
    }
    __syncthreads();
    for (int idx = tid; idx < 48; idx += 128) {
        int i = idx >> 2, h = idx & 3;
        int s0 = c_RS[i], s1 = c_RS[i + 1];
        float m = -3.4e38f;
        for (int e = s0; e < s1; e++) m = fmaxf(m, lg[e * 4 + h]);
        float sum = 0.f;
        for (int e = s0; e < s1; e++) sum += expf(lg[e * 4 + h] - m);
        float* pr = probs2 + (i * 4 + h) * 12;
        for (int j = 0; j < 12; j++) pr[j] = 0.f;
        for (int e = s0; e < s1; e++) pr[c_EJ[e]] = expf(lg[e * 4 + h] - m) / sum;
    }
}

// ---------------------------------------------------------------------------
// Unified fp16 GEMM, double-buffered cp.async pipeline.
// Tile 256x64, 128 threads = 4 warps, warp tile 64x64.
//  EPI 0: fragment-packed Xpre store: [t][tile_n=72][tile_m=256][128]
//  EPI 1: FC: +bias, leaky_relu, (x16-v)^2 row partials
//  EPI 2: ELU + fp16 store stride ldc, col guard nguard, bias idx colg%fpn
//  EPI 3: GAT2 remap: i=colg>>4, f=colg&15 (<12), store col i*12+f, stride 144
// ---------------------------------------------------------------------------
#define GBUF (256 * 56 + 64 * 56)          // halves per buffer
#define GSMEM (2 * GBUF * 2)               // bytes

template <int EPI>
__global__ __launch_bounds__(128, 2) void gemm2(
    const __half* __restrict__ A, int K,
    const __half* __restrict__ Bw, int ldb,
    __half* __restrict__ C, int ldc, int nguard, int fpn,
    const float* __restrict__ bias,
    const __half* __restrict__ x16, float* __restrict__ part) {
    extern __shared__ __align__(16) __half gsm[];
    const int tid = threadIdx.x;
    const int w = tid >> 5, lane = tid & 31;
    const int grp = lane >> 2, tig = lane & 3;

    float acc[4][8][4];
#pragma unroll
    for (int mt = 0; mt < 4; mt++)
#pragma unroll
        for (int nt = 0; nt < 8; nt++)
#pragma unroll
            for (int i = 0; i < 4; i++) acc[mt][nt][i] = 0.f;

    const size_t mBase = (size_t)blockIdx.y * 256;
    const int nBase = blockIdx.x * 64;

    const int aRow = w * 64 + (lane & 15);
    const int aCol = (lane >> 4) * 8;
    const int bRow = (lane & 7) + ((lane >> 4) & 1) * 8;
    const int bCol = ((lane >> 3) & 1) * 8;

    const int KT = K / 48;

    auto issue = [&](int buf, int k0) {
        __half* As = gsm + buf * GBUF;
        __half* Bs = As + 256 * 56;
#pragma unroll
        for (int i = 0; i < 12; i++) {
            int q = tid + i * 128;
            int row = q / 6, off = (q - row * 6) * 8;
            cp16(As + row * 56 + off, A + (mBase + row) * K + k0 + off);
        }
#pragma unroll
        for (int i = 0; i < 3; i++) {
            int q = tid + i * 128;
            int n = q / 6, off = (q - n * 6) * 8;
            cp16(Bs + n * 56 + off, Bw + (size_t)(nBase + n) * ldb + k0 + off);
        }
        cp_commit();
    };

    issue(0, 0);
    for (int kt = 0; kt < KT; kt++) {
        int cur = kt & 1;
        if (kt + 1 < KT) issue(cur ^ 1, (kt + 1) * 48);
        if (kt + 1 < KT) cp_wait<1>(); else cp_wait<0>();
        __syncthreads();
        __half* As = gsm + cur * GBUF;
        __half* Bs = As + 256 * 56;
#pragma unroll
        for (int kc = 0; kc < 3; kc++) {
            uint32_t a[4][4], b[4][4];
#pragma unroll
            for (int mt = 0; mt < 4; mt++)
                ldm_x4(a[mt][0], a[mt][1], a[mt][2], a[mt][3],
                       As + (aRow + mt * 16) * 56 + kc * 16 + aCol);
#pragma unroll
            for (int g = 0; g < 4; g++)
                ldm_x4(b[g][0], b[g][1], b[g][2], b[g][3],
                       Bs + (bRow + g * 16) * 56 + kc * 16 + bCol);
#pragma unroll
            for (int mt = 0; mt < 4; mt++)
#pragma unroll
                for (int g = 0; g < 4; g++) {
                    MMA16(acc[mt][2*g][0], acc[mt][2*g][1], acc[mt][2*g][2], acc[mt][2*g][3],
                          a[mt][0], a[mt][1], a[mt][2], a[mt][3], b[g][0], b[g][1]);
                    MMA16(acc[mt][2*g+1][0], acc[mt][2*g+1][1], acc[mt][2*g+1][2], acc[mt][2*g+1][3],
                          a[mt][0], a[mt][1], a[mt][2], a[mt][3], b[g][2], b[g][3]);
                }
        }
        __syncthreads();
    }

    if (EPI == 0) {
        // fragment-packed Xpre store: coalesced 128B per half-tile
        const int t = (int)(mBase / BB);
        const size_t rowb = (mBase - (size_t)t * BB) + w * 64;
#pragma unroll
        for (int mt = 0; mt < 4; mt++) {
            const int tile_m = (int)((rowb + mt * 16) >> 4);
#pragma unroll
            for (int nt = 0; nt < 8; nt++) {
                const int tile_n = (nBase + nt * 8) >> 3;
                float* a = acc[mt][nt];
                __half* bp = C + (((size_t)t * 72 + tile_n) * 256 + tile_m) * 128 + 2 * lane;
                *(__half2*)bp = __floats2half2_rn(a[0], a[1]);
                *(__half2*)(bp + 64) = __floats2half2_rn(a[2], a[3]);
            }
        }
    } else if (EPI == 2) {
#pragma unroll
        for (int mt = 0; mt < 4; mt++)
#pragma unroll
            for (int nt = 0; nt < 8; nt++) {
                int colg = nBase + nt * 8 + 2 * tig;
                if (colg >= nguard) continue;
                float* a = acc[mt][nt];
                size_t row0 = mBase + w * 64 + mt * 16 + grp;
                int f = colg % fpn;
                float bx = bias[f], by = bias[f + 1];
                *(__half2*)(C + row0 * ldc + colg) =
                    __floats2half2_rn(felu(a[0] + bx), felu(a[1] + by));
                *(__half2*)(C + (row0 + 8) * ldc + colg) =
                    __floats2half2_rn(felu(a[2] + bx), felu(a[3] + by));
            }
    } else if (EPI == 3) {
#pragma unroll
        for (int mt = 0; mt < 4; mt++)
#pragma unroll
            for (int nt = 0; nt < 8; nt++) {
                int colg = nBase + nt * 8 + 2 * tig;
                int f = colg & 15;
                if (f >= 12) continue;
                int i = colg >> 4;
                int oc = i * 12 + f;
                float* a = acc[mt][nt];
                size_t row0 = mBase + w * 64 + mt * 16 + grp;
                float bx = bias[f], by = bias[f + 1];
                *(__half2*)(C + row0 * 144 + oc) =
                    __floats2half2_rn(felu(a[0] + bx), felu(a[1] + by));
                *(__half2*)(C + (row0 + 8) * 144 + oc) =
                    __floats2half2_rn(felu(a[2] + bx), felu(a[3] + by));
            }
    } else {  // EPI 1: FC + MSE partials (x read from padded fp16 x16)
        float s[4][2];
#pragma unroll
        for (int mt = 0; mt < 4; mt++) { s[mt][0] = 0.f; s[mt][1] = 0.f; }
#pragma unroll
        for (int mt = 0; mt < 4; mt++)
#pragma unroll
            for (int nt = 0; nt < 8; nt++) {
                int colg = nBase + nt * 8 + 2 * tig;
                if (colg >= 264) continue;
                float* a = acc[mt][nt];
                size_t row0 = mBase + w * 64 + mt * 16 + grp;
                int jn = colg / 22, kn = colg - jn * 22;   // padded col (even kn<=20)
                int pc = jn * 24 + kn;
                float bx = bias[colg], by = bias[colg + 1];
                float v0 = a[0] + bx, v1 = a[1] + by, v2 = a[2] + bx, v3 = a[3] + by;
                v0 = v0 >= 0.f ? v0 : 0.01f * v0;
                v1 = v1 >= 0.f ? v1 : 0.01f * v1;
                v2 = v2 >= 0.f ? v2 : 0.01f * v2;
                v3 = v3 >= 0.f ? v3 : 0.01f * v3;
                __half2 xa = *(const __half2*)(x16 + row0 * 288 + pc);
                __half2 xb = *(const __half2*)(x16 + (row0 + 8) * 288 + pc);
                float d0 = __half2float(xa.x) - v0, d1 = __half2float(xa.y) - v1;
                float d2 = __half2float(xb.x) - v2, d3 = __half2float(xb.y) - v3;
                s[mt][0] += d0 * d0 + d1 * d1;
                s[mt][1] += d2 * d2 + d3 * d3;
            }
#pragma unroll
        for (int mt = 0; mt < 4; mt++) {
            size_t row0 = mBase + w * 64 + mt * 16 + grp;
            float v0 = s[mt][0], v1 = s[mt][1];
            v0 += __shfl_xor_sync(0xffffffffu, v0, 1);
            v0 += __shfl_xor_sync(0xffffffffu, v0, 2);
            v1 += __shfl_xor_sync(0xffffffffu, v1, 1);
            v1 += __shfl_xor_sync(0xffffffffu, v1, 2);
            if (tig == 0) {
                part[(size_t)blockIdx.x * NB + row0] = v0;
                part[(size_t)blockIdx.x * NB + row0 + 8] = v1;
            }
        }
    }
}

__global__ void mse_final(const float* __restrict__ part, float* __restrict__ out) {
    int idx = blockIdx.x * 256 + threadIdx.x;
    if (idx >= NB) return;
    float s = 0.f;
#pragma unroll
    for (int k = 0; k < 5; k++) s += part[(size_t)k * NB + idx];
    out[idx] = s * (1.f / 264.f);
}

// ---------------------------------------------------------------------------
// Persistent LSTM chain, gate-pair layout: n-tiles 0..8 of each warp = (i,f)
// pairs of units, tiles 9..17 = (g,o) of the same units -> zero shuffles in
// the cell update; cell state c lives in registers (all chains c0 = 0).
// ---------------------------------------------------------------------------
#define CHAIN_SMEM (576 * WPAD * 2 + 2 * 32 * WPAD * 2 + 576 * 4)

__global__ __launch_bounds__(256, 1) void lstm_chain(
    const __half* __restrict__ W16, const float* __restrict__ bias,
    const __half* __restrict__ xpre, const __half* __restrict__ hInit,
    __half* __restrict__ y, size_t yStride) {
    extern __shared__ __align__(16) unsigned char smem_raw[];
    __half* Ws  = (__half*)smem_raw;
    __half* h0s = Ws + 576 * WPAD;
    __half* h1s = h0s + 32 * WPAD;
    float*  bs  = (float*)(h1s + 32 * WPAD);

    const int tid = threadIdx.x;
    const int w = tid >> 5, lane = tid & 31;
    const int warpM = w >> 2, warpN = w & 3;
    const int grp = lane >> 2, tig = lane & 3;
    const size_t gRowBase = (size_t)blockIdx.x * 32;

    {
        const uint4* src = (const uint4*)W16;
        uint4* dst = (uint4*)Ws;
        for (int i = tid; i < 576 * WPAD / 8; i += 256) dst[i] = src[i];
    }
    for (int i = tid; i < 32 * WPAD; i += 256) { h0s[i] = __half(0.f); h1s[i] = __half(0.f); }
    for (int i = tid; i < 576; i += 256) bs[i] = bias[i];
    __syncthreads();
    if (hInit) {
        for (int i = tid; i < 32 * 144; i += 256) {
            int r = i / 144, j = i - r * 144;
            h0s[r * WPAD + j] = hInit[(gRowBase + r) * 144 + j];
        }
        __syncthreads();
    }

    const int aRow = warpM * 16 + (lane & 15);
    const int aCol = (lane >> 4) * 8;
    const int bRowBase = warpN * 144 + (lane & 7) + ((lane >> 4) & 1) * 8;
    const int bCol = ((lane >> 3) & 1) * 8;
    const int tile_m = blockIdx.x * 2 + warpM;
    const int rbase = warpM * 16 + grp;          // block-local row (and +8)

    float creg[9][2];      // cell state for 9 units x 2 rows (rbase, rbase+8)
#pragma unroll
    for (int s = 0; s < 9; s++) { creg[s][0] = 0.f; creg[s][1] = 0.f; }

    int p = 0;
    for (int t = 0; t < PERIOD; t++) {
        const __half* hc = p ? h1s : h0s;
        __half* hn = p ? h0s : h1s;
        const __half* xslice = xpre ? (xpre + (size_t)t * BB * 576) : nullptr;

        uint32_t Areg[9][4];
#pragma unroll
        for (int kc = 0; kc < 9; kc++)
            ldm_x4(Areg[kc][0], Areg[kc][1], Areg[kc][2], Areg[kc][3],
                   hc + aRow * WPAD + kc * 16 + aCol);

        float gif[9][4];   // (i,f) x (row rbase, rbase+8) per unit slot
#pragma unroll
        for (int np = 0; np < 9; np++) {
            float d[2][4];
#pragma unroll
            for (int u = 0; u < 2; u++)
#pragma unroll
                for (int i = 0; i < 4; i++) d[u][i] = 0.f;
            const __half* wb = Ws + (bRowBase + np * 16) * WPAD + bCol;
#pragma unroll
            for (int kc = 0; kc < 9; kc++) {
                uint32_t b0, b1, b2, b3;
                ldm_x4(b0, b1, b2, b3, wb + kc * 16);
                MMA16(d[0][0], d[0][1], d[0][2], d[0][3],
                      Areg[kc][0], Areg[kc][1], Areg[kc][2], Areg[kc][3], b0, b1);
                MMA16(d[1][0], d[1][1], d[1][2], d[1][3],
                      Areg[kc][0], Areg[kc][1], Areg[kc][2], Areg[kc][3], b2, b3);
            }
#pragma unroll
            for (int u = 0; u < 2; u++) {
                int q = 2 * np + u;
                int colg = warpN * 144 + q * 8 + 2 * tig;
                float v0 = d[u][0] + bs[colg], v1 = d[u][1] + bs[colg + 1];
                float v2 = d[u][2] + bs[colg], v3 = d[u][3] + bs[colg + 1];
                if (xslice) {
                    int tile_n = warpN * 18 + q;
                    const __half* tb = xslice +
                        (((size_t)tile_n) * 256 + tile_m) * 128 + 2 * lane;
                    __half2 x01 = *(const __half2*)tb;
                    __half2 x23 = *(const __half2*)(tb + 64);
                    v0 += __half2float(x01.x); v1 += __half2float(x01.y);
                    v2 += __half2float(x23.x); v3 += __half2float(x23.y);
                }
                if (q < 9) {
                    gif[q][0] = v0; gif[q][1] = v1; gif[q][2] = v2; gif[q][3] = v3;
                } else {
                    int s = q - 9;
                    int j = warpN * 36 + s * 4 + tig;
                    // row rbase: gates i=gif[s][0], f=gif[s][1], g=v0, o=v1
                    float c2a = sigm(gif[s][1]) * creg[s][0] + sigm(gif[s][0]) * tanha(v0);
                    float h2a = sigm(v1) * tanha(c2a);
                    creg[s][0] = c2a;
                    hn[rbase * WPAD + j] = __float2half(h2a);
                    // row rbase+8
                    float c2b = sigm(gif[s][3]) * creg[s][1] + sigm(gif[s][2]) * tanha(v2);
                    float h2b = sigm(v3) * tanha(c2b);
                    creg[s][1] = c2b;
                    hn[(rbase + 8) * WPAD + j] = __float2half(h2b);
                }
            }
        }
        __syncthreads();
        // staged coalesced y write (STG.128); enc-final mode writes only t=23
        if (yStride != 0 || t == PERIOD - 1) {
            __half* yslice = y + (size_t)t * yStride;
            for (int i = tid; i < 32 * 18; i += 256) {
                int r = i / 18, q = i - r * 18;
                *(uint4*)(yslice + (gRowBase + r) * 144 + q * 8) =
                    *(const uint4*)(hn + r * WPAD + q * 8);
            }
        }
        p ^= 1;
    }
}

// ---------------------------------------------------------------------------
// Host orchestration
// ---------------------------------------------------------------------------
extern "C" void kernel_launch(void* const* d_in, const int* in_sizes, int n_in,
                              void* d_out, int out_size) {
    const float* x     = (const float*)d_in[0];
    const float* gW0   = (const float*)d_in[1];
    const float* gb0   = (const float*)d_in[2];
    const float* ga0   = (const float*)d_in[3];
    const float* gW1   = (const float*)d_in[4];
    const float* gb1   = (const float*)d_in[5];
    const float* ga1   = (const float*)d_in[6];
    const float* eWih0 = (const float*)d_in[7];
    const float* eWhh0 = (const float*)d_in[8];
    const float* ebih0 = (const float*)d_in[9];
    const float* ebhh0 = (const float*)d_in[10];
    const float* eWih1 = (const float*)d_in[11];
    const float* eWhh1 = (const float*)d_in[12];
    const float* ebih1 = (const float*)d_in[13];
    const float* ebhh1 = (const float*)d_in[14];
    const float* dWhh0 = (const float*)d_in[16];
    const float* dbih0 = (const float*)d_in[17];
    const float* dbhh0 = (const float*)d_in[18];
    const float* dWih1 = (const float*)d_in[19];
    const float* dWhh1 = (const float*)d_in[20];
    const float* dbih1 = (const float*)d_in[21];
    const float* dbhh1 = (const float*)d_in[22];
    const float* gW3   = (const float*)d_in[23];
    const float* gb3   = (const float*)d_in[24];
    const float* ga3   = (const float*)d_in[25];
    const float* gW4   = (const float*)d_in[26];
    const float* gb4   = (const float*)d_in[27];
    const float* ga4   = (const float*)d_in[28];
    const float* fW    = (const float*)d_in[29];
    const float* fb    = (const float*)d_in[30];

    float* S = nullptr;
    cudaGetSymbolAddress((void**)&S, g_scratch);

    __half* x16     = (__half*)(S + OFF_X16);
    __half* out1    = (__half*)(S + OFF_OUT1);
    __half* h2_16   = (__half*)(S + OFF_H2);
    __half* Xpre16  = (__half*)(S + OFF_XPRE);
    __half* y0_16   = (__half*)(S + OFF_Y0);
    __half* yd0_16  = (__half*)(S + OFF_YD0);
    __half* yd1_16  = (__half*)(S + OFF_YD1);
    __half* o3_16   = (__half*)(S + OFF_O3);
    __half* h4_16   = (__half*)(S + OFF_H4);
    __half* enc1_16 = (__half*)(S + OFF_ENC1);
    float*  part    = S + OFF_PART;
    float*  probs   = S + OFF_PROBS;
    __half* Mb      = (__half*)(S + OFF_M);
    __half* w16     = (__half*)(S + OFF_W16);
    float*  br      = S + OFF_BR;
    __half* fw16    = (__half*)(S + OFF_FW16);

    __half* M1 = Mb;
    __half* M2 = M1 + 192 * 288;
    __half* M3 = M2 + 192 * 192;
    __half* M4 = M3 + 192 * 144;

    const size_t WSLICE = (size_t)576 * WPAD;
    __half* w_eWih0 = w16 + 0 * WSLICE;
    __half* w_eWhh0 = w16 + 1 * WSLICE;
    __half* w_eWih1 = w16 + 2 * WSLICE;
    __half* w_eWhh1 = w16 + 3 * WSLICE;
    __half* w_dWhh0 = w16 + 4 * WSLICE;
    __half* w_dWih1 = w16 + 5 * WSLICE;
    __half* w_dWhh1 = w16 + 6 * WSLICE;

    cudaFuncSetAttribute(lstm_chain, cudaFuncAttributeMaxDynamicSharedMemorySize,
                         CHAIN_SMEM);
    cudaFuncSetAttribute(gemm2<0>, cudaFuncAttributeMaxDynamicSharedMemorySize, GSMEM);
    cudaFuncSetAttribute(gemm2<1>, cudaFuncAttributeMaxDynamicSharedMemorySize, GSMEM);
    cudaFuncSetAttribute(gemm2<2>, cudaFuncAttributeMaxDynamicSharedMemorySize, GSMEM);
    cudaFuncSetAttribute(gemm2<3>, cudaFuncAttributeMaxDynamicSharedMemorySize, GSMEM);

    PrepArgs pa;
    pa.wsrc[0] = eWih0; pa.wsrc[1] = eWhh0; pa.wsrc[2] = eWih1; pa.wsrc[3] = eWhh1;
    pa.wsrc[4] = dWhh0; pa.wsrc[5] = dWih1; pa.wsrc[6] = dWhh1;
    pa.bih[0] = ebih0; pa.bih[1] = ebih1; pa.bih[2] = dbih0; pa.bih[3] = dbih1;
    pa.bhh[0] = ebhh0; pa.bhh[1] = ebhh1; pa.bhh[2] = dbhh0; pa.bhh[3] = dbhh1;
    pa.fW = fW;
    prep_all<<<(PREP_TOT + 255) / 256, 256>>>(pa, w16, br, fw16);
    convert_x<<<(int)(((size_t)NB * 288 + 255) / 256), 256>>>(x, x16);

    // ---- GAT 1+2 as GEMMs ----
    attn_pair<22, 16, 16, 12, false><<<1, 128>>>(x, gW0, gb0, ga0, gW1, gb1, ga1,
                                                 probs, probs + 576);
    build_M<<<(192 * 288 + 255) / 256, 256>>>(probs, gW0, M1, 192, 288, 16, 16, 24, 22);
    build_M<<<(192 * 192 + 255) / 256, 256>>>(probs + 576, gW1, M2, 192, 192, 16, 12, 16, 16);
    gemm2<2><<<dim3(3, NB / 256), 128, GSMEM>>>(x16, 288, M1, 288, out1, 192, 192, 16,
                                                gb0, nullptr, nullptr);
    gemm2<3><<<dim3(3, NB / 256), 128, GSMEM>>>(out1, 192, M2, 192, h2_16, 144, 192, 16,
                                                gb1, nullptr, nullptr);

    // ---- Encoder layer 0 ----
    gemm2<0><<<dim3(9, NB / 256), 128, GSMEM>>>(h2_16, 144, w_eWih0, WPAD, Xpre16, 0,
                                                0, 0, nullptr, nullptr, nullptr);
    lstm_chain<<<BB / 32, 256, CHAIN_SMEM>>>(w_eWhh0, br + 0, Xpre16, nullptr,
                                             y0_16, (size_t)BB * 144);
    // ---- Encoder layer 1 (final h only) ----
    gemm2<0><<<dim3(9, NB / 256), 128, GSMEM>>>(y0_16, 144, w_eWih1, WPAD, Xpre16, 0,
                                                0, 0, nullptr, nullptr, nullptr);
    lstm_chain<<<BB / 32, 256, CHAIN_SMEM>>>(w_eWhh1, br + 576, Xpre16, nullptr,
                                             enc1_16, 0);
    // ---- Decoder layer 0 (zero inputs; h0 = enc0 final = y0[t=23]) ----
    lstm_chain<<<BB / 32, 256, CHAIN_SMEM>>>(w_dWhh0, br + 1152, nullptr,
                                             y0_16 + (size_t)23 * BB * 144,
                                             yd0_16, (size_t)BB * 144);
    // ---- Decoder layer 1 (h0 = enc1 final) ----
    gemm2<0><<<dim3(9, NB / 256), 128, GSMEM>>>(yd0_16, 144, w_dWih1, WPAD, Xpre16, 0,
                                                0, 0, nullptr, nullptr, nullptr);
    lstm_chain<<<BB / 32, 256, CHAIN_SMEM>>>(w_dWhh1, br + 1728, Xpre16, enc1_16,
                                             yd1_16, (size_t)BB * 144);

    // ---- GAT 3+4 as GEMMs ----
    attn_pair<12, 16, 16, 24, true><<<1, 128>>>(yd1_16, gW3, gb3, ga3, gW4, gb4, ga4,
                                                probs + 1152, probs + 1728);
    build_M<<<(192 * 144 + 255) / 256, 256>>>(probs + 1152, gW3, M3, 192, 144, 16, 16, 12, 12);
    build_M<<<(320 * 192 + 255) / 256, 256>>>(probs + 1728, gW4, M4, 320, 192, 24, 24, 16, 16);
    gemm2<2><<<dim3(3, NB / 256), 128, GSMEM>>>(yd1_16, 144, M3, 144, o3_16, 192, 192, 16,
                                                gb3, nullptr, nullptr);
    gemm2<2><<<dim3(5, NB / 256), 128, GSMEM>>>(o3_16, 192, M4, 192, h4_16, 288, 288, 24,
                                                gb4, nullptr, nullptr);

    // ---- FC + leaky + MSE ----
    gemm2<1><<<dim3(5, NB / 256), 128, GSMEM>>>(h4_16, 288, fw16, 288, nullptr, 0, 0, 0,
                                                fb, x16, part);
    mse_final<<<(NB + 255) / 256, 256>>>(part, (float*)d_out);
}